// round 3
// baseline (speedup 1.0000x reference)
#include <cuda_runtime.h>
#include <math.h>

// ---------------- problem constants ----------------
#define DIMC   2048
#define SEQ    2048
#define BATCH  2
#define HEADS  16
#define DH     128
#define FFI    8192
#define NPROJ  18688            // 2048+128+128+8192+8192
#define NROWS  4096             // BATCH*SEQ
#define COL_Q  0
#define COL_K  2048
#define COL_V  2176
#define COL_FF 2304
#define COL_G  10496
#define RMS_SCALE 45.25483399593904f   // sqrt(2048)
#define Q_SCALE   0.08838834764831845f // 1/sqrt(128)

// ---------------- scratch (device globals; allocation-free) ----------------
__device__ float g_xn  [(size_t)NROWS * DIMC];                 //  33.5 MB
__device__ float g_proj[(size_t)NROWS * NPROJ];                // 306   MB
__device__ float g_qt  [(size_t)BATCH * HEADS * SEQ * DH];     //  33.5 MB
__device__ float g_kt  [(size_t)BATCH * DH * SEQ];             //   2   MB
__device__ float g_sim [(size_t)BATCH * HEADS * SEQ * SEQ];    // 537   MB
__device__ float g_attn[(size_t)NROWS * DIMC];                 //  33.5 MB

// ---------------- RMSNorm ----------------
__global__ __launch_bounds__(256) void rmsnorm_kernel(
    const float* __restrict__ x, const float* __restrict__ gamma,
    float* __restrict__ xn)
{
    const size_t row = blockIdx.x;
    const float* xr = x + row * DIMC;
    float*       yr = xn + row * DIMC;
    const int t = threadIdx.x;

    float s = 0.f;
    for (int c = t; c < DIMC; c += 256) { float v = xr[c]; s += v * v; }

    __shared__ float red[8];
    #pragma unroll
    for (int o = 16; o; o >>= 1) s += __shfl_xor_sync(0xffffffffu, s, o);
    if ((t & 31) == 0) red[t >> 5] = s;
    __syncthreads();
    float tot = red[0] + red[1] + red[2] + red[3] + red[4] + red[5] + red[6] + red[7];
    float inv = rsqrtf(tot + 1e-5f) * RMS_SCALE;

    for (int c = t; c < DIMC; c += 256) yr[c] = xr[c] * inv * gamma[c];
}

// ---------------- generic batched SGEMM (row-major) ----------------
// C[M,N] (+)= A[M,K] @ B[K,N] (+ bias), with per-z offsets:
//   off = (z>>4)*hi + (z&15)*lo   for A, B, C; bias uses (z&15)*biasLo.
// Tiles: 128x128x8, 256 threads, 8x8 per thread.
// Requires: M % 128 == 0, K % 8 == 0, all lda/ldb/ldc multiples of 4.
__global__ __launch_bounds__(256) void sgemm_kernel(
    float* __restrict__ Cb, const float* __restrict__ Ab,
    const float* __restrict__ Bb, const float* __restrict__ biasB,
    int M, int N, int K, int lda, int ldb, int ldc, int ldBias,
    long long aHi, long long aLo, long long bHi, long long bLo,
    long long cHi, long long cLo, long long biasLo, int accum)
{
    const int z  = blockIdx.z;
    const long long zh = z >> 4, zl = z & 15;
    const float* A = Ab + zh * aHi + zl * aLo;
    const float* Bm = Bb + zh * bHi + zl * bLo;
    float* C = Cb + zh * cHi + zl * cLo;
    const float* bias = biasB ? (biasB + zl * biasLo) : nullptr;

    __shared__ float As[8][128];
    __shared__ float Bs[8][128];

    const int tid  = threadIdx.x;
    const int row0 = blockIdx.y * 128;
    const int col0 = blockIdx.x * 128;

    const int a_r = tid >> 1;          // 0..127
    const int a_c = (tid & 1) * 4;     // 0 or 4
    const int b_r = tid >> 5;          // 0..7
    const int b_c = (tid & 31) * 4;    // 0..124
    const int tr  = (tid >> 4) * 8;    // tile row for this thread
    const int tc  = (tid & 15) * 8;    // tile col for this thread

    float acc[8][8];
    #pragma unroll
    for (int i = 0; i < 8; i++)
        #pragma unroll
        for (int j = 0; j < 8; j++) acc[i][j] = 0.f;

    const float* Aptr = A + (size_t)(row0 + a_r) * lda + a_c;
    const float* Bptr = Bm + (size_t)b_r * ldb + col0 + b_c;
    const bool bvec = (col0 + b_c + 3) < N;

    for (int k0 = 0; k0 < K; k0 += 8) {
        // load A tile (transposed into smem)
        float4 av = *(const float4*)(Aptr + k0);
        As[a_c + 0][a_r] = av.x;
        As[a_c + 1][a_r] = av.y;
        As[a_c + 2][a_r] = av.z;
        As[a_c + 3][a_r] = av.w;
        // load B tile (guarded on N tail)
        if (bvec) {
            *(float4*)&Bs[b_r][b_c] = *(const float4*)(Bptr + (size_t)k0 * ldb);
        } else {
            #pragma unroll
            for (int i = 0; i < 4; i++)
                Bs[b_r][b_c + i] = (col0 + b_c + i < N)
                                     ? Bptr[(size_t)k0 * ldb + i] : 0.f;
        }
        __syncthreads();

        #pragma unroll
        for (int kk = 0; kk < 8; kk++) {
            float ar[8], br[8];
            *(float4*)&ar[0] = *(const float4*)&As[kk][tr];
            *(float4*)&ar[4] = *(const float4*)&As[kk][tr + 4];
            *(float4*)&br[0] = *(const float4*)&Bs[kk][tc];
            *(float4*)&br[4] = *(const float4*)&Bs[kk][tc + 4];
            #pragma unroll
            for (int i = 0; i < 8; i++)
                #pragma unroll
                for (int j = 0; j < 8; j++)
                    acc[i][j] = fmaf(ar[i], br[j], acc[i][j]);
        }
        __syncthreads();
    }

    #pragma unroll
    for (int i = 0; i < 8; i++) {
        const size_t r = (size_t)(row0 + tr + i);
        float* crow = C + r * ldc + col0 + tc;
        const float* brow = bias ? (bias + r * ldBias + col0 + tc) : nullptr;
        #pragma unroll
        for (int j = 0; j < 8; j++) {
            const int c = col0 + tc + j;
            if (c < N) {
                float v = acc[i][j];
                if (brow) v += brow[j];
                if (accum) crow[j] += v; else crow[j] = v;
            }
        }
    }
}

// ---------------- small rearrange / epilogue kernels ----------------
// q_t[b][h][i][d] = proj[(b*S+i), h*128+d] * Q_SCALE
__global__ __launch_bounds__(256) void qt_kernel(
    const float* __restrict__ proj, float* __restrict__ qt)
{
    const size_t idx = (size_t)blockIdx.x * 256 + threadIdx.x;   // < 8388608
    const int d = idx & 127;
    const int i = (idx >> 7) & 2047;
    const int h = (idx >> 18) & 15;
    const int b = (int)(idx >> 22);
    qt[idx] = proj[((size_t)(b * SEQ + i)) * NPROJ + COL_Q + h * DH + d] * Q_SCALE;
}

// k_t[b][d][j] = proj[(b*S+j), 2048+d]
__global__ __launch_bounds__(256) void kt_kernel(
    const float* __restrict__ proj, float* __restrict__ kt)
{
    const size_t idx = (size_t)blockIdx.x * 256 + threadIdx.x;   // < 524288
    const int j = idx & 2047;
    const int d = (idx >> 11) & 127;
    const int b = (int)(idx >> 18);
    kt[idx] = proj[((size_t)(b * SEQ + j)) * NPROJ + COL_K + d];
}

// in-place: ff <- ff * swish(gate)
__global__ __launch_bounds__(256) void swiglu_kernel(float* __restrict__ proj)
{
    const size_t idx = (size_t)blockIdx.x * 256 + threadIdx.x;   // < 4096*8192
    const size_t row = idx >> 13;
    const int c = (int)(idx & 8191);
    float* rp = proj + row * NPROJ;
    const float ff = rp[COL_FF + c];
    const float g  = rp[COL_G + c];
    const float sw = g / (1.f + __expf(-g));
    rp[COL_FF + c] = ff * sw;
}

// row softmax over last dim (2048)
__global__ __launch_bounds__(256) void softmax_kernel(float* __restrict__ sim)
{
    float* p = sim + (size_t)blockIdx.x * SEQ;
    const int t = threadIdx.x;
    float4 a = ((float4*)p)[t];
    float4 b = ((float4*)p)[t + 256];

    float m = fmaxf(fmaxf(fmaxf(a.x, a.y), fmaxf(a.z, a.w)),
                    fmaxf(fmaxf(b.x, b.y), fmaxf(b.z, b.w)));
    __shared__ float redm[8], reds[8];
    #pragma unroll
    for (int o = 16; o; o >>= 1) m = fmaxf(m, __shfl_xor_sync(0xffffffffu, m, o));
    if ((t & 31) == 0) redm[t >> 5] = m;
    __syncthreads();
    const float bm = fmaxf(fmaxf(fmaxf(redm[0], redm[1]), fmaxf(redm[2], redm[3])),
                           fmaxf(fmaxf(redm[4], redm[5]), fmaxf(redm[6], redm[7])));

    a.x = __expf(a.x - bm); a.y = __expf(a.y - bm);
    a.z = __expf(a.z - bm); a.w = __expf(a.w - bm);
    b.x = __expf(b.x - bm); b.y = __expf(b.y - bm);
    b.z = __expf(b.z - bm); b.w = __expf(b.w - bm);

    float s = a.x + a.y + a.z + a.w + b.x + b.y + b.z + b.w;
    #pragma unroll
    for (int o = 16; o; o >>= 1) s += __shfl_xor_sync(0xffffffffu, s, o);
    if ((t & 31) == 0) reds[t >> 5] = s;
    __syncthreads();
    const float bs = reds[0] + reds[1] + reds[2] + reds[3]
                   + reds[4] + reds[5] + reds[6] + reds[7];
    const float inv = 1.f / bs;

    a.x *= inv; a.y *= inv; a.z *= inv; a.w *= inv;
    b.x *= inv; b.y *= inv; b.z *= inv; b.w *= inv;
    ((float4*)p)[t] = a;
    ((float4*)p)[t + 256] = b;
}

// ---------------- launch ----------------
extern "C" void kernel_launch(void* const* d_in, const int* in_sizes, int n_in,
                              void* d_out, int out_size)
{
    // Bind inputs BY ELEMENT COUNT (all six are distinct) — robust to any
    // metadata ordering.
    const float *x = 0, *bias = 0, *gamma = 0, *wi = 0, *attn_wo = 0, *ff_wo = 0;
    for (int i = 0; i < n_in; i++) {
        switch (in_sizes[i]) {
            case  8388608: x       = (const float*)d_in[i]; break; // 2*2048*2048
            case 67108864: bias    = (const float*)d_in[i]; break; // 16*2048*2048
            case     2048: gamma   = (const float*)d_in[i]; break; // 2048
            case 38273024: wi      = (const float*)d_in[i]; break; // 2048*18688
            case  4194304: attn_wo = (const float*)d_in[i]; break; // 2048*2048
            case 16777216: ff_wo   = (const float*)d_in[i]; break; // 8192*2048
        }
    }
    float* out = (float*)d_out;

    float *xn, *proj, *qt, *kt, *sim, *attn;
    cudaGetSymbolAddress((void**)&xn,   g_xn);
    cudaGetSymbolAddress((void**)&proj, g_proj);
    cudaGetSymbolAddress((void**)&qt,   g_qt);
    cudaGetSymbolAddress((void**)&kt,   g_kt);
    cudaGetSymbolAddress((void**)&sim,  g_sim);
    cudaGetSymbolAddress((void**)&attn, g_attn);

    // 1. RMSNorm
    rmsnorm_kernel<<<NROWS, 256>>>(x, gamma, xn);

    // 2. proj = xn @ wi   [4096, 18688]  (18688 = 146 * 128, no tail)
    sgemm_kernel<<<dim3(146, 32, 1), 256>>>(
        proj, xn, wi, nullptr,
        NROWS, NPROJ, DIMC, DIMC, NPROJ, NPROJ, 0,
        0, 0, 0, 0, 0, 0, 0, 0);

    // 3./4. gather q (scaled) and k-transposed
    qt_kernel<<<32768, 256>>>(proj, qt);
    kt_kernel<<<2048, 256>>>(proj, kt);

    // 5. ff <- ff * swish(gate) (in-place inside proj)
    swiglu_kernel<<<131072, 256>>>(proj);

    // 6. sim[z] = q_t[z] @ k_t[b] + bias[h],  z = b*16 + h
    sgemm_kernel<<<dim3(16, 16, 32), 256>>>(
        sim, qt, kt, bias,
        SEQ, SEQ, DH, DH, SEQ, SEQ, SEQ,
        /*aHi*/ (long long)HEADS * SEQ * DH, /*aLo*/ (long long)SEQ * DH,
        /*bHi*/ (long long)DH * SEQ,         /*bLo*/ 0,
        /*cHi*/ (long long)HEADS * SEQ * SEQ, /*cLo*/ (long long)SEQ * SEQ,
        /*biasLo*/ (long long)SEQ * SEQ, 0);

    // 7. softmax rows
    softmax_kernel<<<BATCH * HEADS * SEQ, 256>>>(sim);

    // 8. attn_out[z] = P[z] @ v[b]   -> g_attn[b, i, h*128+d]
    sgemm_kernel<<<dim3(1, 16, 32), 256>>>(
        attn, sim, proj + COL_V, nullptr,
        SEQ, DH, SEQ, SEQ, NPROJ, DIMC, 0,
        /*aHi*/ (long long)HEADS * SEQ * SEQ, /*aLo*/ (long long)SEQ * SEQ,
        /*bHi*/ (long long)SEQ * NPROJ,       /*bLo*/ 0,
        /*cHi*/ (long long)SEQ * DIMC,        /*cLo*/ (long long)DH, 0, 0);

    // 9. out = attn @ attn_wo
    sgemm_kernel<<<dim3(16, 32, 1), 256>>>(
        out, attn, attn_wo, nullptr,
        NROWS, DIMC, DIMC, DIMC, DIMC, DIMC, 0,
        0, 0, 0, 0, 0, 0, 0, 0);

    // 10. out += h @ ff_wo
    sgemm_kernel<<<dim3(16, 32, 1), 256>>>(
        out, proj + COL_FF, ff_wo, nullptr,
        NROWS, DIMC, FFI, NPROJ, DIMC, DIMC, 0,
        0, 0, 0, 0, 0, 0, 0, 1);
}

// round 4
// speedup vs baseline: 1.0453x; 1.0453x over previous
#include <cuda_runtime.h>
#include <math.h>
#include <stdint.h>

// ---------------- problem constants ----------------
#define DIMC   2048
#define SEQ    2048
#define BATCH  2
#define HEADS  16
#define DH     128
#define FFI    8192
#define NPROJ  18688            // 2048+128+128+8192+8192
#define NROWS  4096             // BATCH*SEQ
#define COL_Q  0
#define COL_K  2048
#define COL_V  2176
#define COL_FF 2304
#define COL_G  10496
#define RMS_SCALE 45.25483399593904f   // sqrt(2048)
#define Q_SCALE   0.08838834764831845f // 1/sqrt(128)

// ---------------- scratch (device globals; allocation-free) ----------------
__device__ float g_xn  [(size_t)NROWS * DIMC];                 //  33.5 MB
__device__ float g_proj[(size_t)NROWS * NPROJ];                // 306   MB
__device__ float g_qt  [(size_t)BATCH * HEADS * SEQ * DH];     //  33.5 MB
__device__ float g_kt  [(size_t)BATCH * DH * SEQ];             //   2   MB
__device__ float g_sim [(size_t)BATCH * HEADS * SEQ * SEQ];    // 537   MB
__device__ float g_attn[(size_t)NROWS * DIMC];                 //  33.5 MB

// ---------------- RMSNorm ----------------
__global__ __launch_bounds__(256) void rmsnorm_kernel(
    const float* __restrict__ x, const float* __restrict__ gamma,
    float* __restrict__ xn)
{
    const size_t row = blockIdx.x;
    const float* xr = x + row * DIMC;
    float*       yr = xn + row * DIMC;
    const int t = threadIdx.x;

    float s = 0.f;
    for (int c = t; c < DIMC; c += 256) { float v = xr[c]; s += v * v; }

    __shared__ float red[8];
    #pragma unroll
    for (int o = 16; o; o >>= 1) s += __shfl_xor_sync(0xffffffffu, s, o);
    if ((t & 31) == 0) red[t >> 5] = s;
    __syncthreads();
    float tot = red[0] + red[1] + red[2] + red[3] + red[4] + red[5] + red[6] + red[7];
    float inv = rsqrtf(tot + 1e-5f) * RMS_SCALE;

    for (int c = t; c < DIMC; c += 256) yr[c] = xr[c] * inv * gamma[c];
}

// ---------------- packed f32x2 helpers ----------------
__device__ __forceinline__ void ffma2(unsigned long long& d,
                                      unsigned long long a,
                                      unsigned long long b)
{
    asm("fma.rn.f32x2 %0, %1, %2, %0;" : "+l"(d) : "l"(a), "l"(b));
}
__device__ __forceinline__ unsigned long long dup2(float v)
{
    unsigned long long r;
    asm("mov.b64 %0, {%1, %1};" : "=l"(r) : "r"(__float_as_uint(v)));
    return r;
}

// ---------------- generic batched SGEMM (row-major, FFMA2 inner loop) -------
// C[M,N] (+)= A[M,K] @ B[K,N] (+ bias), with per-z offsets:
//   off = (z>>4)*hi + (z&15)*lo   for A, B, C; bias uses (z&15)*biasLo.
// Tiles: 128x128x8, 256 threads, 8x8 per thread.
// Requires: M % 128 == 0, K % 8 == 0, all lda/ldb/ldc multiples of 4.
__global__ __launch_bounds__(256) void sgemm_kernel(
    float* __restrict__ Cb, const float* __restrict__ Ab,
    const float* __restrict__ Bb, const float* __restrict__ biasB,
    int M, int N, int K, int lda, int ldb, int ldc, int ldBias,
    long long aHi, long long aLo, long long bHi, long long bLo,
    long long cHi, long long cLo, long long biasLo, int accum)
{
    const int z  = blockIdx.z;
    const long long zh = z >> 4, zl = z & 15;
    const float* A = Ab + zh * aHi + zl * aLo;
    const float* Bm = Bb + zh * bHi + zl * bLo;
    float* C = Cb + zh * cHi + zl * cLo;
    const float* bias = biasB ? (biasB + zl * biasLo) : nullptr;

    __shared__ float As[8][128];
    __shared__ float Bs[8][128];

    const int tid  = threadIdx.x;
    const int row0 = blockIdx.y * 128;
    const int col0 = blockIdx.x * 128;

    const int a_r = tid >> 1;          // 0..127
    const int a_c = (tid & 1) * 4;     // 0 or 4
    const int b_r = tid >> 5;          // 0..7
    const int b_c = (tid & 31) * 4;    // 0..124
    const int tr  = (tid >> 4) * 8;    // tile row for this thread
    const int tc  = (tid & 15) * 8;    // tile col for this thread

    // accumulators: 8 rows x 4 packed float2 columns (lo=.even col, hi=.odd)
    unsigned long long acc[8][4];
    #pragma unroll
    for (int i = 0; i < 8; i++)
        #pragma unroll
        for (int j = 0; j < 4; j++) acc[i][j] = 0ull;

    const float* Aptr = A + (size_t)(row0 + a_r) * lda + a_c;
    const float* Bptr = Bm + (size_t)b_r * ldb + col0 + b_c;
    const bool bvec = (col0 + b_c + 3) < N;

    for (int k0 = 0; k0 < K; k0 += 8) {
        // load A tile (transposed into smem)
        float4 av = *(const float4*)(Aptr + k0);
        As[a_c + 0][a_r] = av.x;
        As[a_c + 1][a_r] = av.y;
        As[a_c + 2][a_r] = av.z;
        As[a_c + 3][a_r] = av.w;
        // load B tile (guarded on N tail)
        if (bvec) {
            *(float4*)&Bs[b_r][b_c] = *(const float4*)(Bptr + (size_t)k0 * ldb);
        } else {
            #pragma unroll
            for (int i = 0; i < 4; i++)
                Bs[b_r][b_c + i] = (col0 + b_c + i < N)
                                     ? Bptr[(size_t)k0 * ldb + i] : 0.f;
        }
        __syncthreads();

        #pragma unroll
        for (int kk = 0; kk < 8; kk++) {
            float ar[8];
            unsigned long long bp[4];
            *(float4*)&ar[0] = *(const float4*)&As[kk][tr];
            *(float4*)&ar[4] = *(const float4*)&As[kk][tr + 4];
            // B row pairs: float4 == 2 packed f32x2 lanes (little-endian)
            *(float4*)&bp[0] = *(const float4*)&Bs[kk][tc];
            *(float4*)&bp[2] = *(const float4*)&Bs[kk][tc + 4];
            #pragma unroll
            for (int i = 0; i < 8; i++) {
                const unsigned long long ad = dup2(ar[i]);
                #pragma unroll
                for (int j = 0; j < 4; j++)
                    ffma2(acc[i][j], ad, bp[j]);
            }
        }
        __syncthreads();
    }

    #pragma unroll
    for (int i = 0; i < 8; i++) {
        const size_t r = (size_t)(row0 + tr + i);
        float* crow = C + r * ldc + col0 + tc;
        const float* brow = bias ? (bias + r * ldBias + col0 + tc) : nullptr;
        #pragma unroll
        for (int j = 0; j < 8; j++) {
            const int c = col0 + tc + j;
            if (c < N) {
                const unsigned long long p = acc[i][j >> 1];
                float v = (j & 1) ? __uint_as_float((unsigned)(p >> 32))
                                  : __uint_as_float((unsigned)p);
                if (brow) v += brow[j];
                if (accum) crow[j] += v; else crow[j] = v;
            }
        }
    }
}

// ---------------- small rearrange / epilogue kernels ----------------
// q_t[b][h][i][d] = proj[(b*S+i), h*128+d] * Q_SCALE
__global__ __launch_bounds__(256) void qt_kernel(
    const float* __restrict__ proj, float* __restrict__ qt)
{
    const size_t idx = (size_t)blockIdx.x * 256 + threadIdx.x;   // < 8388608
    const int d = idx & 127;
    const int i = (idx >> 7) & 2047;
    const int h = (idx >> 18) & 15;
    const int b = (int)(idx >> 22);
    qt[idx] = proj[((size_t)(b * SEQ + i)) * NPROJ + COL_Q + h * DH + d] * Q_SCALE;
}

// k_t[b][d][j] = proj[(b*S+j), 2048+d]
__global__ __launch_bounds__(256) void kt_kernel(
    const float* __restrict__ proj, float* __restrict__ kt)
{
    const size_t idx = (size_t)blockIdx.x * 256 + threadIdx.x;   // < 524288
    const int j = idx & 2047;
    const int d = (idx >> 11) & 127;
    const int b = (int)(idx >> 18);
    kt[idx] = proj[((size_t)(b * SEQ + j)) * NPROJ + COL_K + d];
}

// in-place: ff <- ff * swish(gate)
__global__ __launch_bounds__(256) void swiglu_kernel(float* __restrict__ proj)
{
    const size_t idx = (size_t)blockIdx.x * 256 + threadIdx.x;   // < 4096*8192
    const size_t row = idx >> 13;
    const int c = (int)(idx & 8191);
    float* rp = proj + row * NPROJ;
    const float ff = rp[COL_FF + c];
    const float g  = rp[COL_G + c];
    const float sw = g / (1.f + __expf(-g));
    rp[COL_FF + c] = ff * sw;
}

// row softmax over last dim (2048)
__global__ __launch_bounds__(256) void softmax_kernel(float* __restrict__ sim)
{
    float* p = sim + (size_t)blockIdx.x * SEQ;
    const int t = threadIdx.x;
    float4 a = ((float4*)p)[t];
    float4 b = ((float4*)p)[t + 256];

    float m = fmaxf(fmaxf(fmaxf(a.x, a.y), fmaxf(a.z, a.w)),
                    fmaxf(fmaxf(b.x, b.y), fmaxf(b.z, b.w)));
    __shared__ float redm[8], reds[8];
    #pragma unroll
    for (int o = 16; o; o >>= 1) m = fmaxf(m, __shfl_xor_sync(0xffffffffu, m, o));
    if ((t & 31) == 0) redm[t >> 5] = m;
    __syncthreads();
    const float bm = fmaxf(fmaxf(fmaxf(redm[0], redm[1]), fmaxf(redm[2], redm[3])),
                           fmaxf(fmaxf(redm[4], redm[5]), fmaxf(redm[6], redm[7])));

    a.x = __expf(a.x - bm); a.y = __expf(a.y - bm);
    a.z = __expf(a.z - bm); a.w = __expf(a.w - bm);
    b.x = __expf(b.x - bm); b.y = __expf(b.y - bm);
    b.z = __expf(b.z - bm); b.w = __expf(b.w - bm);

    float s = a.x + a.y + a.z + a.w + b.x + b.y + b.z + b.w;
    #pragma unroll
    for (int o = 16; o; o >>= 1) s += __shfl_xor_sync(0xffffffffu, s, o);
    if ((t & 31) == 0) reds[t >> 5] = s;
    __syncthreads();
    const float bs = reds[0] + reds[1] + reds[2] + reds[3]
                   + reds[4] + reds[5] + reds[6] + reds[7];
    const float inv = 1.f / bs;

    a.x *= inv; a.y *= inv; a.z *= inv; a.w *= inv;
    b.x *= inv; b.y *= inv; b.z *= inv; b.w *= inv;
    ((float4*)p)[t] = a;
    ((float4*)p)[t + 256] = b;
}

// ---------------- launch ----------------
extern "C" void kernel_launch(void* const* d_in, const int* in_sizes, int n_in,
                              void* d_out, int out_size)
{
    // Bind inputs BY ELEMENT COUNT (all six are distinct) — robust to any
    // metadata ordering.
    const float *x = 0, *bias = 0, *gamma = 0, *wi = 0, *attn_wo = 0, *ff_wo = 0;
    for (int i = 0; i < n_in; i++) {
        switch (in_sizes[i]) {
            case  8388608: x       = (const float*)d_in[i]; break; // 2*2048*2048
            case 67108864: bias    = (const float*)d_in[i]; break; // 16*2048*2048
            case     2048: gamma   = (const float*)d_in[i]; break; // 2048
            case 38273024: wi      = (const float*)d_in[i]; break; // 2048*18688
            case  4194304: attn_wo = (const float*)d_in[i]; break; // 2048*2048
            case 16777216: ff_wo   = (const float*)d_in[i]; break; // 8192*2048
        }
    }
    float* out = (float*)d_out;

    float *xn, *proj, *qt, *kt, *sim, *attn;
    cudaGetSymbolAddress((void**)&xn,   g_xn);
    cudaGetSymbolAddress((void**)&proj, g_proj);
    cudaGetSymbolAddress((void**)&qt,   g_qt);
    cudaGetSymbolAddress((void**)&kt,   g_kt);
    cudaGetSymbolAddress((void**)&sim,  g_sim);
    cudaGetSymbolAddress((void**)&attn, g_attn);

    // 1. RMSNorm
    rmsnorm_kernel<<<NROWS, 256>>>(x, gamma, xn);

    // 2. proj = xn @ wi   [4096, 18688]  (18688 = 146 * 128, no tail)
    sgemm_kernel<<<dim3(146, 32, 1), 256>>>(
        proj, xn, wi, nullptr,
        NROWS, NPROJ, DIMC, DIMC, NPROJ, NPROJ, 0,
        0, 0, 0, 0, 0, 0, 0, 0);

    // 3./4. gather q (scaled) and k-transposed
    qt_kernel<<<32768, 256>>>(proj, qt);
    kt_kernel<<<2048, 256>>>(proj, kt);

    // 5. ff <- ff * swish(gate) (in-place inside proj)
    swiglu_kernel<<<131072, 256>>>(proj);

    // 6. sim[z] = q_t[z] @ k_t[b] + bias[h],  z = b*16 + h
    sgemm_kernel<<<dim3(16, 16, 32), 256>>>(
        sim, qt, kt, bias,
        SEQ, SEQ, DH, DH, SEQ, SEQ, SEQ,
        /*aHi*/ (long long)HEADS * SEQ * DH, /*aLo*/ (long long)SEQ * DH,
        /*bHi*/ (long long)DH * SEQ,         /*bLo*/ 0,
        /*cHi*/ (long long)HEADS * SEQ * SEQ, /*cLo*/ (long long)SEQ * SEQ,
        /*biasLo*/ (long long)SEQ * SEQ, 0);

    // 7. softmax rows
    softmax_kernel<<<BATCH * HEADS * SEQ, 256>>>(sim);

    // 8. attn_out[z] = P[z] @ v[b]   -> g_attn[b, i, h*128+d]
    sgemm_kernel<<<dim3(1, 16, 32), 256>>>(
        attn, sim, proj + COL_V, nullptr,
        SEQ, DH, SEQ, SEQ, NPROJ, DIMC, 0,
        /*aHi*/ (long long)HEADS * SEQ * SEQ, /*aLo*/ (long long)SEQ * SEQ,
        /*bHi*/ (long long)SEQ * NPROJ,       /*bLo*/ 0,
        /*cHi*/ (long long)SEQ * DIMC,        /*cLo*/ (long long)DH, 0, 0);

    // 9. out = attn @ attn_wo
    sgemm_kernel<<<dim3(16, 32, 1), 256>>>(
        out, attn, attn_wo, nullptr,
        NROWS, DIMC, DIMC, DIMC, DIMC, DIMC, 0,
        0, 0, 0, 0, 0, 0, 0, 0);

    // 10. out += h @ ff_wo
    sgemm_kernel<<<dim3(16, 32, 1), 256>>>(
        out, proj + COL_FF, ff_wo, nullptr,
        NROWS, DIMC, FFI, NPROJ, DIMC, DIMC, 0,
        0, 0, 0, 0, 0, 0, 0, 1);
}

// round 6
// speedup vs baseline: 2.2154x; 2.1194x over previous
#include <cuda_runtime.h>
#include <cuda_bf16.h>
#include <math.h>
#include <stdint.h>

// ---------------- problem constants ----------------
#define DIMC   2048
#define SEQ    2048
#define BATCH  2
#define HEADS  16
#define DH     128
#define FFI    8192
#define NPROJ  18688            // 2048+128+128+8192+8192
#define NROWS  4096             // BATCH*SEQ
#define COL_K  2048
#define COL_V  2176
#define COL_FF 2304
#define COL_G  10496
#define RMS_SCALE 45.25483399593904f   // sqrt(2048)
#define Q_SCALE   0.08838834764831845f // 1/sqrt(128)

// smem: 2 stages * 4 tiles * (128 rows * 80B) = 81920
#define TILE_B   10240
#define STAGE_B  40960
#define SMEM_BYTES 81920

// ---------------- scratch (device globals; allocation-free) ----------------
__device__ __nv_bfloat16 g_xn_h [(size_t)NROWS * DIMC];
__device__ __nv_bfloat16 g_xn_l [(size_t)NROWS * DIMC];
__device__ __nv_bfloat16 g_wiT_h[(size_t)NPROJ * DIMC];
__device__ __nv_bfloat16 g_wiT_l[(size_t)NPROJ * DIMC];
__device__ __nv_bfloat16 g_pr_h [(size_t)NROWS * NPROJ];
__device__ __nv_bfloat16 g_pr_l [(size_t)NROWS * NPROJ];
__device__ __nv_bfloat16 g_qt_h [(size_t)BATCH * HEADS * SEQ * DH];
__device__ __nv_bfloat16 g_qt_l [(size_t)BATCH * HEADS * SEQ * DH];
__device__ __nv_bfloat16 g_kt_h [(size_t)BATCH * SEQ * DH];
__device__ __nv_bfloat16 g_kt_l [(size_t)BATCH * SEQ * DH];
__device__ __nv_bfloat16 g_vt_h [(size_t)BATCH * DH * SEQ];
__device__ __nv_bfloat16 g_vt_l [(size_t)BATCH * DH * SEQ];
__device__ float         g_sim  [(size_t)BATCH * HEADS * SEQ * SEQ];
__device__ __nv_bfloat16 g_P_h  [(size_t)BATCH * HEADS * SEQ * SEQ];
__device__ __nv_bfloat16 g_P_l  [(size_t)BATCH * HEADS * SEQ * SEQ];
__device__ __nv_bfloat16 g_at_h [(size_t)NROWS * DIMC];
__device__ __nv_bfloat16 g_at_l [(size_t)NROWS * DIMC];
__device__ __nv_bfloat16 g_awT_h[(size_t)DIMC * DIMC];
__device__ __nv_bfloat16 g_awT_l[(size_t)DIMC * DIMC];
__device__ __nv_bfloat16 g_fwT_h[(size_t)DIMC * FFI];
__device__ __nv_bfloat16 g_fwT_l[(size_t)DIMC * FFI];
__device__ __nv_bfloat16 g_h_h  [(size_t)NROWS * FFI];
__device__ __nv_bfloat16 g_h_l  [(size_t)NROWS * FFI];

// ---------------- helpers ----------------
__device__ __forceinline__ uint32_t smem_u32(const void* p) {
    uint32_t a;
    asm("{ .reg .u64 t; cvta.to.shared.u64 t, %1; cvt.u32.u64 %0, t; }"
        : "=r"(a) : "l"(p));
    return a;
}
__device__ __forceinline__ void split_bf16(float v, __nv_bfloat16& h, __nv_bfloat16& l) {
    h = __float2bfloat16(v);
    l = __float2bfloat16(v - __bfloat162float(h));
}
__device__ __forceinline__ void ldm4(uint32_t* r, uint32_t a) {
    asm volatile("ldmatrix.sync.aligned.m8n8.x4.shared.b16 {%0,%1,%2,%3}, [%4];"
                 : "=r"(r[0]), "=r"(r[1]), "=r"(r[2]), "=r"(r[3]) : "r"(a));
}
__device__ __forceinline__ void mma16816(float* d, const uint32_t* a,
                                         uint32_t b0, uint32_t b1) {
    asm volatile(
        "mma.sync.aligned.m16n8k16.row.col.f32.bf16.bf16.f32 "
        "{%0,%1,%2,%3}, {%4,%5,%6,%7}, {%8,%9}, {%0,%1,%2,%3};"
        : "+f"(d[0]), "+f"(d[1]), "+f"(d[2]), "+f"(d[3])
        : "r"(a[0]), "r"(a[1]), "r"(a[2]), "r"(a[3]), "r"(b0), "r"(b1));
}

// ---------------- HMMA bf16x3 batched GEMM ----------------
// D[M,N] = (Ah+Al)[M,K] @ (Bh+Bl)[N,K]^T, fp32 acc, 3 MMA terms.
// Tile 128x128x32, 256 thr, 8 warps (4 m x 2 n), each warp 32x64.
// per-z offsets: zh = z>>4, zl = z&15.
__global__ __launch_bounds__(256) void gemm3x_kernel(
    const __nv_bfloat16* __restrict__ Ah, const __nv_bfloat16* __restrict__ Al,
    int lda, long long aHi, long long aLo,
    const __nv_bfloat16* __restrict__ Bh, const __nv_bfloat16* __restrict__ Bl,
    int ldb, long long bHi, long long bLo,
    float* C, int ldc, long long cHi, long long cLo, int accum,
    __nv_bfloat16* Oh, __nv_bfloat16* Ol, int ldo, long long oHi, long long oLo,
    const float* bias, int ldBias, long long biasLo,
    int K)
{
    extern __shared__ char smem[];
    const uint32_t sb = smem_u32(smem);
    const int tid  = threadIdx.x;
    const int wid  = tid >> 5;
    const int lane = tid & 31;
    const int mw   = wid & 3;          // m-warp 0..3
    const int nw   = wid >> 2;         // n-warp 0..1

    const int z = blockIdx.z, zh = z >> 4, zl = z & 15;
    const int row0 = blockIdx.y * 128, col0 = blockIdx.x * 128;

    const __nv_bfloat16* Ahz = Ah + (size_t)zh * aHi + (size_t)zl * aLo;
    const __nv_bfloat16* Alz = Al + (size_t)zh * aHi + (size_t)zl * aLo;
    const __nv_bfloat16* Bhz = Bh + (size_t)zh * bHi + (size_t)zl * bLo;
    const __nv_bfloat16* Blz = Bl + (size_t)zh * bHi + (size_t)zl * bLo;

    // gmem->smem chunk mapping: idx = tid + q*256; r = idx>>2 (row), c = idx&3 (16B seg)
    const int ldr0 = (tid + 0)   >> 2, ldc0 = (tid + 0)   & 3;
    const int ldr1 = (tid + 256) >> 2, ldc1 = (tid + 256) & 3;

    float acc[2][8][4];
    #pragma unroll
    for (int i = 0; i < 2; i++)
        #pragma unroll
        for (int j = 0; j < 8; j++)
            #pragma unroll
            for (int k = 0; k < 4; k++) acc[i][j][k] = 0.f;

    const int NC = K >> 5;

    // preload chunk 0 into buf 0
    {
        const uint32_t tb = sb;
        const __nv_bfloat16* srcs[4] = {Ahz, Alz, Bhz, Blz};
        const int g0s[4] = {row0, row0, col0, col0};
        const int lds[4] = {lda, lda, ldb, ldb};
        #pragma unroll
        for (int t = 0; t < 4; t++) {
            const uint4 v0 = *(const uint4*)(srcs[t] + (size_t)(g0s[t] + ldr0) * lds[t] + ldc0 * 8);
            const uint4 v1 = *(const uint4*)(srcs[t] + (size_t)(g0s[t] + ldr1) * lds[t] + ldc1 * 8);
            uint32_t b = tb + t * TILE_B;
            *(uint4*)(smem + (b - sb) + ldr0 * 80 + ldc0 * 16) = v0;
            *(uint4*)(smem + (b - sb) + ldr1 * 80 + ldc1 * 16) = v1;
        }
    }
    __syncthreads();

    // ldmatrix lane addressing: row_off = lane&15, chunk_off = lane>>4
    const int lrow = lane & 15;
    const int lchk = lane >> 4;

    for (int c = 0; c < NC; c++) {
        const int buf = c & 1;
        const uint32_t tb = sb + buf * STAGE_B;

        // stage next chunk into registers (latency hidden by MMAs below)
        uint4 st0[4], st1[4];
        const bool more = (c + 1 < NC);
        if (more) {
            const int k0 = (c + 1) << 5;
            st0[0] = *(const uint4*)(Ahz + (size_t)(row0 + ldr0) * lda + k0 + ldc0 * 8);
            st1[0] = *(const uint4*)(Ahz + (size_t)(row0 + ldr1) * lda + k0 + ldc1 * 8);
            st0[1] = *(const uint4*)(Alz + (size_t)(row0 + ldr0) * lda + k0 + ldc0 * 8);
            st1[1] = *(const uint4*)(Alz + (size_t)(row0 + ldr1) * lda + k0 + ldc1 * 8);
            st0[2] = *(const uint4*)(Bhz + (size_t)(col0 + ldr0) * ldb + k0 + ldc0 * 8);
            st1[2] = *(const uint4*)(Bhz + (size_t)(col0 + ldr1) * ldb + k0 + ldc1 * 8);
            st0[3] = *(const uint4*)(Blz + (size_t)(col0 + ldr0) * ldb + k0 + ldc0 * 8);
            st1[3] = *(const uint4*)(Blz + (size_t)(col0 + ldr1) * ldb + k0 + ldc1 * 8);
        }

        // compute on current buffer: two k16 halves
        #pragma unroll
        for (int kk = 0; kk < 2; kk++) {
            const int ch0 = kk * 2;  // 16B chunk base for this k16
            uint32_t aH[2][4], aL[2][4], bH[4][4], bL[4][4];
            #pragma unroll
            for (int mt = 0; mt < 2; mt++) {
                const uint32_t ad = tb + (mw * 32 + mt * 16 + lrow) * 80 + (ch0 + lchk) * 16;
                ldm4(aH[mt], ad);
                ldm4(aL[mt], ad + TILE_B);
            }
            #pragma unroll
            for (int nt = 0; nt < 4; nt++) {
                const uint32_t bd = tb + 2 * TILE_B
                                  + (nw * 64 + nt * 16 + lrow) * 80 + (ch0 + lchk) * 16;
                ldm4(bH[nt], bd);
                ldm4(bL[nt], bd + TILE_B);
            }
            #pragma unroll
            for (int mt = 0; mt < 2; mt++) {
                #pragma unroll
                for (int n8 = 0; n8 < 8; n8++) {
                    const int g = n8 >> 1, p = n8 & 1;
                    mma16816(acc[mt][n8], aH[mt], bH[g][p ? 1 : 0], bH[g][p ? 3 : 2]);
                    mma16816(acc[mt][n8], aH[mt], bL[g][p ? 1 : 0], bL[g][p ? 3 : 2]);
                    mma16816(acc[mt][n8], aL[mt], bH[g][p ? 1 : 0], bH[g][p ? 3 : 2]);
                }
            }
        }

        if (more) {
            char* db = smem + (buf ^ 1) * STAGE_B;
            #pragma unroll
            for (int t = 0; t < 4; t++) {
                *(uint4*)(db + t * TILE_B + ldr0 * 80 + ldc0 * 16) = st0[t];
                *(uint4*)(db + t * TILE_B + ldr1 * 80 + ldc1 * 16) = st1[t];
            }
        }
        __syncthreads();
    }

    // ---------------- epilogue ----------------
    float* Cp = C ? (C + (size_t)zh * cHi + (size_t)zl * cLo) : (float*)0;
    __nv_bfloat16* OhP = Oh ? (Oh + (size_t)zh * oHi + (size_t)zl * oLo) : (__nv_bfloat16*)0;
    __nv_bfloat16* OlP = Ol ? (Ol + (size_t)zh * oHi + (size_t)zl * oLo) : (__nv_bfloat16*)0;
    const float* bb = bias ? (bias + (size_t)zl * biasLo) : (const float*)0;

    const int tr  = lane >> 2;
    const int tc2 = (lane & 3) * 2;

    #pragma unroll
    for (int mt = 0; mt < 2; mt++) {
        #pragma unroll
        for (int hf = 0; hf < 2; hf++) {
            const int r = row0 + mw * 32 + mt * 16 + hf * 8 + tr;
            #pragma unroll
            for (int n8 = 0; n8 < 8; n8++) {
                const int cc = col0 + nw * 64 + n8 * 8 + tc2;
                float v0 = acc[mt][n8][hf * 2 + 0];
                float v1 = acc[mt][n8][hf * 2 + 1];
                if (bb) {
                    v0 += bb[(size_t)r * ldBias + cc];
                    v1 += bb[(size_t)r * ldBias + cc + 1];
                }
                if (Cp) {
                    float* cp = Cp + (size_t)r * ldc + cc;
                    if (accum) { cp[0] += v0; cp[1] += v1; }
                    else       { cp[0]  = v0; cp[1]  = v1; }
                }
                if (OhP) {
                    __nv_bfloat16 h0, l0, h1, l1;
                    split_bf16(v0, h0, l0);
                    split_bf16(v1, h1, l1);
                    const size_t o = (size_t)r * ldo + cc;
                    OhP[o] = h0; OhP[o + 1] = h1;
                    OlP[o] = l0; OlP[o + 1] = l1;
                }
            }
        }
    }
}

// ---------------- RMSNorm -> bf16 pair ----------------
__global__ __launch_bounds__(256) void rmsnorm_pair_kernel(
    const float* __restrict__ x, const float* __restrict__ gamma,
    __nv_bfloat16* __restrict__ xh, __nv_bfloat16* __restrict__ xl)
{
    const size_t row = blockIdx.x;
    const float* xr = x + row * DIMC;
    const int t = threadIdx.x;

    float s = 0.f;
    for (int c = t; c < DIMC; c += 256) { float v = xr[c]; s += v * v; }
    __shared__ float red[8];
    #pragma unroll
    for (int o = 16; o; o >>= 1) s += __shfl_xor_sync(0xffffffffu, s, o);
    if ((t & 31) == 0) red[t >> 5] = s;
    __syncthreads();
    float tot = red[0]+red[1]+red[2]+red[3]+red[4]+red[5]+red[6]+red[7];
    float inv = rsqrtf(tot + 1e-5f) * RMS_SCALE;

    for (int c = t; c < DIMC; c += 256) {
        float v = xr[c] * inv * gamma[c];
        __nv_bfloat16 h, l; split_bf16(v, h, l);
        xh[row * DIMC + c] = h; xl[row * DIMC + c] = l;
    }
}

// ---------------- fp32 [R,C] -> transposed bf16 pair [C,R] ----------------
__global__ void transpose_pair_kernel(const float* __restrict__ src, int R, int C,
                                      __nv_bfloat16* __restrict__ dh,
                                      __nv_bfloat16* __restrict__ dl)
{
    __shared__ float t[32][33];
    const int cx = blockIdx.x * 32 + threadIdx.x;
    const int ry = blockIdx.y * 32;
    #pragma unroll
    for (int j = 0; j < 32; j += 8)
        t[threadIdx.y + j][threadIdx.x] = src[(size_t)(ry + threadIdx.y + j) * C + cx];
    __syncthreads();
    const int dr0 = blockIdx.x * 32;
    const int dc  = ry + threadIdx.x;
    #pragma unroll
    for (int j = 0; j < 32; j += 8) {
        float v = t[threadIdx.x][threadIdx.y + j];
        __nv_bfloat16 h, l; split_bf16(v, h, l);
        const size_t o = (size_t)(dr0 + threadIdx.y + j) * R + dc;
        dh[o] = h; dl[o] = l;
    }
}

// ---------------- gathers from proj pair ----------------
__global__ __launch_bounds__(256) void qt_pair_kernel(
    const __nv_bfloat16* __restrict__ ph, const __nv_bfloat16* __restrict__ pl,
    __nv_bfloat16* __restrict__ qh, __nv_bfloat16* __restrict__ ql)
{
    const size_t idx = (size_t)blockIdx.x * 256 + threadIdx.x;   // [b][h][i][d]
    const int d = idx & 127;
    const int i = (idx >> 7) & 2047;
    const int h = (idx >> 18) & 15;
    const int b = (int)(idx >> 22);
    const size_t s = (size_t)(b * SEQ + i) * NPROJ + h * DH + d;
    const float v = (__bfloat162float(ph[s]) + __bfloat162float(pl[s])) * Q_SCALE;
    __nv_bfloat16 hh, ll; split_bf16(v, hh, ll);
    qh[idx] = hh; ql[idx] = ll;
}

__global__ __launch_bounds__(256) void kt_pair_kernel(
    const __nv_bfloat16* __restrict__ ph, const __nv_bfloat16* __restrict__ pl,
    __nv_bfloat16* __restrict__ kh, __nv_bfloat16* __restrict__ kl)
{
    const size_t idx = (size_t)blockIdx.x * 256 + threadIdx.x;   // [b][j][d]
    const int d = idx & 127;
    const size_t row = idx >> 7;                                 // b*SEQ + j
    const size_t s = row * NPROJ + COL_K + d;
    kh[idx] = ph[s]; kl[idx] = pl[s];
}

__global__ __launch_bounds__(256) void vt_pair_kernel(
    const __nv_bfloat16* __restrict__ ph, const __nv_bfloat16* __restrict__ pl,
    __nv_bfloat16* __restrict__ vh, __nv_bfloat16* __restrict__ vl)
{
    const size_t idx = (size_t)blockIdx.x * 256 + threadIdx.x;   // [b][d][j]
    const int j = idx & 2047;
    const int d = (idx >> 11) & 127;
    const int b = (int)(idx >> 18);
    const size_t s = (size_t)(b * SEQ + j) * NPROJ + COL_V + d;
    vh[idx] = ph[s]; vl[idx] = pl[s];
}

__global__ __launch_bounds__(256) void swiglu_pair_kernel(
    const __nv_bfloat16* __restrict__ ph, const __nv_bfloat16* __restrict__ pl,
    __nv_bfloat16* __restrict__ hh, __nv_bfloat16* __restrict__ hl)
{
    const size_t idx = (size_t)blockIdx.x * 256 + threadIdx.x;   // [row][c<8192]
    const size_t row = idx >> 13;
    const int c = (int)(idx & 8191);
    const size_t sf = row * NPROJ + COL_FF + c;
    const size_t sg = row * NPROJ + COL_G + c;
    const float ff = __bfloat162float(ph[sf]) + __bfloat162float(pl[sf]);
    const float g  = __bfloat162float(ph[sg]) + __bfloat162float(pl[sg]);
    const float v  = ff * (g / (1.f + __expf(-g)));
    __nv_bfloat16 h, l; split_bf16(v, h, l);
    hh[idx] = h; hl[idx] = l;
}

// ---------------- softmax (fp32 in) -> bf16 pair ----------------
__global__ __launch_bounds__(256) void softmax_pair_kernel(
    const float* __restrict__ sim,
    __nv_bfloat16* __restrict__ Ph, __nv_bfloat16* __restrict__ Pl)
{
    const float* p = sim + (size_t)blockIdx.x * SEQ;
    const int t = threadIdx.x;
    float4 a = ((const float4*)p)[t];
    float4 b = ((const float4*)p)[t + 256];

    float m = fmaxf(fmaxf(fmaxf(a.x, a.y), fmaxf(a.z, a.w)),
                    fmaxf(fmaxf(b.x, b.y), fmaxf(b.z, b.w)));
    __shared__ float redm[8], reds[8];
    #pragma unroll
    for (int o = 16; o; o >>= 1) m = fmaxf(m, __shfl_xor_sync(0xffffffffu, m, o));
    if ((t & 31) == 0) redm[t >> 5] = m;
    __syncthreads();
    const float bm = fmaxf(fmaxf(fmaxf(redm[0], redm[1]), fmaxf(redm[2], redm[3])),
                           fmaxf(fmaxf(redm[4], redm[5]), fmaxf(redm[6], redm[7])));

    a.x = __expf(a.x - bm); a.y = __expf(a.y - bm);
    a.z = __expf(a.z - bm); a.w = __expf(a.w - bm);
    b.x = __expf(b.x - bm); b.y = __expf(b.y - bm);
    b.z = __expf(b.z - bm); b.w = __expf(b.w - bm);

    float s = a.x + a.y + a.z + a.w + b.x + b.y + b.z + b.w;
    #pragma unroll
    for (int o = 16; o; o >>= 1) s += __shfl_xor_sync(0xffffffffu, s, o);
    if ((t & 31) == 0) reds[t >> 5] = s;
    __syncthreads();
    const float bs = reds[0]+reds[1]+reds[2]+reds[3]+reds[4]+reds[5]+reds[6]+reds[7];
    const float inv = 1.f / bs;

    const size_t base = (size_t)blockIdx.x * SEQ;
    float va[8] = {a.x*inv, a.y*inv, a.z*inv, a.w*inv, b.x*inv, b.y*inv, b.z*inv, b.w*inv};
    #pragma unroll
    for (int i = 0; i < 8; i++) {
        const size_t o = base + (i < 4 ? t*4 + i : 1024 + t*4 + (i-4));
        __nv_bfloat16 h, l; split_bf16(va[i], h, l);
        Ph[o] = h; Pl[o] = l;
    }
}

// ---------------- launch ----------------
extern "C" void kernel_launch(void* const* d_in, const int* in_sizes, int n_in,
                              void* d_out, int out_size)
{
    const float *x = 0, *bias = 0, *gamma = 0, *wi = 0, *attn_wo = 0, *ff_wo = 0;
    for (int i = 0; i < n_in; i++) {
        switch (in_sizes[i]) {
            case  8388608: x       = (const float*)d_in[i]; break;
            case 67108864: bias    = (const float*)d_in[i]; break;
            case     2048: gamma   = (const float*)d_in[i]; break;
            case 38273024: wi      = (const float*)d_in[i]; break;
            case  4194304: attn_wo = (const float*)d_in[i]; break;
            case 16777216: ff_wo   = (const float*)d_in[i]; break;
        }
    }
    float* out = (float*)d_out;

    __nv_bfloat16 *xnh, *xnl, *wiTh, *wiTl, *prh, *prl, *qth, *qtl, *kth, *ktl;
    __nv_bfloat16 *vth, *vtl, *Ph, *Pl, *ath, *atl, *awTh, *awTl, *fwTh, *fwTl, *hh, *hl;
    float *sim;
    cudaGetSymbolAddress((void**)&xnh,  g_xn_h);  cudaGetSymbolAddress((void**)&xnl,  g_xn_l);
    cudaGetSymbolAddress((void**)&wiTh, g_wiT_h); cudaGetSymbolAddress((void**)&wiTl, g_wiT_l);
    cudaGetSymbolAddress((void**)&prh,  g_pr_h);  cudaGetSymbolAddress((void**)&prl,  g_pr_l);
    cudaGetSymbolAddress((void**)&qth,  g_qt_h);  cudaGetSymbolAddress((void**)&qtl,  g_qt_l);
    cudaGetSymbolAddress((void**)&kth,  g_kt_h);  cudaGetSymbolAddress((void**)&ktl,  g_kt_l);
    cudaGetSymbolAddress((void**)&vth,  g_vt_h);  cudaGetSymbolAddress((void**)&vtl,  g_vt_l);
    cudaGetSymbolAddress((void**)&sim,  g_sim);
    cudaGetSymbolAddress((void**)&Ph,   g_P_h);   cudaGetSymbolAddress((void**)&Pl,   g_P_l);
    cudaGetSymbolAddress((void**)&ath,  g_at_h);  cudaGetSymbolAddress((void**)&atl,  g_at_l);
    cudaGetSymbolAddress((void**)&awTh, g_awT_h); cudaGetSymbolAddress((void**)&awTl, g_awT_l);
    cudaGetSymbolAddress((void**)&fwTh, g_fwT_h); cudaGetSymbolAddress((void**)&fwTl, g_fwT_l);
    cudaGetSymbolAddress((void**)&hh,   g_h_h);   cudaGetSymbolAddress((void**)&hl,   g_h_l);

    cudaFuncSetAttribute(gemm3x_kernel,
                         cudaFuncAttributeMaxDynamicSharedMemorySize, SMEM_BYTES);

    // 1. RMSNorm -> xn pair
    rmsnorm_pair_kernel<<<NROWS, 256>>>(x, gamma, xnh, xnl);

    // 2. weight transposes -> bf16 pairs
    transpose_pair_kernel<<<dim3(NPROJ/32, DIMC/32), dim3(32, 8)>>>(wi, DIMC, NPROJ, wiTh, wiTl);
    transpose_pair_kernel<<<dim3(DIMC/32, DIMC/32),  dim3(32, 8)>>>(attn_wo, DIMC, DIMC, awTh, awTl);
    transpose_pair_kernel<<<dim3(DIMC/32, FFI/32),   dim3(32, 8)>>>(ff_wo, FFI, DIMC, fwTh, fwTl);

    // 3. proj = xn @ wi  -> proj pair [4096, 18688]
    gemm3x_kernel<<<dim3(NPROJ/128, NROWS/128, 1), 256, SMEM_BYTES>>>(
        xnh, xnl, DIMC, 0, 0,
        wiTh, wiTl, DIMC, 0, 0,
        (float*)0, 0, 0, 0, 0,
        prh, prl, NPROJ, 0, 0,
        (const float*)0, 0, 0, DIMC);

    // 4. gathers
    qt_pair_kernel<<<32768, 256>>>(prh, prl, qth, qtl);
    kt_pair_kernel<<<2048, 256>>>(prh, prl, kth, ktl);
    vt_pair_kernel<<<2048, 256>>>(prh, prl, vth, vtl);
    swiglu_pair_kernel<<<131072, 256>>>(prh, prl, hh, hl);

    // 5. sim[z] = q[z] @ k[b]^T + bias[h]   (z = b*16 + h)
    gemm3x_kernel<<<dim3(SEQ/128, SEQ/128, BATCH*HEADS), 256, SMEM_BYTES>>>(
        qth, qtl, DH, (long long)HEADS*SEQ*DH, (long long)SEQ*DH,
        kth, ktl, DH, (long long)SEQ*DH, 0,
        sim, SEQ, (long long)HEADS*SEQ*SEQ, (long long)SEQ*SEQ, 0,
        (__nv_bfloat16*)0, (__nv_bfloat16*)0, 0, 0, 0,
        bias, SEQ, (long long)SEQ*SEQ, DH);

    // 6. softmax -> P pair
    softmax_pair_kernel<<<BATCH*HEADS*SEQ, 256>>>(sim, Ph, Pl);

    // 7. attn[b,i,h*128+d] = P[z] @ v[b]^T  -> attn pair
    gemm3x_kernel<<<dim3(1, SEQ/128, BATCH*HEADS), 256, SMEM_BYTES>>>(
        Ph, Pl, SEQ, (long long)HEADS*SEQ*SEQ, (long long)SEQ*SEQ,
        vth, vtl, SEQ, (long long)DH*SEQ, 0,
        (float*)0, 0, 0, 0, 0,
        ath, atl, DIMC, (long long)SEQ*DIMC, (long long)DH,
        (const float*)0, 0, 0, SEQ);

    // 8. out = attn @ attn_wo
    gemm3x_kernel<<<dim3(DIMC/128, NROWS/128, 1), 256, SMEM_BYTES>>>(
        ath, atl, DIMC, 0, 0,
        awTh, awTl, DIMC, 0, 0,
        out, DIMC, 0, 0, 0,
        (__nv_bfloat16*)0, (__nv_bfloat16*)0, 0, 0, 0,
        (const float*)0, 0, 0, DIMC);

    // 9. out += h @ ff_wo
    gemm3x_kernel<<<dim3(DIMC/128, NROWS/128, 1), 256, SMEM_BYTES>>>(
        hh, hl, FFI, 0, 0,
        fwTh, fwTl, FFI, 0, 0,
        out, DIMC, 0, 0, 1,
        (__nv_bfloat16*)0, (__nv_bfloat16*)0, 0, 0, 0,
        (const float*)0, 0, 0, FFI);
}

// round 7
// speedup vs baseline: 2.8993x; 1.3087x over previous
#include <cuda_runtime.h>
#include <cuda_fp16.h>
#include <math.h>
#include <stdint.h>

// ---------------- problem constants ----------------
#define DIMC   2048
#define SEQ    2048
#define BATCH  2
#define HEADS  16
#define DH     128
#define FFI    8192
#define NPROJ  18688            // 2048+128+128+8192+8192
#define NROWS  4096             // BATCH*SEQ
#define COL_K  2048
#define COL_V  2176
#define COL_FF 2304
#define COL_G  10496
#define RMS_SCALE 45.25483399593904f   // sqrt(2048)
#define Q_SCALE   0.08838834764831845f // 1/sqrt(128)

// smem: 2 stages * 3 tiles * (128 rows * 80B) = 61440
#define TILE_B   10240
#define STAGE_B  30720
#define SMEM_BYTES 61440

// ---------------- scratch (device globals; allocation-free) ----------------
__device__ __half g_xn_h [(size_t)NROWS * DIMC];
__device__ __half g_xn_l [(size_t)NROWS * DIMC];
__device__ __half g_wiT  [(size_t)NPROJ * DIMC];
__device__ __half g_pr_h [(size_t)NROWS * NPROJ];
__device__ __half g_pr_l [(size_t)NROWS * NPROJ];
__device__ __half g_qt_h [(size_t)BATCH * HEADS * SEQ * DH];
__device__ __half g_qt_l [(size_t)BATCH * HEADS * SEQ * DH];
__device__ __half g_kt   [(size_t)BATCH * SEQ * DH];
__device__ __half g_vt   [(size_t)BATCH * DH * SEQ];
__device__ __half g_P_h  [(size_t)BATCH * HEADS * SEQ * SEQ];
__device__ __half g_P_l  [(size_t)BATCH * HEADS * SEQ * SEQ];
__device__ __half g_at_h [(size_t)NROWS * DIMC];
__device__ __half g_at_l [(size_t)NROWS * DIMC];
__device__ __half g_awT  [(size_t)DIMC * DIMC];
__device__ __half g_fwT  [(size_t)DIMC * FFI];
__device__ __half g_h_h  [(size_t)NROWS * FFI];
__device__ __half g_h_l  [(size_t)NROWS * FFI];
__device__ float  g_psum [(size_t)BATCH * HEADS * SEQ * 32];   // [z][row][16 coltiles][2 nw]

// ---------------- helpers ----------------
__device__ __forceinline__ uint32_t smem_u32(const void* p) {
    uint32_t a;
    asm("{ .reg .u64 t; cvta.to.shared.u64 t, %1; cvt.u32.u64 %0, t; }"
        : "=r"(a) : "l"(p));
    return a;
}
__device__ __forceinline__ void split_h(float v, __half& h, __half& l) {
    h = __float2half_rn(v);
    l = __float2half_rn(v - __half2float(h));
}
__device__ __forceinline__ void ldm4(uint32_t* r, uint32_t a) {
    asm volatile("ldmatrix.sync.aligned.m8n8.x4.shared.b16 {%0,%1,%2,%3}, [%4];"
                 : "=r"(r[0]), "=r"(r[1]), "=r"(r[2]), "=r"(r[3]) : "r"(a));
}
__device__ __forceinline__ void mma16816(float* d, const uint32_t* a,
                                         uint32_t b0, uint32_t b1) {
    asm volatile(
        "mma.sync.aligned.m16n8k16.row.col.f32.f16.f16.f32 "
        "{%0,%1,%2,%3}, {%4,%5,%6,%7}, {%8,%9}, {%0,%1,%2,%3};"
        : "+f"(d[0]), "+f"(d[1]), "+f"(d[2]), "+f"(d[3])
        : "r"(a[0]), "r"(a[1]), "r"(a[2]), "r"(a[3]), "r"(b0), "r"(b1));
}

// ---------------- HMMA fp16x2 batched GEMM ----------------
// D[M,N] = (Ah+Al)[M,K] @ Bh[N,K]^T, fp32 acc, 2 MMA terms.
// Tile 128x128x32, 256 thr, 8 warps (4 m x 2 n), each warp 32x64.
// per-z offsets: zh = z>>4, zl = z&15.
// mode 0: plain (C and/or pair output, optional bias)
// mode 1: v = exp(v + bias); write pairs; write row partial sums to psum
// mode 2: v *= 1/rowsum(psum); write pairs (PV normalize)
__global__ __launch_bounds__(256) void gemm2x_kernel(
    const __half* __restrict__ Ah, const __half* __restrict__ Al,
    int lda, long long aHi, long long aLo,
    const __half* __restrict__ Bh, int ldb, long long bHi, long long bLo,
    float* C, int ldc, long long cHi, long long cLo, int accum,
    __half* Oh, __half* Ol, int ldo, long long oHi, long long oLo,
    const float* bias, int ldBias, long long biasLo,
    float* psum, int mode, int gridSwap, int K)
{
    extern __shared__ char smem[];
    const uint32_t sb = smem_u32(smem);
    const int tid  = threadIdx.x;
    const int wid  = tid >> 5;
    const int lane = tid & 31;
    const int mw   = wid & 3;          // m-warp 0..3
    const int nw   = wid >> 2;         // n-warp 0..1

    const int z = blockIdx.z, zh = z >> 4, zl = z & 15;
    const int rb_ = gridSwap ? blockIdx.x : blockIdx.y;
    const int cb_ = gridSwap ? blockIdx.y : blockIdx.x;
    const int row0 = rb_ * 128, col0 = cb_ * 128;

    const __half* Ahz = Ah + (size_t)zh * aHi + (size_t)zl * aLo;
    const __half* Alz = Al + (size_t)zh * aHi + (size_t)zl * aLo;
    const __half* Bhz = Bh + (size_t)zh * bHi + (size_t)zl * bLo;

    const int ldr0 = (tid + 0)   >> 2, ldc0 = (tid + 0)   & 3;
    const int ldr1 = (tid + 256) >> 2, ldc1 = (tid + 256) & 3;

    float acc[2][8][4];
    #pragma unroll
    for (int i = 0; i < 2; i++)
        #pragma unroll
        for (int j = 0; j < 8; j++)
            #pragma unroll
            for (int k = 0; k < 4; k++) acc[i][j][k] = 0.f;

    const int NC = K >> 5;

    // preload chunk 0 into buf 0
    {
        const __half* srcs[3] = {Ahz, Alz, Bhz};
        const int g0s[3] = {row0, row0, col0};
        const int lds[3] = {lda, lda, ldb};
        #pragma unroll
        for (int t = 0; t < 3; t++) {
            const uint4 v0 = *(const uint4*)(srcs[t] + (size_t)(g0s[t] + ldr0) * lds[t] + ldc0 * 8);
            const uint4 v1 = *(const uint4*)(srcs[t] + (size_t)(g0s[t] + ldr1) * lds[t] + ldc1 * 8);
            *(uint4*)(smem + t * TILE_B + ldr0 * 80 + ldc0 * 16) = v0;
            *(uint4*)(smem + t * TILE_B + ldr1 * 80 + ldc1 * 16) = v1;
        }
    }
    __syncthreads();

    const int lrow = lane & 15;
    const int lchk = lane >> 4;

    for (int c = 0; c < NC; c++) {
        const int buf = c & 1;
        const uint32_t tb = sb + buf * STAGE_B;

        uint4 st0[3], st1[3];
        const bool more = (c + 1 < NC);
        if (more) {
            const int k0 = (c + 1) << 5;
            st0[0] = *(const uint4*)(Ahz + (size_t)(row0 + ldr0) * lda + k0 + ldc0 * 8);
            st1[0] = *(const uint4*)(Ahz + (size_t)(row0 + ldr1) * lda + k0 + ldc1 * 8);
            st0[1] = *(const uint4*)(Alz + (size_t)(row0 + ldr0) * lda + k0 + ldc0 * 8);
            st1[1] = *(const uint4*)(Alz + (size_t)(row0 + ldr1) * lda + k0 + ldc1 * 8);
            st0[2] = *(const uint4*)(Bhz + (size_t)(col0 + ldr0) * ldb + k0 + ldc0 * 8);
            st1[2] = *(const uint4*)(Bhz + (size_t)(col0 + ldr1) * ldb + k0 + ldc1 * 8);
        }

        #pragma unroll
        for (int kk = 0; kk < 2; kk++) {
            const int ch0 = kk * 2;
            uint32_t aH[2][4], aL[2][4], bF[4][4];
            #pragma unroll
            for (int mt = 0; mt < 2; mt++) {
                const uint32_t ad = tb + (mw * 32 + mt * 16 + lrow) * 80 + (ch0 + lchk) * 16;
                ldm4(aH[mt], ad);
                ldm4(aL[mt], ad + TILE_B);
            }
            #pragma unroll
            for (int nt = 0; nt < 4; nt++) {
                const uint32_t bd = tb + 2 * TILE_B
                                  + (nw * 64 + nt * 16 + lrow) * 80 + (ch0 + lchk) * 16;
                ldm4(bF[nt], bd);
            }
            #pragma unroll
            for (int mt = 0; mt < 2; mt++) {
                #pragma unroll
                for (int n8 = 0; n8 < 8; n8++) {
                    const int g = n8 >> 1, p = n8 & 1;
                    mma16816(acc[mt][n8], aH[mt], bF[g][p ? 1 : 0], bF[g][p ? 3 : 2]);
                    mma16816(acc[mt][n8], aL[mt], bF[g][p ? 1 : 0], bF[g][p ? 3 : 2]);
                }
            }
        }

        if (more) {
            char* db = smem + (buf ^ 1) * STAGE_B;
            #pragma unroll
            for (int t = 0; t < 3; t++) {
                *(uint4*)(db + t * TILE_B + ldr0 * 80 + ldc0 * 16) = st0[t];
                *(uint4*)(db + t * TILE_B + ldr1 * 80 + ldc1 * 16) = st1[t];
            }
        }
        __syncthreads();
    }

    // ---------------- epilogue ----------------
    float* sdiv = (float*)smem;
    if (mode == 2) {
        if (tid < 128) {
            const float* pp = psum + ((size_t)z * SEQ + row0 + tid) * 32;
            float s = 0.f;
            #pragma unroll
            for (int j = 0; j < 32; j++) s += pp[j];
            sdiv[tid] = 1.f / s;
        }
        __syncthreads();
    }

    float* Cp = C ? (C + (size_t)zh * cHi + (size_t)zl * cLo) : (float*)0;
    __half* OhP = Oh ? (Oh + (size_t)zh * oHi + (size_t)zl * oLo) : (__half*)0;
    __half* OlP = Ol ? (Ol + (size_t)zh * oHi + (size_t)zl * oLo) : (__half*)0;
    const float* bb = bias ? (bias + (size_t)zl * biasLo) : (const float*)0;

    const int tr  = lane >> 2;
    const int tc2 = (lane & 3) * 2;

    #pragma unroll
    for (int mt = 0; mt < 2; mt++) {
        #pragma unroll
        for (int hf = 0; hf < 2; hf++) {
            const int rloc = mw * 32 + mt * 16 + hf * 8 + tr;
            const int r = row0 + rloc;
            float rowsum = 0.f;
            #pragma unroll
            for (int n8 = 0; n8 < 8; n8++) {
                const int cc = col0 + nw * 64 + n8 * 8 + tc2;
                float v0 = acc[mt][n8][hf * 2 + 0];
                float v1 = acc[mt][n8][hf * 2 + 1];
                if (bb) {
                    v0 += bb[(size_t)r * ldBias + cc];
                    v1 += bb[(size_t)r * ldBias + cc + 1];
                }
                if (mode == 1) {
                    v0 = __expf(v0); v1 = __expf(v1);
                    rowsum += v0 + v1;
                } else if (mode == 2) {
                    const float d = sdiv[rloc];
                    v0 *= d; v1 *= d;
                }
                if (Cp) {
                    float* cp = Cp + (size_t)r * ldc + cc;
                    if (accum) { cp[0] += v0; cp[1] += v1; }
                    else       { cp[0]  = v0; cp[1]  = v1; }
                }
                if (OhP) {
                    __half h0, l0, h1, l1;
                    split_h(v0, h0, l0);
                    split_h(v1, h1, l1);
                    const size_t o = (size_t)r * ldo + cc;
                    OhP[o] = h0; OhP[o + 1] = h1;
                    OlP[o] = l0; OlP[o + 1] = l1;
                }
            }
            if (mode == 1) {
                rowsum += __shfl_xor_sync(0xffffffffu, rowsum, 1);
                rowsum += __shfl_xor_sync(0xffffffffu, rowsum, 2);
                if ((lane & 3) == 0)
                    psum[(((size_t)z * SEQ + r) * 16 + cb_) * 2 + nw] = rowsum;
            }
        }
    }
}

// ---------------- RMSNorm -> fp16 pair ----------------
__global__ __launch_bounds__(256) void rmsnorm_pair_kernel(
    const float* __restrict__ x, const float* __restrict__ gamma,
    __half* __restrict__ xh, __half* __restrict__ xl)
{
    const size_t row = blockIdx.x;
    const float* xr = x + row * DIMC;
    const int t = threadIdx.x;

    float s = 0.f;
    for (int c = t; c < DIMC; c += 256) { float v = xr[c]; s += v * v; }
    __shared__ float red[8];
    #pragma unroll
    for (int o = 16; o; o >>= 1) s += __shfl_xor_sync(0xffffffffu, s, o);
    if ((t & 31) == 0) red[t >> 5] = s;
    __syncthreads();
    float tot = red[0]+red[1]+red[2]+red[3]+red[4]+red[5]+red[6]+red[7];
    float inv = rsqrtf(tot + 1e-5f) * RMS_SCALE;

    for (int c = t; c < DIMC; c += 256) {
        float v = xr[c] * inv * gamma[c];
        __half h, l; split_h(v, h, l);
        xh[row * DIMC + c] = h; xl[row * DIMC + c] = l;
    }
}

// ---------------- fp32 [R,C] -> transposed fp16 single [C,R] ----------------
__global__ void transpose_single_kernel(const float* __restrict__ src, int R, int C,
                                        __half* __restrict__ dh)
{
    __shared__ float t[32][33];
    const int cx = blockIdx.x * 32 + threadIdx.x;
    const int ry = blockIdx.y * 32;
    #pragma unroll
    for (int j = 0; j < 32; j += 8)
        t[threadIdx.y + j][threadIdx.x] = src[(size_t)(ry + threadIdx.y + j) * C + cx];
    __syncthreads();
    const int dr0 = blockIdx.x * 32;
    const int dc  = ry + threadIdx.x;
    #pragma unroll
    for (int j = 0; j < 32; j += 8) {
        const size_t o = (size_t)(dr0 + threadIdx.y + j) * R + dc;
        dh[o] = __float2half_rn(t[threadIdx.x][threadIdx.y + j]);
    }
}

// ---------------- gathers from proj pair ----------------
__global__ __launch_bounds__(256) void qt_pair_kernel(
    const __half* __restrict__ ph, const __half* __restrict__ pl,
    __half* __restrict__ qh, __half* __restrict__ ql)
{
    const size_t idx = (size_t)blockIdx.x * 256 + threadIdx.x;   // [b][h][i][d]
    const int d = idx & 127;
    const int i = (idx >> 7) & 2047;
    const int h = (idx >> 18) & 15;
    const int b = (int)(idx >> 22);
    const size_t s = (size_t)(b * SEQ + i) * NPROJ + h * DH + d;
    const float v = (__half2float(ph[s]) + __half2float(pl[s])) * Q_SCALE;
    __half hh, ll; split_h(v, hh, ll);
    qh[idx] = hh; ql[idx] = ll;
}

__global__ __launch_bounds__(256) void kt_single_kernel(
    const __half* __restrict__ ph, const __half* __restrict__ pl,
    __half* __restrict__ kh)
{
    const size_t idx = (size_t)blockIdx.x * 256 + threadIdx.x;   // [b][j][d]
    const int d = idx & 127;
    const size_t row = idx >> 7;
    const size_t s = row * NPROJ + COL_K + d;
    kh[idx] = __float2half_rn(__half2float(ph[s]) + __half2float(pl[s]));
}

__global__ __launch_bounds__(256) void vt_single_kernel(
    const __half* __restrict__ ph, const __half* __restrict__ pl,
    __half* __restrict__ vh)
{
    const size_t idx = (size_t)blockIdx.x * 256 + threadIdx.x;   // [b][d][j]
    const int j = idx & 2047;
    const int d = (idx >> 11) & 127;
    const int b = (int)(idx >> 18);
    const size_t s = (size_t)(b * SEQ + j) * NPROJ + COL_V + d;
    vh[idx] = __float2half_rn(__half2float(ph[s]) + __half2float(pl[s]));
}

__global__ __launch_bounds__(256) void swiglu_pair_kernel(
    const __half* __restrict__ ph, const __half* __restrict__ pl,
    __half* __restrict__ hh, __half* __restrict__ hl)
{
    const size_t idx = (size_t)blockIdx.x * 256 + threadIdx.x;   // [row][c<8192]
    const size_t row = idx >> 13;
    const int c = (int)(idx & 8191);
    const size_t sf = row * NPROJ + COL_FF + c;
    const size_t sg = row * NPROJ + COL_G + c;
    const float ff = __half2float(ph[sf]) + __half2float(pl[sf]);
    const float g  = __half2float(ph[sg]) + __half2float(pl[sg]);
    const float v  = ff * (g / (1.f + __expf(-g)));
    __half h, l; split_h(v, h, l);
    hh[idx] = h; hl[idx] = l;
}

// ---------------- launch ----------------
extern "C" void kernel_launch(void* const* d_in, const int* in_sizes, int n_in,
                              void* d_out, int out_size)
{
    const float *x = 0, *bias = 0, *gamma = 0, *wi = 0, *attn_wo = 0, *ff_wo = 0;
    for (int i = 0; i < n_in; i++) {
        switch (in_sizes[i]) {
            case  8388608: x       = (const float*)d_in[i]; break;
            case 67108864: bias    = (const float*)d_in[i]; break;
            case     2048: gamma   = (const float*)d_in[i]; break;
            case 38273024: wi      = (const float*)d_in[i]; break;
            case  4194304: attn_wo = (const float*)d_in[i]; break;
            case 16777216: ff_wo   = (const float*)d_in[i]; break;
        }
    }
    float* out = (float*)d_out;

    __half *xnh, *xnl, *wiT, *prh, *prl, *qth, *qtl, *kt, *vt;
    __half *Ph, *Pl, *ath, *atl, *awT, *fwT, *hh, *hl;
    float *psum;
    cudaGetSymbolAddress((void**)&xnh, g_xn_h); cudaGetSymbolAddress((void**)&xnl, g_xn_l);
    cudaGetSymbolAddress((void**)&wiT, g_wiT);
    cudaGetSymbolAddress((void**)&prh, g_pr_h); cudaGetSymbolAddress((void**)&prl, g_pr_l);
    cudaGetSymbolAddress((void**)&qth, g_qt_h); cudaGetSymbolAddress((void**)&qtl, g_qt_l);
    cudaGetSymbolAddress((void**)&kt,  g_kt);   cudaGetSymbolAddress((void**)&vt,  g_vt);
    cudaGetSymbolAddress((void**)&Ph,  g_P_h);  cudaGetSymbolAddress((void**)&Pl,  g_P_l);
    cudaGetSymbolAddress((void**)&ath, g_at_h); cudaGetSymbolAddress((void**)&atl, g_at_l);
    cudaGetSymbolAddress((void**)&awT, g_awT);  cudaGetSymbolAddress((void**)&fwT, g_fwT);
    cudaGetSymbolAddress((void**)&hh,  g_h_h);  cudaGetSymbolAddress((void**)&hl,  g_h_l);
    cudaGetSymbolAddress((void**)&psum, g_psum);

    cudaFuncSetAttribute(gemm2x_kernel,
                         cudaFuncAttributeMaxDynamicSharedMemorySize, SMEM_BYTES);

    // 1. RMSNorm -> xn pair
    rmsnorm_pair_kernel<<<NROWS, 256>>>(x, gamma, xnh, xnl);

    // 2. weight transposes -> fp16
    transpose_single_kernel<<<dim3(NPROJ/32, DIMC/32), dim3(32, 8)>>>(wi, DIMC, NPROJ, wiT);
    transpose_single_kernel<<<dim3(DIMC/32, DIMC/32),  dim3(32, 8)>>>(attn_wo, DIMC, DIMC, awT);
    transpose_single_kernel<<<dim3(DIMC/32, FFI/32),   dim3(32, 8)>>>(ff_wo, FFI, DIMC, fwT);

    // 3. proj = xn @ wi -> proj pair [4096, 18688]   (rows fast for L2 reuse)
    gemm2x_kernel<<<dim3(NROWS/128, NPROJ/128, 1), 256, SMEM_BYTES>>>(
        xnh, xnl, DIMC, 0, 0,
        wiT, DIMC, 0, 0,
        (float*)0, 0, 0, 0, 0,
        prh, prl, NPROJ, 0, 0,
        (const float*)0, 0, 0,
        (float*)0, 0, 1, DIMC);

    // 4. gathers
    qt_pair_kernel<<<32768, 256>>>(prh, prl, qth, qtl);
    kt_single_kernel<<<2048, 256>>>(prh, prl, kt);
    vt_single_kernel<<<2048, 256>>>(prh, prl, vt);
    swiglu_pair_kernel<<<131072, 256>>>(prh, prl, hh, hl);

    // 5. QK fused: P_unnorm = exp(q@k^T + bias), pairs + row partial sums
    gemm2x_kernel<<<dim3(SEQ/128, SEQ/128, BATCH*HEADS), 256, SMEM_BYTES>>>(
        qth, qtl, DH, (long long)HEADS*SEQ*DH, (long long)SEQ*DH,
        kt, DH, (long long)SEQ*DH, 0,
        (float*)0, 0, 0, 0, 0,
        Ph, Pl, SEQ, (long long)HEADS*SEQ*SEQ, (long long)SEQ*SEQ,
        bias, SEQ, (long long)SEQ*SEQ,
        psum, 1, 0, DH);

    // 6. PV fused: attn = (P_unnorm @ v^T) / rowsum  -> attn pairs
    gemm2x_kernel<<<dim3(1, SEQ/128, BATCH*HEADS), 256, SMEM_BYTES>>>(
        Ph, Pl, SEQ, (long long)HEADS*SEQ*SEQ, (long long)SEQ*SEQ,
        vt, SEQ, (long long)DH*SEQ, 0,
        (float*)0, 0, 0, 0, 0,
        ath, atl, DIMC, (long long)SEQ*DIMC, (long long)DH,
        (const float*)0, 0, 0,
        psum, 2, 0, SEQ);

    // 7. out = attn @ attn_wo
    gemm2x_kernel<<<dim3(NROWS/128, DIMC/128, 1), 256, SMEM_BYTES>>>(
        ath, atl, DIMC, 0, 0,
        awT, DIMC, 0, 0,
        out, DIMC, 0, 0, 0,
        (__half*)0, (__half*)0, 0, 0, 0,
        (const float*)0, 0, 0,
        (float*)0, 0, 1, DIMC);

    // 8. out += h @ ff_wo
    gemm2x_kernel<<<dim3(NROWS/128, DIMC/128, 1), 256, SMEM_BYTES>>>(
        hh, hl, FFI, 0, 0,
        fwT, FFI, 0, 0,
        out, DIMC, 0, 0, 1,
        (__half*)0, (__half*)0, 0, 0, 0,
        (const float*)0, 0, 0,
        (float*)0, 0, 1, FFI);
}

// round 8
// speedup vs baseline: 3.7911x; 1.3076x over previous
#include <cuda_runtime.h>
#include <cuda_fp16.h>
#include <math.h>
#include <stdint.h>

// ---------------- problem constants ----------------
#define DIMC   2048
#define SEQ    2048
#define BATCH  2
#define HEADS  16
#define DH     128
#define FFI    8192
#define NPROJ  18688            // 2048+128+128+8192+8192
#define NROWS  4096             // BATCH*SEQ
#define COL_K  2048
#define COL_V  2176
#define COL_FF 2304
#define COL_G  10496
#define RMS_SCALE 45.25483399593904f   // sqrt(2048)
#define Q_SCALE   0.08838834764831845f // 1/sqrt(128)

// gemm smem: 2 stages * 3 tiles * (128 rows * 80B) = 61440
#define TILE_B   10240
#define STAGE_B  30720
#define SMEM_GEMM 61440
// flash smem: 2 stages * 2 tiles * (128 rows * 272B) = 139264
#define FSTRIDE  272
#define FK_TILE  34816
#define FSTAGE   69632
#define SMEM_FLASH 139264

// ---------------- scratch (device globals; allocation-free) ----------------
__device__ __half g_xn_h [(size_t)NROWS * DIMC];
__device__ __half g_xn_l [(size_t)NROWS * DIMC];
__device__ __half g_wiT  [(size_t)NPROJ * DIMC];
__device__ __half g_pr_h [(size_t)NROWS * NPROJ];
__device__ __half g_pr_l [(size_t)NROWS * NPROJ];
__device__ __half g_qt_h [(size_t)BATCH * HEADS * SEQ * DH];
__device__ __half g_qt_l [(size_t)BATCH * HEADS * SEQ * DH];
__device__ __half g_kt   [(size_t)BATCH * SEQ * DH];
__device__ __half g_vt   [(size_t)BATCH * DH * SEQ];
__device__ __half g_at_h [(size_t)NROWS * DIMC];
__device__ __half g_at_l [(size_t)NROWS * DIMC];
__device__ __half g_awT  [(size_t)DIMC * DIMC];
__device__ __half g_fwT  [(size_t)DIMC * FFI];
__device__ __half g_h_h  [(size_t)NROWS * FFI];
__device__ __half g_h_l  [(size_t)NROWS * FFI];

// ---------------- helpers ----------------
__device__ __forceinline__ uint32_t smem_u32(const void* p) {
    uint32_t a;
    asm("{ .reg .u64 t; cvta.to.shared.u64 t, %1; cvt.u32.u64 %0, t; }"
        : "=r"(a) : "l"(p));
    return a;
}
__device__ __forceinline__ void split_h(float v, __half& h, __half& l) {
    h = __float2half_rn(v);
    l = __float2half_rn(v - __half2float(h));
}
__device__ __forceinline__ void ldm4(uint32_t* r, uint32_t a) {
    asm volatile("ldmatrix.sync.aligned.m8n8.x4.shared.b16 {%0,%1,%2,%3}, [%4];"
                 : "=r"(r[0]), "=r"(r[1]), "=r"(r[2]), "=r"(r[3]) : "r"(a));
}
__device__ __forceinline__ void mma16816(float* d, const uint32_t* a,
                                         uint32_t b0, uint32_t b1) {
    asm volatile(
        "mma.sync.aligned.m16n8k16.row.col.f32.f16.f16.f32 "
        "{%0,%1,%2,%3}, {%4,%5,%6,%7}, {%8,%9}, {%0,%1,%2,%3};"
        : "+f"(d[0]), "+f"(d[1]), "+f"(d[2]), "+f"(d[3])
        : "r"(a[0]), "r"(a[1]), "r"(a[2]), "r"(a[3]), "r"(b0), "r"(b1));
}
__device__ __forceinline__ void cp16(uint32_t s, const void* g) {
    asm volatile("cp.async.cg.shared.global [%0], [%1], 16;" :: "r"(s), "l"(g));
}
#define CP_COMMIT() asm volatile("cp.async.commit_group;")
#define CP_WAIT1()  asm volatile("cp.async.wait_group 1;" ::: "memory")
// pack (v0,v1) into half2 hi + residual lo
__device__ __forceinline__ uint32_t packpair(float v0, float v1, uint32_t& lo) {
    __half h0 = __float2half_rn(v0), h1 = __float2half_rn(v1);
    __half l0 = __float2half_rn(v0 - __half2float(h0));
    __half l1 = __float2half_rn(v1 - __half2float(h1));
    __half2 H = __halves2half2(h0, h1), L = __halves2half2(l0, l1);
    lo = *(uint32_t*)&L;
    return *(uint32_t*)&H;
}

// ---------------- HMMA fp16x2 GEMM with cp.async double buffering ----------
// D[M,N] = (Ah+Al)[M,K] @ Bh[N,K]^T, fp32 acc.
// Tile 128x128x32, 256 thr, 8 warps (4m x 2n). 2 CTAs/SM.
// blockIdx.x = row block (fast), blockIdx.y = col block.
__global__ __launch_bounds__(256, 2) void gemm2x_kernel(
    const __half* __restrict__ Ah, const __half* __restrict__ Al, int lda,
    const __half* __restrict__ Bh, int ldb,
    float* __restrict__ C, int ldc, int accum,
    __half* __restrict__ Oh, __half* __restrict__ Ol, int ldo,
    int K)
{
    extern __shared__ char smem[];
    const uint32_t sb = smem_u32(smem);
    const int tid  = threadIdx.x;
    const int wid  = tid >> 5;
    const int lane = tid & 31;
    const int mw   = wid & 3;
    const int nw   = wid >> 2;

    const int row0 = blockIdx.x * 128, col0 = blockIdx.y * 128;

    const int ldr0 = (tid + 0)   >> 2, ldc0 = (tid + 0)   & 3;
    const int ldr1 = (tid + 256) >> 2, ldc1 = (tid + 256) & 3;

    float acc[2][8][4];
    #pragma unroll
    for (int i = 0; i < 2; i++)
        #pragma unroll
        for (int j = 0; j < 8; j++)
            #pragma unroll
            for (int k = 0; k < 4; k++) acc[i][j][k] = 0.f;

    const int NC = K >> 5;

    // issue chunk 0 into buf 0
    {
        const uint32_t tb = sb;
        cp16(tb + 0*TILE_B + ldr0*80 + ldc0*16, Ah + (size_t)(row0+ldr0)*lda + ldc0*8);
        cp16(tb + 0*TILE_B + ldr1*80 + ldc1*16, Ah + (size_t)(row0+ldr1)*lda + ldc1*8);
        cp16(tb + 1*TILE_B + ldr0*80 + ldc0*16, Al + (size_t)(row0+ldr0)*lda + ldc0*8);
        cp16(tb + 1*TILE_B + ldr1*80 + ldc1*16, Al + (size_t)(row0+ldr1)*lda + ldc1*8);
        cp16(tb + 2*TILE_B + ldr0*80 + ldc0*16, Bh + (size_t)(col0+ldr0)*ldb + ldc0*8);
        cp16(tb + 2*TILE_B + ldr1*80 + ldc1*16, Bh + (size_t)(col0+ldr1)*ldb + ldc1*8);
    }
    CP_COMMIT();

    const int lrow = lane & 15;
    const int lchk = lane >> 4;

    for (int c = 0; c < NC; c++) {
        const int buf = c & 1;
        __syncthreads();                      // prev compute on buf^1 done
        if (c + 1 < NC) {
            const int k0 = (c + 1) << 5;
            const uint32_t db = sb + (buf ^ 1) * STAGE_B;
            cp16(db + 0*TILE_B + ldr0*80 + ldc0*16, Ah + (size_t)(row0+ldr0)*lda + k0 + ldc0*8);
            cp16(db + 0*TILE_B + ldr1*80 + ldc1*16, Ah + (size_t)(row0+ldr1)*lda + k0 + ldc1*8);
            cp16(db + 1*TILE_B + ldr0*80 + ldc0*16, Al + (size_t)(row0+ldr0)*lda + k0 + ldc0*8);
            cp16(db + 1*TILE_B + ldr1*80 + ldc1*16, Al + (size_t)(row0+ldr1)*lda + k0 + ldc1*8);
            cp16(db + 2*TILE_B + ldr0*80 + ldc0*16, Bh + (size_t)(col0+ldr0)*ldb + k0 + ldc0*8);
            cp16(db + 2*TILE_B + ldr1*80 + ldc1*16, Bh + (size_t)(col0+ldr1)*ldb + k0 + ldc1*8);
        }
        CP_COMMIT();
        CP_WAIT1();                           // chunk c resident
        __syncthreads();

        const uint32_t tb = sb + buf * STAGE_B;
        #pragma unroll
        for (int kk = 0; kk < 2; kk++) {
            const int ch0 = kk * 2;
            uint32_t aH[2][4], aL[2][4], bF[4][4];
            #pragma unroll
            for (int mt = 0; mt < 2; mt++) {
                const uint32_t ad = tb + (mw*32 + mt*16 + lrow)*80 + (ch0 + lchk)*16;
                ldm4(aH[mt], ad);
                ldm4(aL[mt], ad + TILE_B);
            }
            #pragma unroll
            for (int nt = 0; nt < 4; nt++) {
                const uint32_t bd = tb + 2*TILE_B + (nw*64 + nt*16 + lrow)*80 + (ch0 + lchk)*16;
                ldm4(bF[nt], bd);
            }
            #pragma unroll
            for (int mt = 0; mt < 2; mt++) {
                #pragma unroll
                for (int n8 = 0; n8 < 8; n8++) {
                    const int g = n8 >> 1, p = n8 & 1;
                    mma16816(acc[mt][n8], aH[mt], bF[g][p], bF[g][p + 2]);
                    mma16816(acc[mt][n8], aL[mt], bF[g][p], bF[g][p + 2]);
                }
            }
        }
    }

    // ---------------- epilogue ----------------
    const int tr  = lane >> 2;
    const int tc2 = (lane & 3) * 2;

    #pragma unroll
    for (int mt = 0; mt < 2; mt++) {
        #pragma unroll
        for (int hf = 0; hf < 2; hf++) {
            const int r = row0 + mw*32 + mt*16 + hf*8 + tr;
            #pragma unroll
            for (int n8 = 0; n8 < 8; n8++) {
                const int cc = col0 + nw*64 + n8*8 + tc2;
                float v0 = acc[mt][n8][hf*2 + 0];
                float v1 = acc[mt][n8][hf*2 + 1];
                if (C) {
                    float* cp = C + (size_t)r * ldc + cc;
                    if (accum) { cp[0] += v0; cp[1] += v1; }
                    else       { cp[0]  = v0; cp[1]  = v1; }
                }
                if (Oh) {
                    __half h0, l0, h1, l1;
                    split_h(v0, h0, l0);
                    split_h(v1, h1, l1);
                    const size_t o = (size_t)r * ldo + cc;
                    Oh[o] = h0; Oh[o + 1] = h1;
                    Ol[o] = l0; Ol[o + 1] = l1;
                }
            }
        }
    }
}

// ---------------- fused flash attention ----------------
// grid (16 q-blocks, 32 z). 8 warps, each 16 q-rows.
// O[b,i,h*128+d] = softmax(q@k^T + bias) @ v, no P materialization.
__global__ __launch_bounds__(256) void flash_kernel(
    const __half* __restrict__ qh, const __half* __restrict__ ql,
    const __half* __restrict__ kmat,   // [b][key][dh]
    const __half* __restrict__ vmat,   // [b][dh][key]
    const float* __restrict__ bias,    // [h][i][j]
    __half* __restrict__ ath, __half* __restrict__ atl)
{
    extern __shared__ char smem[];
    const uint32_t sb = smem_u32(smem);
    const int tid  = threadIdx.x;
    const int wid  = tid >> 5;
    const int lane = tid & 31;
    const int gr   = lane >> 2;
    const int tc   = lane & 3;
    const int lrow = lane & 15;
    const int lchk = lane >> 4;

    const int z = blockIdx.y, b = z >> 4, h = z & 15;
    const int r0 = blockIdx.x * 128 + wid * 16;

    // Q fragments (pair), held in registers for all 16 j-blocks
    uint32_t qH[8][4], qL[8][4];
    {
        const __half* qb = qh + (size_t)z * SEQ * DH;
        const __half* qlb = ql + (size_t)z * SEQ * DH;
        #pragma unroll
        for (int kt = 0; kt < 8; kt++) {
            const int c0 = kt * 16 + 2 * tc;
            qH[kt][0] = *(const uint32_t*)(qb + (size_t)(r0 + gr    ) * DH + c0);
            qH[kt][1] = *(const uint32_t*)(qb + (size_t)(r0 + gr + 8) * DH + c0);
            qH[kt][2] = *(const uint32_t*)(qb + (size_t)(r0 + gr    ) * DH + c0 + 8);
            qH[kt][3] = *(const uint32_t*)(qb + (size_t)(r0 + gr + 8) * DH + c0 + 8);
            qL[kt][0] = *(const uint32_t*)(qlb + (size_t)(r0 + gr    ) * DH + c0);
            qL[kt][1] = *(const uint32_t*)(qlb + (size_t)(r0 + gr + 8) * DH + c0);
            qL[kt][2] = *(const uint32_t*)(qlb + (size_t)(r0 + gr    ) * DH + c0 + 8);
            qL[kt][3] = *(const uint32_t*)(qlb + (size_t)(r0 + gr + 8) * DH + c0 + 8);
        }
    }

    const __half* ksrc = kmat + (size_t)b * SEQ * DH;
    const __half* vsrc = vmat + (size_t)b * DH * SEQ;

    // issue K/V tile j into stage buf
    auto issueKV = [&](int j, int buf) {
        const uint32_t kb = sb + buf * FSTAGE;
        #pragma unroll
        for (int t = 0; t < 8; t++) {
            const int lin = t * 256 + tid;       // 0..2047
            const int r = lin >> 4, s = lin & 15;
            cp16(kb + r * FSTRIDE + s * 16,
                 ksrc + (size_t)(j * 128 + r) * DH + s * 8);
            cp16(kb + FK_TILE + r * FSTRIDE + s * 16,
                 vsrc + (size_t)r * SEQ + j * 128 + s * 8);
        }
    };

    issueKV(0, 0);
    CP_COMMIT();

    float Oacc[16][4];
    #pragma unroll
    for (int i = 0; i < 16; i++)
        #pragma unroll
        for (int k = 0; k < 4; k++) Oacc[i][k] = 0.f;
    float rs0 = 0.f, rs1 = 0.f;

    for (int j = 0; j < 16; j++) {
        const int buf = j & 1;
        __syncthreads();                       // prev compute on buf^1 done
        if (j + 1 < 16) issueKV(j + 1, buf ^ 1);
        CP_COMMIT();
        CP_WAIT1();
        __syncthreads();

        const uint32_t kb = sb + buf * FSTAGE;
        const uint32_t vb = kb + FK_TILE;

        // S = q @ k^T (pair), fp32 acc
        float S[16][4];
        #pragma unroll
        for (int i = 0; i < 16; i++)
            #pragma unroll
            for (int k = 0; k < 4; k++) S[i][k] = 0.f;

        #pragma unroll
        for (int kt = 0; kt < 8; kt++) {
            uint32_t bK[8][4];
            #pragma unroll
            for (int nt = 0; nt < 8; nt++)
                ldm4(bK[nt], kb + (nt * 16 + lrow) * FSTRIDE + kt * 32 + lchk * 16);
            #pragma unroll
            for (int n8 = 0; n8 < 16; n8++) {
                const int g = n8 >> 1, p = n8 & 1;
                mma16816(S[n8], qH[kt], bK[g][p], bK[g][p + 2]);
                mma16816(S[n8], qL[kt], bK[g][p], bK[g][p + 2]);
            }
        }

        // bias + exp + rowsum (fp32, exact)
        const float* bp  = bias + ((size_t)h * SEQ + r0 + gr) * SEQ + j * 128;
        const float* bp8 = bp + (size_t)8 * SEQ;
        #pragma unroll
        for (int n8 = 0; n8 < 16; n8++) {
            const int cc = n8 * 8 + 2 * tc;
            const float2 b01 = *(const float2*)(bp + cc);
            const float2 b23 = *(const float2*)(bp8 + cc);
            const float e0 = __expf(S[n8][0] + b01.x);
            const float e1 = __expf(S[n8][1] + b01.y);
            const float e2 = __expf(S[n8][2] + b23.x);
            const float e3 = __expf(S[n8][3] + b23.y);
            rs0 += e0 + e1; rs1 += e2 + e3;
            S[n8][0] = e0; S[n8][1] = e1; S[n8][2] = e2; S[n8][3] = e3;
        }

        // Oacc += P @ V (C-frag -> A-frag register identity, pair)
        #pragma unroll
        for (int kp = 0; kp < 8; kp++) {
            uint32_t aPh[4], aPl[4];
            aPh[0] = packpair(S[2*kp    ][0], S[2*kp    ][1], aPl[0]);
            aPh[1] = packpair(S[2*kp    ][2], S[2*kp    ][3], aPl[1]);
            aPh[2] = packpair(S[2*kp + 1][0], S[2*kp + 1][1], aPl[2]);
            aPh[3] = packpair(S[2*kp + 1][2], S[2*kp + 1][3], aPl[3]);
            uint32_t bV[8][4];
            #pragma unroll
            for (int nt = 0; nt < 8; nt++)
                ldm4(bV[nt], vb + (nt * 16 + lrow) * FSTRIDE + kp * 32 + lchk * 16);
            #pragma unroll
            for (int n8 = 0; n8 < 16; n8++) {
                const int g = n8 >> 1, p = n8 & 1;
                mma16816(Oacc[n8], aPh, bV[g][p], bV[g][p + 2]);
                mma16816(Oacc[n8], aPl, bV[g][p], bV[g][p + 2]);
            }
        }
    }

    // normalize + write
    rs0 += __shfl_xor_sync(0xffffffffu, rs0, 1);
    rs0 += __shfl_xor_sync(0xffffffffu, rs0, 2);
    rs1 += __shfl_xor_sync(0xffffffffu, rs1, 1);
    rs1 += __shfl_xor_sync(0xffffffffu, rs1, 2);
    const float i0 = 1.f / rs0, i1 = 1.f / rs1;

    const size_t orow0 = (size_t)(b * SEQ + r0 + gr) * DIMC + h * DH;
    const size_t orow1 = (size_t)(b * SEQ + r0 + gr + 8) * DIMC + h * DH;
    #pragma unroll
    for (int n8 = 0; n8 < 16; n8++) {
        const int cc = n8 * 8 + 2 * tc;
        __half h0, l0, h1, l1;
        split_h(Oacc[n8][0] * i0, h0, l0);
        split_h(Oacc[n8][1] * i0, h1, l1);
        ath[orow0 + cc] = h0; ath[orow0 + cc + 1] = h1;
        atl[orow0 + cc] = l0; atl[orow0 + cc + 1] = l1;
        split_h(Oacc[n8][2] * i1, h0, l0);
        split_h(Oacc[n8][3] * i1, h1, l1);
        ath[orow1 + cc] = h0; ath[orow1 + cc + 1] = h1;
        atl[orow1 + cc] = l0; atl[orow1 + cc + 1] = l1;
    }
}

// ---------------- RMSNorm -> fp16 pair ----------------
__global__ __launch_bounds__(256) void rmsnorm_pair_kernel(
    const float* __restrict__ x, const float* __restrict__ gamma,
    __half* __restrict__ xh, __half* __restrict__ xl)
{
    const size_t row = blockIdx.x;
    const float* xr = x + row * DIMC;
    const int t = threadIdx.x;

    float s = 0.f;
    for (int c = t; c < DIMC; c += 256) { float v = xr[c]; s += v * v; }
    __shared__ float red[8];
    #pragma unroll
    for (int o = 16; o; o >>= 1) s += __shfl_xor_sync(0xffffffffu, s, o);
    if ((t & 31) == 0) red[t >> 5] = s;
    __syncthreads();
    float tot = red[0]+red[1]+red[2]+red[3]+red[4]+red[5]+red[6]+red[7];
    float inv = rsqrtf(tot + 1e-5f) * RMS_SCALE;

    for (int c = t; c < DIMC; c += 256) {
        float v = xr[c] * inv * gamma[c];
        __half h, l; split_h(v, h, l);
        xh[row * DIMC + c] = h; xl[row * DIMC + c] = l;
    }
}

// ---------------- fp32 [R,C] -> transposed fp16 [C,R] ----------------
__global__ void transpose_single_kernel(const float* __restrict__ src, int R, int C,
                                        __half* __restrict__ dh)
{
    __shared__ float t[32][33];
    const int cx = blockIdx.x * 32 + threadIdx.x;
    const int ry = blockIdx.y * 32;
    #pragma unroll
    for (int j = 0; j < 32; j += 8)
        t[threadIdx.y + j][threadIdx.x] = src[(size_t)(ry + threadIdx.y + j) * C + cx];
    __syncthreads();
    const int dr0 = blockIdx.x * 32;
    const int dc  = ry + threadIdx.x;
    #pragma unroll
    for (int j = 0; j < 32; j += 8) {
        const size_t o = (size_t)(dr0 + threadIdx.y + j) * R + dc;
        dh[o] = __float2half_rn(t[threadIdx.x][threadIdx.y + j]);
    }
}

// ---------------- gathers from proj pair ----------------
__global__ __launch_bounds__(256) void qt_pair_kernel(
    const __half* __restrict__ ph, const __half* __restrict__ pl,
    __half* __restrict__ qh, __half* __restrict__ ql)
{
    const size_t idx = (size_t)blockIdx.x * 256 + threadIdx.x;   // [b][h][i][d]
    const int d = idx & 127;
    const int i = (idx >> 7) & 2047;
    const int h = (idx >> 18) & 15;
    const int b = (int)(idx >> 22);
    const size_t s = (size_t)(b * SEQ + i) * NPROJ + h * DH + d;
    const float v = (__half2float(ph[s]) + __half2float(pl[s])) * Q_SCALE;
    __half hh, ll; split_h(v, hh, ll);
    qh[idx] = hh; ql[idx] = ll;
}

__global__ __launch_bounds__(256) void kt_single_kernel(
    const __half* __restrict__ ph, const __half* __restrict__ pl,
    __half* __restrict__ kh)
{
    const size_t idx = (size_t)blockIdx.x * 256 + threadIdx.x;   // [b][j][d]
    const int d = idx & 127;
    const size_t row = idx >> 7;
    const size_t s = row * NPROJ + COL_K + d;
    kh[idx] = __float2half_rn(__half2float(ph[s]) + __half2float(pl[s]));
}

__global__ __launch_bounds__(256) void vt_single_kernel(
    const __half* __restrict__ ph, const __half* __restrict__ pl,
    __half* __restrict__ vh)
{
    const size_t idx = (size_t)blockIdx.x * 256 + threadIdx.x;   // [b][d][j]
    const int j = idx & 2047;
    const int d = (idx >> 11) & 127;
    const int b = (int)(idx >> 18);
    const size_t s = (size_t)(b * SEQ + j) * NPROJ + COL_V + d;
    vh[idx] = __float2half_rn(__half2float(ph[s]) + __half2float(pl[s]));
}

__global__ __launch_bounds__(256) void swiglu_pair_kernel(
    const __half* __restrict__ ph, const __half* __restrict__ pl,
    __half* __restrict__ hh, __half* __restrict__ hl)
{
    const size_t idx = (size_t)blockIdx.x * 256 + threadIdx.x;   // [row][c<8192]
    const size_t row = idx >> 13;
    const int c = (int)(idx & 8191);
    const size_t sf = row * NPROJ + COL_FF + c;
    const size_t sg = row * NPROJ + COL_G + c;
    const float ff = __half2float(ph[sf]) + __half2float(pl[sf]);
    const float g  = __half2float(ph[sg]) + __half2float(pl[sg]);
    const float v  = ff * (g / (1.f + __expf(-g)));
    __half h, l; split_h(v, h, l);
    hh[idx] = h; hl[idx] = l;
}

// ---------------- launch ----------------
extern "C" void kernel_launch(void* const* d_in, const int* in_sizes, int n_in,
                              void* d_out, int out_size)
{
    const float *x = 0, *bias = 0, *gamma = 0, *wi = 0, *attn_wo = 0, *ff_wo = 0;
    for (int i = 0; i < n_in; i++) {
        switch (in_sizes[i]) {
            case  8388608: x       = (const float*)d_in[i]; break;
            case 67108864: bias    = (const float*)d_in[i]; break;
            case     2048: gamma   = (const float*)d_in[i]; break;
            case 38273024: wi      = (const float*)d_in[i]; break;
            case  4194304: attn_wo = (const float*)d_in[i]; break;
            case 16777216: ff_wo   = (const float*)d_in[i]; break;
        }
    }
    float* out = (float*)d_out;

    __half *xnh, *xnl, *wiT, *prh, *prl, *qth, *qtl, *kt, *vt;
    __half *ath, *atl, *awT, *fwT, *hh, *hl;
    cudaGetSymbolAddress((void**)&xnh, g_xn_h); cudaGetSymbolAddress((void**)&xnl, g_xn_l);
    cudaGetSymbolAddress((void**)&wiT, g_wiT);
    cudaGetSymbolAddress((void**)&prh, g_pr_h); cudaGetSymbolAddress((void**)&prl, g_pr_l);
    cudaGetSymbolAddress((void**)&qth, g_qt_h); cudaGetSymbolAddress((void**)&qtl, g_qt_l);
    cudaGetSymbolAddress((void**)&kt,  g_kt);   cudaGetSymbolAddress((void**)&vt,  g_vt);
    cudaGetSymbolAddress((void**)&ath, g_at_h); cudaGetSymbolAddress((void**)&atl, g_at_l);
    cudaGetSymbolAddress((void**)&awT, g_awT);  cudaGetSymbolAddress((void**)&fwT, g_fwT);
    cudaGetSymbolAddress((void**)&hh,  g_h_h);  cudaGetSymbolAddress((void**)&hl,  g_h_l);

    cudaFuncSetAttribute(gemm2x_kernel,
                         cudaFuncAttributeMaxDynamicSharedMemorySize, SMEM_GEMM);
    cudaFuncSetAttribute(flash_kernel,
                         cudaFuncAttributeMaxDynamicSharedMemorySize, SMEM_FLASH);

    // 1. RMSNorm -> xn pair
    rmsnorm_pair_kernel<<<NROWS, 256>>>(x, gamma, xnh, xnl);

    // 2. weight transposes -> fp16
    transpose_single_kernel<<<dim3(NPROJ/32, DIMC/32), dim3(32, 8)>>>(wi, DIMC, NPROJ, wiT);
    transpose_single_kernel<<<dim3(DIMC/32, DIMC/32),  dim3(32, 8)>>>(attn_wo, DIMC, DIMC, awT);
    transpose_single_kernel<<<dim3(DIMC/32, FFI/32),   dim3(32, 8)>>>(ff_wo, FFI, DIMC, fwT);

    // 3. proj = xn @ wi -> proj pair
    gemm2x_kernel<<<dim3(NROWS/128, NPROJ/128), 256, SMEM_GEMM>>>(
        xnh, xnl, DIMC, wiT, DIMC,
        (float*)0, 0, 0, prh, prl, NPROJ, DIMC);

    // 4. gathers
    qt_pair_kernel<<<32768, 256>>>(prh, prl, qth, qtl);
    kt_single_kernel<<<2048, 256>>>(prh, prl, kt);
    vt_single_kernel<<<2048, 256>>>(prh, prl, vt);
    swiglu_pair_kernel<<<131072, 256>>>(prh, prl, hh, hl);

    // 5. fused attention -> attn pairs
    flash_kernel<<<dim3(SEQ/128, BATCH*HEADS), 256, SMEM_FLASH>>>(
        qth, qtl, kt, vt, bias, ath, atl);

    // 6. out = attn @ attn_wo
    gemm2x_kernel<<<dim3(NROWS/128, DIMC/128), 256, SMEM_GEMM>>>(
        ath, atl, DIMC, awT, DIMC,
        out, DIMC, 0, (__half*)0, (__half*)0, 0, DIMC);

    // 7. out += h @ ff_wo
    gemm2x_kernel<<<dim3(NROWS/128, DIMC/128), 256, SMEM_GEMM>>>(
        hh, hl, FFI, fwT, FFI,
        out, DIMC, 1, (__half*)0, (__half*)0, 0, FFI);
}

// round 9
// speedup vs baseline: 4.7907x; 1.2637x over previous
#include <cuda_runtime.h>
#include <cuda_fp16.h>
#include <math.h>
#include <stdint.h>

// ---------------- problem constants ----------------
#define DIMC   2048
#define SEQ    2048
#define BATCH  2
#define HEADS  16
#define DH     128
#define FFI    8192
#define NPROJ  18688            // 2048+128+128+8192+8192
#define NROWS  4096             // BATCH*SEQ
#define COL_K  2048
#define COL_V  2176
#define COL_FF 2304
#define COL_G  10496
#define RMS_SCALE 45.25483399593904f   // sqrt(2048)
#define Q_SCALE   0.08838834764831845f // 1/sqrt(128)

// gemm smem: 2 stages * 2 tiles * (128 rows * 80B) = 40960
#define TILE_B   10240
#define STAGE_B  20480
#define SMEM_GEMM 40960
// flash smem: 2 stages * 2 tiles * (128 rows * 272B) = 139264
#define FSTRIDE  272
#define FK_TILE  34816
#define FSTAGE   69632
#define SMEM_FLASH 139264

// ---------------- scratch (device globals; allocation-free) ----------------
__device__ __half g_xn  [(size_t)NROWS * DIMC];
__device__ __half g_wiT [(size_t)NPROJ * DIMC];
__device__ __half g_pr  [(size_t)NROWS * NPROJ];
__device__ __half g_qt  [(size_t)BATCH * HEADS * SEQ * DH];
__device__ __half g_kt  [(size_t)BATCH * SEQ * DH];
__device__ __half g_vt  [(size_t)BATCH * DH * SEQ];
__device__ __half g_at  [(size_t)NROWS * DIMC];
__device__ __half g_awT [(size_t)DIMC * DIMC];
__device__ __half g_fwT [(size_t)DIMC * FFI];
__device__ __half g_h   [(size_t)NROWS * FFI];

// ---------------- helpers ----------------
__device__ __forceinline__ uint32_t smem_u32(const void* p) {
    uint32_t a;
    asm("{ .reg .u64 t; cvta.to.shared.u64 t, %1; cvt.u32.u64 %0, t; }"
        : "=r"(a) : "l"(p));
    return a;
}
__device__ __forceinline__ void ldm4(uint32_t* r, uint32_t a) {
    asm volatile("ldmatrix.sync.aligned.m8n8.x4.shared.b16 {%0,%1,%2,%3}, [%4];"
                 : "=r"(r[0]), "=r"(r[1]), "=r"(r[2]), "=r"(r[3]) : "r"(a));
}
__device__ __forceinline__ void mma16816(float* d, const uint32_t* a,
                                         uint32_t b0, uint32_t b1) {
    asm volatile(
        "mma.sync.aligned.m16n8k16.row.col.f32.f16.f16.f32 "
        "{%0,%1,%2,%3}, {%4,%5,%6,%7}, {%8,%9}, {%0,%1,%2,%3};"
        : "+f"(d[0]), "+f"(d[1]), "+f"(d[2]), "+f"(d[3])
        : "r"(a[0]), "r"(a[1]), "r"(a[2]), "r"(a[3]), "r"(b0), "r"(b1));
}
__device__ __forceinline__ void cp16(uint32_t s, const void* g) {
    asm volatile("cp.async.cg.shared.global [%0], [%1], 16;" :: "r"(s), "l"(g));
}
#define CP_COMMIT() asm volatile("cp.async.commit_group;")
#define CP_WAIT1()  asm volatile("cp.async.wait_group 1;" ::: "memory")
__device__ __forceinline__ uint32_t pack2(float v0, float v1) {
    __half2 H = __floats2half2_rn(v0, v1);
    return *(uint32_t*)&H;
}

// ---------------- HMMA fp16 GEMM with cp.async double buffering ----------
// D[M,N] = A[M,K] @ B[N,K]^T, fp32 acc.
// Tile 128x128x32, 256 thr, 8 warps (4m x 2n). 2 CTAs/SM.
__global__ __launch_bounds__(256, 2) void gemm_kernel(
    const __half* __restrict__ A, int lda,
    const __half* __restrict__ B, int ldb,
    float* __restrict__ C, int ldc, int accum,
    __half* __restrict__ O, int ldo,
    int K)
{
    extern __shared__ char smem[];
    const uint32_t sb = smem_u32(smem);
    const int tid  = threadIdx.x;
    const int wid  = tid >> 5;
    const int lane = tid & 31;
    const int mw   = wid & 3;
    const int nw   = wid >> 2;

    const int row0 = blockIdx.x * 128, col0 = blockIdx.y * 128;

    const int ldr0 = (tid + 0)   >> 2, ldc0 = (tid + 0)   & 3;
    const int ldr1 = (tid + 256) >> 2, ldc1 = (tid + 256) & 3;

    float acc[2][8][4];
    #pragma unroll
    for (int i = 0; i < 2; i++)
        #pragma unroll
        for (int j = 0; j < 8; j++)
            #pragma unroll
            for (int k = 0; k < 4; k++) acc[i][j][k] = 0.f;

    const int NC = K >> 5;

    // issue chunk 0 into buf 0
    cp16(sb + 0*TILE_B + ldr0*80 + ldc0*16, A + (size_t)(row0+ldr0)*lda + ldc0*8);
    cp16(sb + 0*TILE_B + ldr1*80 + ldc1*16, A + (size_t)(row0+ldr1)*lda + ldc1*8);
    cp16(sb + 1*TILE_B + ldr0*80 + ldc0*16, B + (size_t)(col0+ldr0)*ldb + ldc0*8);
    cp16(sb + 1*TILE_B + ldr1*80 + ldc1*16, B + (size_t)(col0+ldr1)*ldb + ldc1*8);
    CP_COMMIT();

    const int lrow = lane & 15;
    const int lchk = lane >> 4;

    for (int c = 0; c < NC; c++) {
        const int buf = c & 1;
        __syncthreads();
        if (c + 1 < NC) {
            const int k0 = (c + 1) << 5;
            const uint32_t db = sb + (buf ^ 1) * STAGE_B;
            cp16(db + 0*TILE_B + ldr0*80 + ldc0*16, A + (size_t)(row0+ldr0)*lda + k0 + ldc0*8);
            cp16(db + 0*TILE_B + ldr1*80 + ldc1*16, A + (size_t)(row0+ldr1)*lda + k0 + ldc1*8);
            cp16(db + 1*TILE_B + ldr0*80 + ldc0*16, B + (size_t)(col0+ldr0)*ldb + k0 + ldc0*8);
            cp16(db + 1*TILE_B + ldr1*80 + ldc1*16, B + (size_t)(col0+ldr1)*ldb + k0 + ldc1*8);
        }
        CP_COMMIT();
        CP_WAIT1();
        __syncthreads();

        const uint32_t tb = sb + buf * STAGE_B;
        #pragma unroll
        for (int kk = 0; kk < 2; kk++) {
            const int ch0 = kk * 2;
            uint32_t aF[2][4], bF[4][4];
            #pragma unroll
            for (int mt = 0; mt < 2; mt++)
                ldm4(aF[mt], tb + (mw*32 + mt*16 + lrow)*80 + (ch0 + lchk)*16);
            #pragma unroll
            for (int nt = 0; nt < 4; nt++)
                ldm4(bF[nt], tb + TILE_B + (nw*64 + nt*16 + lrow)*80 + (ch0 + lchk)*16);
            #pragma unroll
            for (int mt = 0; mt < 2; mt++) {
                #pragma unroll
                for (int n8 = 0; n8 < 8; n8++) {
                    const int g = n8 >> 1, p = n8 & 1;
                    mma16816(acc[mt][n8], aF[mt], bF[g][p], bF[g][p + 2]);
                }
            }
        }
    }

    // ---------------- epilogue ----------------
    const int tr  = lane >> 2;
    const int tc2 = (lane & 3) * 2;

    #pragma unroll
    for (int mt = 0; mt < 2; mt++) {
        #pragma unroll
        for (int hf = 0; hf < 2; hf++) {
            const int r = row0 + mw*32 + mt*16 + hf*8 + tr;
            #pragma unroll
            for (int n8 = 0; n8 < 8; n8++) {
                const int cc = col0 + nw*64 + n8*8 + tc2;
                const float v0 = acc[mt][n8][hf*2 + 0];
                const float v1 = acc[mt][n8][hf*2 + 1];
                if (C) {
                    float* cp = C + (size_t)r * ldc + cc;
                    if (accum) { cp[0] += v0; cp[1] += v1; }
                    else       { cp[0]  = v0; cp[1]  = v1; }
                }
                if (O) {
                    *(uint32_t*)(O + (size_t)r * ldo + cc) = pack2(v0, v1);
                }
            }
        }
    }
}

// ---------------- fused flash attention ----------------
// grid (16 q-blocks, 32 z). 8 warps, each 16 q-rows.
__global__ __launch_bounds__(256) void flash_kernel(
    const __half* __restrict__ q,      // [z][i][dh]
    const __half* __restrict__ kmat,   // [b][key][dh]
    const __half* __restrict__ vmat,   // [b][dh][key]
    const float* __restrict__ bias,    // [h][i][j]
    __half* __restrict__ at)           // [b][i][h*128+d]
{
    extern __shared__ char smem[];
    const uint32_t sb = smem_u32(smem);
    const int tid  = threadIdx.x;
    const int wid  = tid >> 5;
    const int lane = tid & 31;
    const int gr   = lane >> 2;
    const int tc   = lane & 3;
    const int lrow = lane & 15;
    const int lchk = lane >> 4;

    const int z = blockIdx.y, b = z >> 4, h = z & 15;
    const int r0 = blockIdx.x * 128 + wid * 16;

    // Q fragments held in registers for all 16 j-blocks
    uint32_t qF[8][4];
    {
        const __half* qb = q + (size_t)z * SEQ * DH;
        #pragma unroll
        for (int kt = 0; kt < 8; kt++) {
            const int c0 = kt * 16 + 2 * tc;
            qF[kt][0] = *(const uint32_t*)(qb + (size_t)(r0 + gr    ) * DH + c0);
            qF[kt][1] = *(const uint32_t*)(qb + (size_t)(r0 + gr + 8) * DH + c0);
            qF[kt][2] = *(const uint32_t*)(qb + (size_t)(r0 + gr    ) * DH + c0 + 8);
            qF[kt][3] = *(const uint32_t*)(qb + (size_t)(r0 + gr + 8) * DH + c0 + 8);
        }
    }

    const __half* ksrc = kmat + (size_t)b * SEQ * DH;
    const __half* vsrc = vmat + (size_t)b * DH * SEQ;

    auto issueKV = [&](int j, int buf) {
        const uint32_t kb = sb + buf * FSTAGE;
        #pragma unroll
        for (int t = 0; t < 8; t++) {
            const int lin = t * 256 + tid;       // 0..2047
            const int r = lin >> 4, s = lin & 15;
            cp16(kb + r * FSTRIDE + s * 16,
                 ksrc + (size_t)(j * 128 + r) * DH + s * 8);
            cp16(kb + FK_TILE + r * FSTRIDE + s * 16,
                 vsrc + (size_t)r * SEQ + j * 128 + s * 8);
        }
    };

    issueKV(0, 0);
    CP_COMMIT();

    float Oacc[16][4];
    #pragma unroll
    for (int i = 0; i < 16; i++)
        #pragma unroll
        for (int k = 0; k < 4; k++) Oacc[i][k] = 0.f;
    float rs0 = 0.f, rs1 = 0.f;

    for (int j = 0; j < 16; j++) {
        const int buf = j & 1;
        __syncthreads();
        if (j + 1 < 16) issueKV(j + 1, buf ^ 1);
        CP_COMMIT();
        CP_WAIT1();
        __syncthreads();

        const uint32_t kb = sb + buf * FSTAGE;
        const uint32_t vb = kb + FK_TILE;

        // S = q @ k^T, fp32 acc
        float S[16][4];
        #pragma unroll
        for (int i = 0; i < 16; i++)
            #pragma unroll
            for (int k = 0; k < 4; k++) S[i][k] = 0.f;

        #pragma unroll
        for (int kt = 0; kt < 8; kt++) {
            uint32_t bK[8][4];
            #pragma unroll
            for (int nt = 0; nt < 8; nt++)
                ldm4(bK[nt], kb + (nt * 16 + lrow) * FSTRIDE + kt * 32 + lchk * 16);
            #pragma unroll
            for (int n8 = 0; n8 < 16; n8++) {
                const int g = n8 >> 1, p = n8 & 1;
                mma16816(S[n8], qF[kt], bK[g][p], bK[g][p + 2]);
            }
        }

        // bias + exp + rowsum
        const float* bp  = bias + ((size_t)h * SEQ + r0 + gr) * SEQ + j * 128;
        const float* bp8 = bp + (size_t)8 * SEQ;
        #pragma unroll
        for (int n8 = 0; n8 < 16; n8++) {
            const int cc = n8 * 8 + 2 * tc;
            const float2 b01 = *(const float2*)(bp + cc);
            const float2 b23 = *(const float2*)(bp8 + cc);
            const float e0 = __expf(S[n8][0] + b01.x);
            const float e1 = __expf(S[n8][1] + b01.y);
            const float e2 = __expf(S[n8][2] + b23.x);
            const float e3 = __expf(S[n8][3] + b23.y);
            rs0 += e0 + e1; rs1 += e2 + e3;
            S[n8][0] = e0; S[n8][1] = e1; S[n8][2] = e2; S[n8][3] = e3;
        }

        // Oacc += P @ V (C-frag -> A-frag register identity)
        #pragma unroll
        for (int kp = 0; kp < 8; kp++) {
            uint32_t aP[4];
            aP[0] = pack2(S[2*kp    ][0], S[2*kp    ][1]);
            aP[1] = pack2(S[2*kp    ][2], S[2*kp    ][3]);
            aP[2] = pack2(S[2*kp + 1][0], S[2*kp + 1][1]);
            aP[3] = pack2(S[2*kp + 1][2], S[2*kp + 1][3]);
            uint32_t bV[8][4];
            #pragma unroll
            for (int nt = 0; nt < 8; nt++)
                ldm4(bV[nt], vb + (nt * 16 + lrow) * FSTRIDE + kp * 32 + lchk * 16);
            #pragma unroll
            for (int n8 = 0; n8 < 16; n8++) {
                const int g = n8 >> 1, p = n8 & 1;
                mma16816(Oacc[n8], aP, bV[g][p], bV[g][p + 2]);
            }
        }
    }

    // normalize + write
    rs0 += __shfl_xor_sync(0xffffffffu, rs0, 1);
    rs0 += __shfl_xor_sync(0xffffffffu, rs0, 2);
    rs1 += __shfl_xor_sync(0xffffffffu, rs1, 1);
    rs1 += __shfl_xor_sync(0xffffffffu, rs1, 2);
    const float i0 = 1.f / rs0, i1 = 1.f / rs1;

    const size_t orow0 = (size_t)(b * SEQ + r0 + gr) * DIMC + h * DH;
    const size_t orow1 = (size_t)(b * SEQ + r0 + gr + 8) * DIMC + h * DH;
    #pragma unroll
    for (int n8 = 0; n8 < 16; n8++) {
        const int cc = n8 * 8 + 2 * tc;
        *(uint32_t*)(at + orow0 + cc) = pack2(Oacc[n8][0] * i0, Oacc[n8][1] * i0);
        *(uint32_t*)(at + orow1 + cc) = pack2(Oacc[n8][2] * i1, Oacc[n8][3] * i1);
    }
}

// ---------------- RMSNorm -> fp16 ----------------
__global__ __launch_bounds__(256) void rmsnorm_kernel(
    const float* __restrict__ x, const float* __restrict__ gamma,
    __half* __restrict__ xn)
{
    const size_t row = blockIdx.x;
    const float* xr = x + row * DIMC;
    const int t = threadIdx.x;

    float s = 0.f;
    for (int c = t; c < DIMC; c += 256) { float v = xr[c]; s += v * v; }
    __shared__ float red[8];
    #pragma unroll
    for (int o = 16; o; o >>= 1) s += __shfl_xor_sync(0xffffffffu, s, o);
    if ((t & 31) == 0) red[t >> 5] = s;
    __syncthreads();
    float tot = red[0]+red[1]+red[2]+red[3]+red[4]+red[5]+red[6]+red[7];
    float inv = rsqrtf(tot + 1e-5f) * RMS_SCALE;

    for (int c = t; c < DIMC; c += 256)
        xn[row * DIMC + c] = __float2half_rn(xr[c] * inv * gamma[c]);
}

// ---------------- fp32 [R,C] -> transposed fp16 [C,R] ----------------
__global__ void transpose_single_kernel(const float* __restrict__ src, int R, int C,
                                        __half* __restrict__ dh)
{
    __shared__ float t[32][33];
    const int cx = blockIdx.x * 32 + threadIdx.x;
    const int ry = blockIdx.y * 32;
    #pragma unroll
    for (int j = 0; j < 32; j += 8)
        t[threadIdx.y + j][threadIdx.x] = src[(size_t)(ry + threadIdx.y + j) * C + cx];
    __syncthreads();
    const int dr0 = blockIdx.x * 32;
    const int dc  = ry + threadIdx.x;
    #pragma unroll
    for (int j = 0; j < 32; j += 8) {
        const size_t o = (size_t)(dr0 + threadIdx.y + j) * R + dc;
        dh[o] = __float2half_rn(t[threadIdx.x][threadIdx.y + j]);
    }
}

// ---------------- gathers from proj ----------------
__global__ __launch_bounds__(256) void qt_kernel(
    const __half* __restrict__ pr, __half* __restrict__ q)
{
    const size_t idx = (size_t)blockIdx.x * 256 + threadIdx.x;   // [b][h][i][d]
    const int d = idx & 127;
    const int i = (idx >> 7) & 2047;
    const int h = (idx >> 18) & 15;
    const int b = (int)(idx >> 22);
    const size_t s = (size_t)(b * SEQ + i) * NPROJ + h * DH + d;
    q[idx] = __float2half_rn(__half2float(pr[s]) * Q_SCALE);
}

__global__ __launch_bounds__(256) void kt_kernel(
    const __half* __restrict__ pr, __half* __restrict__ k)
{
    const size_t idx = (size_t)blockIdx.x * 256 + threadIdx.x;   // [b][j][d]
    const int d = idx & 127;
    const size_t row = idx >> 7;
    k[idx] = pr[row * NPROJ + COL_K + d];
}

__global__ __launch_bounds__(256) void vt_kernel(
    const __half* __restrict__ pr, __half* __restrict__ v)
{
    const size_t idx = (size_t)blockIdx.x * 256 + threadIdx.x;   // [b][d][j]
    const int j = idx & 2047;
    const int d = (idx >> 11) & 127;
    const int b = (int)(idx >> 18);
    v[idx] = pr[(size_t)(b * SEQ + j) * NPROJ + COL_V + d];
}

__global__ __launch_bounds__(256) void swiglu_kernel(
    const __half* __restrict__ pr, __half* __restrict__ hmat)
{
    const size_t idx = (size_t)blockIdx.x * 256 + threadIdx.x;   // [row][c<8192]
    const size_t row = idx >> 13;
    const int c = (int)(idx & 8191);
    const float ff = __half2float(pr[row * NPROJ + COL_FF + c]);
    const float g  = __half2float(pr[row * NPROJ + COL_G + c]);
    hmat[idx] = __float2half_rn(ff * (g / (1.f + __expf(-g))));
}

// ---------------- launch ----------------
extern "C" void kernel_launch(void* const* d_in, const int* in_sizes, int n_in,
                              void* d_out, int out_size)
{
    const float *x = 0, *bias = 0, *gamma = 0, *wi = 0, *attn_wo = 0, *ff_wo = 0;
    for (int i = 0; i < n_in; i++) {
        switch (in_sizes[i]) {
            case  8388608: x       = (const float*)d_in[i]; break;
            case 67108864: bias    = (const float*)d_in[i]; break;
            case     2048: gamma   = (const float*)d_in[i]; break;
            case 38273024: wi      = (const float*)d_in[i]; break;
            case  4194304: attn_wo = (const float*)d_in[i]; break;
            case 16777216: ff_wo   = (const float*)d_in[i]; break;
        }
    }
    float* out = (float*)d_out;

    __half *xn, *wiT, *pr, *qt, *kt, *vt, *at, *awT, *fwT, *hm;
    cudaGetSymbolAddress((void**)&xn,  g_xn);
    cudaGetSymbolAddress((void**)&wiT, g_wiT);
    cudaGetSymbolAddress((void**)&pr,  g_pr);
    cudaGetSymbolAddress((void**)&qt,  g_qt);
    cudaGetSymbolAddress((void**)&kt,  g_kt);
    cudaGetSymbolAddress((void**)&vt,  g_vt);
    cudaGetSymbolAddress((void**)&at,  g_at);
    cudaGetSymbolAddress((void**)&awT, g_awT);
    cudaGetSymbolAddress((void**)&fwT, g_fwT);
    cudaGetSymbolAddress((void**)&hm,  g_h);

    cudaFuncSetAttribute(gemm_kernel,
                         cudaFuncAttributeMaxDynamicSharedMemorySize, SMEM_GEMM);
    cudaFuncSetAttribute(flash_kernel,
                         cudaFuncAttributeMaxDynamicSharedMemorySize, SMEM_FLASH);

    // 1. RMSNorm -> xn
    rmsnorm_kernel<<<NROWS, 256>>>(x, gamma, xn);

    // 2. weight transposes -> fp16
    transpose_single_kernel<<<dim3(NPROJ/32, DIMC/32), dim3(32, 8)>>>(wi, DIMC, NPROJ, wiT);
    transpose_single_kernel<<<dim3(DIMC/32, DIMC/32),  dim3(32, 8)>>>(attn_wo, DIMC, DIMC, awT);
    transpose_single_kernel<<<dim3(DIMC/32, FFI/32),   dim3(32, 8)>>>(ff_wo, FFI, DIMC, fwT);

    // 3. proj = xn @ wi
    gemm_kernel<<<dim3(NROWS/128, NPROJ/128), 256, SMEM_GEMM>>>(
        xn, DIMC, wiT, DIMC,
        (float*)0, 0, 0, pr, NPROJ, DIMC);

    // 4. gathers
    qt_kernel<<<32768, 256>>>(pr, qt);
    kt_kernel<<<2048, 256>>>(pr, kt);
    vt_kernel<<<2048, 256>>>(pr, vt);
    swiglu_kernel<<<131072, 256>>>(pr, hm);

    // 5. fused attention -> at
    flash_kernel<<<dim3(SEQ/128, BATCH*HEADS), 256, SMEM_FLASH>>>(
        qt, kt, vt, bias, at);

    // 6. out = at @ attn_wo
    gemm_kernel<<<dim3(NROWS/128, DIMC/128), 256, SMEM_GEMM>>>(
        at, DIMC, awT, DIMC,
        out, DIMC, 0, (__half*)0, 0, DIMC);

    // 7. out += h @ ff_wo
    gemm_kernel<<<dim3(NROWS/128, DIMC/128), 256, SMEM_GEMM>>>(
        hm, FFI, fwT, FFI,
        out, DIMC, 1, (__half*)0, 0, FFI);
}

// round 10
// speedup vs baseline: 7.1357x; 1.4895x over previous
#include <cuda_runtime.h>
#include <cuda_fp16.h>
#include <math.h>
#include <stdint.h>

// ---------------- problem constants ----------------
#define DIMC   2048
#define SEQ    2048
#define BATCH  2
#define HEADS  16
#define DH     128
#define FFI    8192
#define NPROJ  18688            // 2048+128+128+8192+8192
#define NROWS  4096             // BATCH*SEQ
#define NCAT   10240            // 2048 (attn) + 8192 (ff)
#define COL_K  2048
#define COL_V  2176
#define COL_FF 2304
#define COL_G  10496
#define RMS_SCALE 45.25483399593904f   // sqrt(2048)
#define Q_SCALE   0.08838834764831845f // 1/sqrt(128)
#define LOG2E     1.4426950408889634f

// gemm smem: 2 stages * 2 tiles * (128 rows * 80B) = 40960
#define TILE_B   10240
#define STAGE_B  20480
#define SMEM_GEMM 40960
// flash smem: 2 stages * (K 128x272 + V 144x272) = 147968
#define FSTRIDE  272
#define FK_TILE  34816
#define FV_TILE  39168
#define FSTAGE   73984
#define SMEM_FLASH 147968

// ---------------- scratch (device globals; allocation-free) ----------------
__device__ __half g_xn  [(size_t)NROWS * DIMC];
__device__ __half g_wiT [(size_t)NPROJ * DIMC];
__device__ __half g_pr  [(size_t)NROWS * NPROJ];
__device__ __half g_qt  [(size_t)BATCH * HEADS * SEQ * DH];
__device__ __half g_kt  [(size_t)BATCH * SEQ * DH];
__device__ __half g_vt  [(size_t)BATCH * DH * SEQ];
__device__ __half g_cat [(size_t)NROWS * NCAT];     // [at | h]
__device__ __half g_wcat[(size_t)DIMC * NCAT];      // [awT | fwT]

// ---------------- helpers ----------------
__device__ __forceinline__ uint32_t smem_u32(const void* p) {
    uint32_t a;
    asm("{ .reg .u64 t; cvta.to.shared.u64 t, %1; cvt.u32.u64 %0, t; }"
        : "=r"(a) : "l"(p));
    return a;
}
__device__ __forceinline__ void ldm4(uint32_t* r, uint32_t a) {
    asm volatile("ldmatrix.sync.aligned.m8n8.x4.shared.b16 {%0,%1,%2,%3}, [%4];"
                 : "=r"(r[0]), "=r"(r[1]), "=r"(r[2]), "=r"(r[3]) : "r"(a));
}
__device__ __forceinline__ void mma16816(float* d, const uint32_t* a,
                                         uint32_t b0, uint32_t b1) {
    asm volatile(
        "mma.sync.aligned.m16n8k16.row.col.f32.f16.f16.f32 "
        "{%0,%1,%2,%3}, {%4,%5,%6,%7}, {%8,%9}, {%0,%1,%2,%3};"
        : "+f"(d[0]), "+f"(d[1]), "+f"(d[2]), "+f"(d[3])
        : "r"(a[0]), "r"(a[1]), "r"(a[2]), "r"(a[3]), "r"(b0), "r"(b1));
}
__device__ __forceinline__ void cp16(uint32_t s, const void* g) {
    asm volatile("cp.async.cg.shared.global [%0], [%1], 16;" :: "r"(s), "l"(g));
}
#define CP_COMMIT() asm volatile("cp.async.commit_group;")
#define CP_WAIT1()  asm volatile("cp.async.wait_group 1;" ::: "memory")
__device__ __forceinline__ uint32_t pack2(float v0, float v1) {
    __half2 H = __floats2half2_rn(v0, v1);
    return *(uint32_t*)&H;
}
__device__ __forceinline__ uint32_t exp2h2(float v0, float v1) {
    uint32_t p = pack2(v0, v1), r;
    asm("ex2.approx.f16x2 %0, %1;" : "=r"(r) : "r"(p));
    return r;
}

// ---------------- HMMA fp16 GEMM with cp.async double buffering ----------
// D[M,N] = A[M,K] @ B[N,K]^T, fp32 acc. Tile 128x128x32, 8 warps, 2 CTA/SM.
__global__ __launch_bounds__(256, 2) void gemm_kernel(
    const __half* __restrict__ A, int lda,
    const __half* __restrict__ B, int ldb,
    float* __restrict__ C, int ldc,
    __half* __restrict__ O, int ldo,
    int K)
{
    extern __shared__ char smem[];
    const uint32_t sb = smem_u32(smem);
    const int tid  = threadIdx.x;
    const int wid  = tid >> 5;
    const int lane = tid & 31;
    const int mw   = wid & 3;
    const int nw   = wid >> 2;

    const int row0 = blockIdx.x * 128, col0 = blockIdx.y * 128;

    const int ldr0 = (tid + 0)   >> 2, ldc0 = (tid + 0)   & 3;
    const int ldr1 = (tid + 256) >> 2, ldc1 = (tid + 256) & 3;

    float acc[2][8][4];
    #pragma unroll
    for (int i = 0; i < 2; i++)
        #pragma unroll
        for (int j = 0; j < 8; j++)
            #pragma unroll
            for (int k = 0; k < 4; k++) acc[i][j][k] = 0.f;

    const int NC = K >> 5;

    cp16(sb + 0*TILE_B + ldr0*80 + ldc0*16, A + (size_t)(row0+ldr0)*lda + ldc0*8);
    cp16(sb + 0*TILE_B + ldr1*80 + ldc1*16, A + (size_t)(row0+ldr1)*lda + ldc1*8);
    cp16(sb + 1*TILE_B + ldr0*80 + ldc0*16, B + (size_t)(col0+ldr0)*ldb + ldc0*8);
    cp16(sb + 1*TILE_B + ldr1*80 + ldc1*16, B + (size_t)(col0+ldr1)*ldb + ldc1*8);
    CP_COMMIT();

    const int lrow = lane & 15;
    const int lchk = lane >> 4;

    for (int c = 0; c < NC; c++) {
        const int buf = c & 1;
        __syncthreads();
        if (c + 1 < NC) {
            const int k0 = (c + 1) << 5;
            const uint32_t db = sb + (buf ^ 1) * STAGE_B;
            cp16(db + 0*TILE_B + ldr0*80 + ldc0*16, A + (size_t)(row0+ldr0)*lda + k0 + ldc0*8);
            cp16(db + 0*TILE_B + ldr1*80 + ldc1*16, A + (size_t)(row0+ldr1)*lda + k0 + ldc1*8);
            cp16(db + 1*TILE_B + ldr0*80 + ldc0*16, B + (size_t)(col0+ldr0)*ldb + k0 + ldc0*8);
            cp16(db + 1*TILE_B + ldr1*80 + ldc1*16, B + (size_t)(col0+ldr1)*ldb + k0 + ldc1*8);
        }
        CP_COMMIT();
        CP_WAIT1();
        __syncthreads();

        const uint32_t tb = sb + buf * STAGE_B;
        #pragma unroll
        for (int kk = 0; kk < 2; kk++) {
            const int ch0 = kk * 2;
            uint32_t aF[2][4], bF[4][4];
            #pragma unroll
            for (int mt = 0; mt < 2; mt++)
                ldm4(aF[mt], tb + (mw*32 + mt*16 + lrow)*80 + (ch0 + lchk)*16);
            #pragma unroll
            for (int nt = 0; nt < 4; nt++)
                ldm4(bF[nt], tb + TILE_B + (nw*64 + nt*16 + lrow)*80 + (ch0 + lchk)*16);
            #pragma unroll
            for (int mt = 0; mt < 2; mt++) {
                #pragma unroll
                for (int n8 = 0; n8 < 8; n8++) {
                    const int g = n8 >> 1, p = n8 & 1;
                    mma16816(acc[mt][n8], aF[mt], bF[g][p], bF[g][p + 2]);
                }
            }
        }
    }

    const int tr  = lane >> 2;
    const int tc2 = (lane & 3) * 2;

    #pragma unroll
    for (int mt = 0; mt < 2; mt++) {
        #pragma unroll
        for (int hf = 0; hf < 2; hf++) {
            const int r = row0 + mw*32 + mt*16 + hf*8 + tr;
            #pragma unroll
            for (int n8 = 0; n8 < 8; n8++) {
                const int cc = col0 + nw*64 + n8*8 + tc2;
                const float v0 = acc[mt][n8][hf*2 + 0];
                const float v1 = acc[mt][n8][hf*2 + 1];
                if (C) {
                    float* cp = C + (size_t)r * ldc + cc;
                    cp[0] = v0; cp[1] = v1;
                }
                if (O) {
                    *(uint32_t*)(O + (size_t)r * ldo + cc) = pack2(v0, v1);
                }
            }
        }
    }
}

// ---------------- fused flash attention ----------------
// grid (16 q-blocks, 32 z). 8 warps, each 16 q-rows. Rowsum via ones-row in V.
__global__ __launch_bounds__(256) void flash_kernel(
    const __half* __restrict__ q,      // [z][i][dh]  (pre-scaled by Q_SCALE*log2e)
    const __half* __restrict__ kmat,   // [b][key][dh]
    const __half* __restrict__ vmat,   // [b][dh][key]
    const float* __restrict__ bias,    // [h][i][j]
    __half* __restrict__ at, int ldo)  // cat buffer, cols [h*128 .. h*128+127]
{
    extern __shared__ char smem[];
    const uint32_t sb = smem_u32(smem);
    const int tid  = threadIdx.x;
    const int wid  = tid >> 5;
    const int lane = tid & 31;
    const int gr   = lane >> 2;
    const int tc   = lane & 3;
    const int lrow = lane & 15;
    const int lchk = lane >> 4;

    const int z = blockIdx.y, b = z >> 4, h = z & 15;
    const int r0 = blockIdx.x * 128 + wid * 16;

    // init ones-row (dh=128) and zero rows 129..143 of both V buffers
    #pragma unroll
    for (int bufi = 0; bufi < 2; bufi++) {
        char* vrows = smem + bufi * FSTAGE + FK_TILE + 128 * FSTRIDE;
        for (int i = tid; i < 16 * 136; i += 256) {
            const int r = i / 136, cc = i % 136;
            *(__half*)(vrows + r * FSTRIDE + cc * 2) =
                (r == 0) ? __float2half(1.0f) : __float2half(0.0f);
        }
    }

    // Q fragments held in registers for all 16 j-blocks
    uint32_t qF[8][4];
    {
        const __half* qb = q + (size_t)z * SEQ * DH;
        #pragma unroll
        for (int kt = 0; kt < 8; kt++) {
            const int c0 = kt * 16 + 2 * tc;
            qF[kt][0] = *(const uint32_t*)(qb + (size_t)(r0 + gr    ) * DH + c0);
            qF[kt][1] = *(const uint32_t*)(qb + (size_t)(r0 + gr + 8) * DH + c0);
            qF[kt][2] = *(const uint32_t*)(qb + (size_t)(r0 + gr    ) * DH + c0 + 8);
            qF[kt][3] = *(const uint32_t*)(qb + (size_t)(r0 + gr + 8) * DH + c0 + 8);
        }
    }

    const __half* ksrc = kmat + (size_t)b * SEQ * DH;
    const __half* vsrc = vmat + (size_t)b * DH * SEQ;

    auto issueKV = [&](int j, int buf) {
        const uint32_t kb = sb + buf * FSTAGE;
        #pragma unroll
        for (int t = 0; t < 8; t++) {
            const int lin = t * 256 + tid;       // 0..2047
            const int r = lin >> 4, s = lin & 15;
            cp16(kb + r * FSTRIDE + s * 16,
                 ksrc + (size_t)(j * 128 + r) * DH + s * 8);
            cp16(kb + FK_TILE + r * FSTRIDE + s * 16,
                 vsrc + (size_t)r * SEQ + j * 128 + s * 8);
        }
    };

    issueKV(0, 0);
    CP_COMMIT();

    float Oacc[17][4];
    #pragma unroll
    for (int i = 0; i < 17; i++)
        #pragma unroll
        for (int k = 0; k < 4; k++) Oacc[i][k] = 0.f;

    for (int j = 0; j < 16; j++) {
        const int buf = j & 1;
        __syncthreads();
        if (j + 1 < 16) issueKV(j + 1, buf ^ 1);
        CP_COMMIT();
        CP_WAIT1();
        __syncthreads();

        const uint32_t kb = sb + buf * FSTAGE;
        const uint32_t vb = kb + FK_TILE;

        // S = q @ k^T (log2-scaled), fp32 acc
        float S[16][4];
        #pragma unroll
        for (int i = 0; i < 16; i++)
            #pragma unroll
            for (int k = 0; k < 4; k++) S[i][k] = 0.f;

        #pragma unroll
        for (int kt = 0; kt < 8; kt++) {
            uint32_t bK[8][4];
            #pragma unroll
            for (int nt = 0; nt < 8; nt++)
                ldm4(bK[nt], kb + (nt * 16 + lrow) * FSTRIDE + kt * 32 + lchk * 16);
            #pragma unroll
            for (int n8 = 0; n8 < 16; n8++) {
                const int g = n8 >> 1, p = n8 & 1;
                mma16816(S[n8], qF[kt], bK[g][p], bK[g][p + 2]);
            }
        }

        // P = 2^(S + bias*log2e) via ex2.approx.f16x2 -> fp16 A fragments
        const float* bp  = bias + ((size_t)h * SEQ + r0 + gr) * SEQ + j * 128;
        const float* bp8 = bp + (size_t)8 * SEQ;
        uint32_t P2[16][2];
        #pragma unroll
        for (int n8 = 0; n8 < 16; n8++) {
            const int cc = n8 * 8 + 2 * tc;
            const float2 b01 = *(const float2*)(bp + cc);
            const float2 b23 = *(const float2*)(bp8 + cc);
            P2[n8][0] = exp2h2(fmaf(b01.x, LOG2E, S[n8][0]),
                               fmaf(b01.y, LOG2E, S[n8][1]));
            P2[n8][1] = exp2h2(fmaf(b23.x, LOG2E, S[n8][2]),
                               fmaf(b23.y, LOG2E, S[n8][3]));
        }

        // Oacc += P @ [V ; ones]   (17 n8 tiles; col 128 = rowsum)
        #pragma unroll
        for (int kp = 0; kp < 8; kp++) {
            uint32_t aP[4];
            aP[0] = P2[2*kp    ][0];
            aP[1] = P2[2*kp    ][1];
            aP[2] = P2[2*kp + 1][0];
            aP[3] = P2[2*kp + 1][1];
            uint32_t bV[9][4];
            #pragma unroll
            for (int nt = 0; nt < 9; nt++)
                ldm4(bV[nt], vb + (nt * 16 + lrow) * FSTRIDE + kp * 32 + lchk * 16);
            #pragma unroll
            for (int n8 = 0; n8 < 17; n8++) {
                const int g = n8 >> 1, p = n8 & 1;
                mma16816(Oacc[n8], aP, bV[g][p], bV[g][p + 2]);
            }
        }
    }

    // rowsums live in col 128 (n8=16, lanes with tc==0)
    const float rs0 = __shfl_sync(0xffffffffu, Oacc[16][0], lane & 28);
    const float rs1 = __shfl_sync(0xffffffffu, Oacc[16][2], lane & 28);
    const float i0 = 1.f / rs0, i1 = 1.f / rs1;

    const size_t orow0 = (size_t)(b * SEQ + r0 + gr    ) * ldo + h * DH;
    const size_t orow1 = (size_t)(b * SEQ + r0 + gr + 8) * ldo + h * DH;
    #pragma unroll
    for (int n8 = 0; n8 < 16; n8++) {
        const int cc = n8 * 8 + 2 * tc;
        *(uint32_t*)(at + orow0 + cc) = pack2(Oacc[n8][0] * i0, Oacc[n8][1] * i0);
        *(uint32_t*)(at + orow1 + cc) = pack2(Oacc[n8][2] * i1, Oacc[n8][3] * i1);
    }
}

// ---------------- RMSNorm -> fp16 ----------------
__global__ __launch_bounds__(256) void rmsnorm_kernel(
    const float* __restrict__ x, const float* __restrict__ gamma,
    __half* __restrict__ xn)
{
    const size_t row = blockIdx.x;
    const float* xr = x + row * DIMC;
    const int t = threadIdx.x;

    float s = 0.f;
    for (int c = t; c < DIMC; c += 256) { float v = xr[c]; s += v * v; }
    __shared__ float red[8];
    #pragma unroll
    for (int o = 16; o; o >>= 1) s += __shfl_xor_sync(0xffffffffu, s, o);
    if ((t & 31) == 0) red[t >> 5] = s;
    __syncthreads();
    float tot = red[0]+red[1]+red[2]+red[3]+red[4]+red[5]+red[6]+red[7];
    float inv = rsqrtf(tot + 1e-5f) * RMS_SCALE;

    for (int c = t; c < DIMC; c += 256)
        xn[row * DIMC + c] = __float2half_rn(xr[c] * inv * gamma[c]);
}

// ---------------- fp32 [R,C] -> transposed fp16 dst[col][dstOff + row] -----
__global__ void transpose_single_kernel(const float* __restrict__ src, int R, int C,
                                        __half* __restrict__ dh, int dstLd, int dstOff)
{
    __shared__ float t[32][33];
    const int cx = blockIdx.x * 32 + threadIdx.x;
    const int ry = blockIdx.y * 32;
    #pragma unroll
    for (int j = 0; j < 32; j += 8)
        t[threadIdx.y + j][threadIdx.x] = src[(size_t)(ry + threadIdx.y + j) * C + cx];
    __syncthreads();
    const int dr0 = blockIdx.x * 32;
    const int dc  = ry + threadIdx.x;
    #pragma unroll
    for (int j = 0; j < 32; j += 8) {
        const size_t o = (size_t)(dr0 + threadIdx.y + j) * dstLd + dstOff + dc;
        dh[o] = __float2half_rn(t[threadIdx.x][threadIdx.y + j]);
    }
}

// ---------------- gathers from proj ----------------
__global__ __launch_bounds__(256) void qt_kernel(
    const __half* __restrict__ pr, __half* __restrict__ q)
{
    const size_t idx = (size_t)blockIdx.x * 256 + threadIdx.x;   // [b][h][i][d]
    const int d = idx & 127;
    const int i = (idx >> 7) & 2047;
    const int h = (idx >> 18) & 15;
    const int b = (int)(idx >> 22);
    const size_t s = (size_t)(b * SEQ + i) * NPROJ + h * DH + d;
    q[idx] = __float2half_rn(__half2float(pr[s]) * (Q_SCALE * LOG2E));
}

__global__ __launch_bounds__(256) void kt_kernel(
    const __half* __restrict__ pr, __half* __restrict__ k)
{
    const size_t idx = (size_t)blockIdx.x * 256 + threadIdx.x;   // [b][j][d]
    const int d = idx & 127;
    const size_t row = idx >> 7;
    k[idx] = pr[row * NPROJ + COL_K + d];
}

__global__ __launch_bounds__(256) void vt_kernel(
    const __half* __restrict__ pr, __half* __restrict__ v)
{
    const size_t idx = (size_t)blockIdx.x * 256 + threadIdx.x;   // [b][d][j]
    const int j = idx & 2047;
    const int d = (idx >> 11) & 127;
    const int b = (int)(idx >> 18);
    v[idx] = pr[(size_t)(b * SEQ + j) * NPROJ + COL_V + d];
}

__global__ __launch_bounds__(256) void swiglu_kernel(
    const __half* __restrict__ pr, __half* __restrict__ cat)
{
    const size_t idx = (size_t)blockIdx.x * 256 + threadIdx.x;   // [row][c<8192]
    const size_t row = idx >> 13;
    const int c = (int)(idx & 8191);
    const float ff = __half2float(pr[row * NPROJ + COL_FF + c]);
    const float g  = __half2float(pr[row * NPROJ + COL_G + c]);
    cat[row * NCAT + 2048 + c] = __float2half_rn(ff * (g / (1.f + __expf(-g))));
}

// ---------------- launch ----------------
extern "C" void kernel_launch(void* const* d_in, const int* in_sizes, int n_in,
                              void* d_out, int out_size)
{
    const float *x = 0, *bias = 0, *gamma = 0, *wi = 0, *attn_wo = 0, *ff_wo = 0;
    for (int i = 0; i < n_in; i++) {
        switch (in_sizes[i]) {
            case  8388608: x       = (const float*)d_in[i]; break;
            case 67108864: bias    = (const float*)d_in[i]; break;
            case     2048: gamma   = (const float*)d_in[i]; break;
            case 38273024: wi      = (const float*)d_in[i]; break;
            case  4194304: attn_wo = (const float*)d_in[i]; break;
            case 16777216: ff_wo   = (const float*)d_in[i]; break;
        }
    }
    float* out = (float*)d_out;

    __half *xn, *wiT, *pr, *qt, *kt, *vt, *cat, *wcat;
    cudaGetSymbolAddress((void**)&xn,   g_xn);
    cudaGetSymbolAddress((void**)&wiT,  g_wiT);
    cudaGetSymbolAddress((void**)&pr,   g_pr);
    cudaGetSymbolAddress((void**)&qt,   g_qt);
    cudaGetSymbolAddress((void**)&kt,   g_kt);
    cudaGetSymbolAddress((void**)&vt,   g_vt);
    cudaGetSymbolAddress((void**)&cat,  g_cat);
    cudaGetSymbolAddress((void**)&wcat, g_wcat);

    cudaFuncSetAttribute(gemm_kernel,
                         cudaFuncAttributeMaxDynamicSharedMemorySize, SMEM_GEMM);
    cudaFuncSetAttribute(flash_kernel,
                         cudaFuncAttributeMaxDynamicSharedMemorySize, SMEM_FLASH);

    // 1. RMSNorm -> xn
    rmsnorm_kernel<<<NROWS, 256>>>(x, gamma, xn);

    // 2. weight transposes -> fp16 (wiT; wcat = [awT | fwT])
    transpose_single_kernel<<<dim3(NPROJ/32, DIMC/32), dim3(32, 8)>>>(wi, DIMC, NPROJ, wiT, DIMC, 0);
    transpose_single_kernel<<<dim3(DIMC/32, DIMC/32),  dim3(32, 8)>>>(attn_wo, DIMC, DIMC, wcat, NCAT, 0);
    transpose_single_kernel<<<dim3(DIMC/32, FFI/32),   dim3(32, 8)>>>(ff_wo, FFI, DIMC, wcat, NCAT, 2048);

    // 3. proj = xn @ wi
    gemm_kernel<<<dim3(NROWS/128, NPROJ/128), 256, SMEM_GEMM>>>(
        xn, DIMC, wiT, DIMC, (float*)0, 0, pr, NPROJ, DIMC);

    // 4. gathers (+ swiglu into cat cols 2048..)
    qt_kernel<<<32768, 256>>>(pr, qt);
    kt_kernel<<<2048, 256>>>(pr, kt);
    vt_kernel<<<2048, 256>>>(pr, vt);
    swiglu_kernel<<<131072, 256>>>(pr, cat);

    // 5. fused attention -> cat cols 0..2047
    flash_kernel<<<dim3(SEQ/128, BATCH*HEADS), 256, SMEM_FLASH>>>(
        qt, kt, vt, bias, cat, NCAT);

    // 6. out = cat @ wcat^T   (K = 10240, single fused output GEMM)
    gemm_kernel<<<dim3(NROWS/128, DIMC/128), 256, SMEM_GEMM>>>(
        cat, NCAT, wcat, NCAT, out, DIMC, (__half*)0, 0, NCAT);
}

// round 12
// speedup vs baseline: 7.4716x; 1.0471x over previous
#include <cuda_runtime.h>
#include <cuda_fp16.h>
#include <math.h>
#include <stdint.h>

// ---------------- problem constants ----------------
#define DIMC   2048
#define SEQ    2048
#define BATCH  2
#define HEADS  16
#define DH     128
#define FFI    8192
#define NPROJ  18688            // 2048+128+128+8192+8192
#define NROWS  4096             // BATCH*SEQ
#define NCAT   10240            // 2048 (attn) + 8192 (ff)
#define RMS_SCALE 45.25483399593904f   // sqrt(2048)
#define Q_SCALE   0.08838834764831845f // 1/sqrt(128)
#define LOG2E     1.4426950408889634f

// gemm smem: 2 stages * 2 tiles * (128 rows * 80B) = 40960
#define TILE_B   10240
#define STAGE_B  20480
#define SMEM_GEMM 40960
// flash smem: 2 stages * (K 128x272 + V 144x272) = 147968
#define FSTRIDE  272
#define FK_TILE  34816
#define FSTAGE   73984
#define SMEM_FLASH 147968

// ---------------- scratch (device globals; allocation-free) ----------------
__device__ __half g_xn  [(size_t)NROWS * DIMC];
__device__ __half g_wiT [(size_t)NPROJ * DIMC];     // PERMUTED: q|k|v|ff/gate interleaved
__device__ __half g_qt  [(size_t)BATCH * HEADS * SEQ * DH];
__device__ __half g_kt  [(size_t)BATCH * SEQ * DH];
__device__ __half g_vt  [(size_t)BATCH * DH * SEQ];
__device__ __half g_cat [(size_t)NROWS * NCAT];     // [at | h]
__device__ __half g_wcat[(size_t)DIMC * NCAT];      // [awT | fwT]

// ---------------- helpers ----------------
__device__ __forceinline__ uint32_t smem_u32(const void* p) {
    uint32_t a;
    asm("{ .reg .u64 t; cvta.to.shared.u64 t, %1; cvt.u32.u64 %0, t; }"
        : "=r"(a) : "l"(p));
    return a;
}
__device__ __forceinline__ void ldm4(uint32_t* r, uint32_t a) {
    asm volatile("ldmatrix.sync.aligned.m8n8.x4.shared.b16 {%0,%1,%2,%3}, [%4];"
                 : "=r"(r[0]), "=r"(r[1]), "=r"(r[2]), "=r"(r[3]) : "r"(a));
}
__device__ __forceinline__ void mma16816(float* d, const uint32_t* a,
                                         uint32_t b0, uint32_t b1) {
    asm volatile(
        "mma.sync.aligned.m16n8k16.row.col.f32.f16.f16.f32 "
        "{%0,%1,%2,%3}, {%4,%5,%6,%7}, {%8,%9}, {%0,%1,%2,%3};"
        : "+f"(d[0]), "+f"(d[1]), "+f"(d[2]), "+f"(d[3])
        : "r"(a[0]), "r"(a[1]), "r"(a[2]), "r"(a[3]), "r"(b0), "r"(b1));
}
__device__ __forceinline__ void cp16(uint32_t s, const void* g) {
    asm volatile("cp.async.cg.shared.global [%0], [%1], 16;" :: "r"(s), "l"(g));
}
#define CP_COMMIT() asm volatile("cp.async.commit_group;")
#define CP_WAIT1()  asm volatile("cp.async.wait_group 1;" ::: "memory")
__device__ __forceinline__ uint32_t pack2(float v0, float v1) {
    __half2 H = __floats2half2_rn(v0, v1);
    return *(uint32_t*)&H;
}
__device__ __forceinline__ uint32_t exp2h2(float v0, float v1) {
    uint32_t p = pack2(v0, v1), r;
    asm("ex2.approx.f16x2 %0, %1;" : "=r"(r) : "r"(p));
    return r;
}

// ================== GEMM mainloop (shared by both kernels) ==================
#define GEMM_MAIN(Aptr, lda_, Bptr, ldb_, Kdim)                                         \
    float acc[2][8][4];                                                                 \
    _Pragma("unroll")                                                                   \
    for (int i = 0; i < 2; i++)                                                         \
        _Pragma("unroll")                                                               \
        for (int j = 0; j < 8; j++)                                                     \
            _Pragma("unroll")                                                           \
            for (int k = 0; k < 4; k++) acc[i][j][k] = 0.f;                             \
    const int NC = (Kdim) >> 5;                                                         \
    cp16(sb + 0*TILE_B + ldr0*80 + ldc0*16, (Aptr) + (size_t)(row0+ldr0)*(lda_) + ldc0*8); \
    cp16(sb + 0*TILE_B + ldr1*80 + ldc1*16, (Aptr) + (size_t)(row0+ldr1)*(lda_) + ldc1*8); \
    cp16(sb + 1*TILE_B + ldr0*80 + ldc0*16, (Bptr) + (size_t)(col0+ldr0)*(ldb_) + ldc0*8); \
    cp16(sb + 1*TILE_B + ldr1*80 + ldc1*16, (Bptr) + (size_t)(col0+ldr1)*(ldb_) + ldc1*8); \
    CP_COMMIT();                                                                        \
    const int lrow = lane & 15;                                                         \
    const int lchk = lane >> 4;                                                         \
    for (int c = 0; c < NC; c++) {                                                      \
        const int buf = c & 1;                                                          \
        __syncthreads();                                                                \
        if (c + 1 < NC) {                                                               \
            const int k0 = (c + 1) << 5;                                                \
            const uint32_t db = sb + (buf ^ 1) * STAGE_B;                               \
            cp16(db + 0*TILE_B + ldr0*80 + ldc0*16, (Aptr) + (size_t)(row0+ldr0)*(lda_) + k0 + ldc0*8); \
            cp16(db + 0*TILE_B + ldr1*80 + ldc1*16, (Aptr) + (size_t)(row0+ldr1)*(lda_) + k0 + ldc1*8); \
            cp16(db + 1*TILE_B + ldr0*80 + ldc0*16, (Bptr) + (size_t)(col0+ldr0)*(ldb_) + k0 + ldc0*8); \
            cp16(db + 1*TILE_B + ldr1*80 + ldc1*16, (Bptr) + (size_t)(col0+ldr1)*(ldb_) + k0 + ldc1*8); \
        }                                                                               \
        CP_COMMIT();                                                                    \
        CP_WAIT1();                                                                     \
        __syncthreads();                                                                \
        const uint32_t tb = sb + buf * STAGE_B;                                         \
        _Pragma("unroll")                                                               \
        for (int kk = 0; kk < 2; kk++) {                                                \
            const int ch0 = kk * 2;                                                     \
            uint32_t aF[2][4], bF[4][4];                                                \
            _Pragma("unroll")                                                           \
            for (int mt = 0; mt < 2; mt++)                                              \
                ldm4(aF[mt], tb + (mw*32 + mt*16 + lrow)*80 + (ch0 + lchk)*16);         \
            _Pragma("unroll")                                                           \
            for (int nt = 0; nt < 4; nt++)                                              \
                ldm4(bF[nt], tb + TILE_B + (nw*64 + nt*16 + lrow)*80 + (ch0 + lchk)*16);\
            _Pragma("unroll")                                                           \
            for (int mt = 0; mt < 2; mt++) {                                            \
                _Pragma("unroll")                                                       \
                for (int n8 = 0; n8 < 8; n8++) {                                        \
                    const int g = n8 >> 1, p = n8 & 1;                                  \
                    mma16816(acc[mt][n8], aF[mt], bF[g][p], bF[g][p + 2]);              \
                }                                                                       \
            }                                                                           \
        }                                                                               \
    }

// ---------------- plain GEMM (final output) ----------------
__global__ __launch_bounds__(256, 2) void gemm_kernel(
    const __half* __restrict__ A, int lda,
    const __half* __restrict__ B, int ldb,
    float* __restrict__ C, int ldc, int K)
{
    extern __shared__ char smem[];
    const uint32_t sb = smem_u32(smem);
    const int tid  = threadIdx.x;
    const int wid  = tid >> 5;
    const int lane = tid & 31;
    const int mw   = wid & 3;
    const int nw   = wid >> 2;
    const int row0 = blockIdx.x * 128, col0 = blockIdx.y * 128;
    const int ldr0 = (tid + 0)   >> 2, ldc0 = (tid + 0)   & 3;
    const int ldr1 = (tid + 256) >> 2, ldc1 = (tid + 256) & 3;

    GEMM_MAIN(A, lda, B, ldb, K)

    const int tr  = lane >> 2;
    const int tc2 = (lane & 3) * 2;
    #pragma unroll
    for (int mt = 0; mt < 2; mt++)
        #pragma unroll
        for (int hf = 0; hf < 2; hf++) {
            const int r = row0 + mw*32 + mt*16 + hf*8 + tr;
            #pragma unroll
            for (int n8 = 0; n8 < 8; n8++) {
                const int cc = col0 + nw*64 + n8*8 + tc2;
                float* cp = C + (size_t)r * ldc + cc;
                cp[0] = acc[mt][n8][hf*2 + 0];
                cp[1] = acc[mt][n8][hf*2 + 1];
            }
        }
}

// ---------------- proj GEMM with fused gather epilogue ----------------
// B = permuted wiT: rows 0..2047 q, 2048..2175 k, 2176..2303 v,
//                   2304..18687 interleaved (even=ff_j, odd=gate_j).
__global__ __launch_bounds__(256, 2) void proj_kernel(
    const __half* __restrict__ A, int lda,
    const __half* __restrict__ B, int ldb,
    __half* __restrict__ q, __half* __restrict__ kmat,
    __half* __restrict__ vmat, __half* __restrict__ cat, int K)
{
    extern __shared__ char smem[];
    const uint32_t sb = smem_u32(smem);
    const int tid  = threadIdx.x;
    const int wid  = tid >> 5;
    const int lane = tid & 31;
    const int mw   = wid & 3;
    const int nw   = wid >> 2;
    const int row0 = blockIdx.x * 128, col0 = blockIdx.y * 128;
    const int ldr0 = (tid + 0)   >> 2, ldc0 = (tid + 0)   & 3;
    const int ldr1 = (tid + 256) >> 2, ldc1 = (tid + 256) & 3;

    GEMM_MAIN(A, lda, B, ldb, K)

    const int tr  = lane >> 2;
    const int tc2 = (lane & 3) * 2;

    #pragma unroll
    for (int mt = 0; mt < 2; mt++)
        #pragma unroll
        for (int hf = 0; hf < 2; hf++) {
            const int r = row0 + mw*32 + mt*16 + hf*8 + tr;
            const int i = r & 2047, b = r >> 11;
            #pragma unroll
            for (int n8 = 0; n8 < 8; n8++) {
                const int cc = col0 + nw*64 + n8*8 + tc2;
                const float v0 = acc[mt][n8][hf*2 + 0];
                const float v1 = acc[mt][n8][hf*2 + 1];
                if (col0 < 2048) {
                    // q[z][i][d], pre-scaled by Q_SCALE*LOG2E
                    const int h = cc >> 7, d = cc & 127;
                    const size_t o = ((size_t)(b * HEADS + h) * SEQ + i) * DH + d;
                    *(uint32_t*)(q + o) = pack2(v0 * (Q_SCALE * LOG2E),
                                                v1 * (Q_SCALE * LOG2E));
                } else if (col0 == 2048) {
                    // k[b][j][d]: row-major = r*128 + d
                    const int d = cc - 2048;
                    *(uint32_t*)(kmat + (size_t)r * DH + d) = pack2(v0, v1);
                } else if (col0 == 2176) {
                    // v[b][d][j]: scattered transpose (small region)
                    const int d = cc - 2176;
                    const size_t o = (size_t)b * DH * SEQ + (size_t)d * SEQ + i;
                    vmat[o]       = __float2half_rn(v0);
                    vmat[o + SEQ] = __float2half_rn(v1);
                } else {
                    // interleaved ff/gate: v0 = ff_j, v1 = gate_j
                    const int jp = (cc - 2304) >> 1;
                    const float sw = v1 / (1.f + __expf(-v1));
                    cat[(size_t)r * NCAT + 2048 + jp] = __float2half_rn(v0 * sw);
                }
            }
        }
}

// ---------------- fused flash attention ----------------
__global__ __launch_bounds__(256) void flash_kernel(
    const __half* __restrict__ q,      // [z][i][dh]  (pre-scaled by Q_SCALE*log2e)
    const __half* __restrict__ kmat,   // [b][key][dh]
    const __half* __restrict__ vmat,   // [b][dh][key]
    const float* __restrict__ bias,    // [h][i][j]
    __half* __restrict__ at, int ldo)
{
    extern __shared__ char smem[];
    const uint32_t sb = smem_u32(smem);
    const int tid  = threadIdx.x;
    const int wid  = tid >> 5;
    const int lane = tid & 31;
    const int gr   = lane >> 2;
    const int tc   = lane & 3;
    const int lrow = lane & 15;
    const int lchk = lane >> 4;

    const int z = blockIdx.y, b = z >> 4, h = z & 15;
    const int r0 = blockIdx.x * 128 + wid * 16;

    // init ones-row (dh=128) and zero rows of both V buffers
    #pragma unroll
    for (int bufi = 0; bufi < 2; bufi++) {
        char* vrows = smem + bufi * FSTAGE + FK_TILE + 128 * FSTRIDE;
        for (int i = tid; i < 16 * 136; i += 256) {
            const int r = i / 136, cc = i % 136;
            *(__half*)(vrows + r * FSTRIDE + cc * 2) =
                (r == 0) ? __float2half(1.0f) : __float2half(0.0f);
        }
    }

    uint32_t qF[8][4];
    {
        const __half* qb = q + (size_t)z * SEQ * DH;
        #pragma unroll
        for (int kt = 0; kt < 8; kt++) {
            const int c0 = kt * 16 + 2 * tc;
            qF[kt][0] = *(const uint32_t*)(qb + (size_t)(r0 + gr    ) * DH + c0);
            qF[kt][1] = *(const uint32_t*)(qb + (size_t)(r0 + gr + 8) * DH + c0);
            qF[kt][2] = *(const uint32_t*)(qb + (size_t)(r0 + gr    ) * DH + c0 + 8);
            qF[kt][3] = *(const uint32_t*)(qb + (size_t)(r0 + gr + 8) * DH + c0 + 8);
        }
    }

    const __half* ksrc = kmat + (size_t)b * SEQ * DH;
    const __half* vsrc = vmat + (size_t)b * DH * SEQ;

    auto issueKV = [&](int j, int buf) {
        const uint32_t kb = sb + buf * FSTAGE;
        #pragma unroll
        for (int t = 0; t < 8; t++) {
            const int lin = t * 256 + tid;
            const int r = lin >> 4, s = lin & 15;
            cp16(kb + r * FSTRIDE + s * 16,
                 ksrc + (size_t)(j * 128 + r) * DH + s * 8);
            cp16(kb + FK_TILE + r * FSTRIDE + s * 16,
                 vsrc + (size_t)r * SEQ + j * 128 + s * 8);
        }
    };

    issueKV(0, 0);
    CP_COMMIT();

    float Oacc[17][4];
    #pragma unroll
    for (int i = 0; i < 17; i++)
        #pragma unroll
        for (int k = 0; k < 4; k++) Oacc[i][k] = 0.f;

    for (int j = 0; j < 16; j++) {
        const int buf = j & 1;
        __syncthreads();
        if (j + 1 < 16) issueKV(j + 1, buf ^ 1);
        CP_COMMIT();
        CP_WAIT1();
        __syncthreads();

        const uint32_t kb = sb + buf * FSTAGE;
        const uint32_t vb = kb + FK_TILE;

        float S[16][4];
        #pragma unroll
        for (int i = 0; i < 16; i++)
            #pragma unroll
            for (int k = 0; k < 4; k++) S[i][k] = 0.f;

        #pragma unroll
        for (int kt = 0; kt < 8; kt++) {
            uint32_t bK[8][4];
            #pragma unroll
            for (int nt = 0; nt < 8; nt++)
                ldm4(bK[nt], kb + (nt * 16 + lrow) * FSTRIDE + kt * 32 + lchk * 16);
            #pragma unroll
            for (int n8 = 0; n8 < 16; n8++) {
                const int g = n8 >> 1, p = n8 & 1;
                mma16816(S[n8], qF[kt], bK[g][p], bK[g][p + 2]);
            }
        }

        const float* bp  = bias + ((size_t)h * SEQ + r0 + gr) * SEQ + j * 128;
        const float* bp8 = bp + (size_t)8 * SEQ;
        uint32_t P2[16][2];
        #pragma unroll
        for (int n8 = 0; n8 < 16; n8++) {
            const int cc = n8 * 8 + 2 * tc;
            const float2 b01 = *(const float2*)(bp + cc);
            const float2 b23 = *(const float2*)(bp8 + cc);
            P2[n8][0] = exp2h2(fmaf(b01.x, LOG2E, S[n8][0]),
                               fmaf(b01.y, LOG2E, S[n8][1]));
            P2[n8][1] = exp2h2(fmaf(b23.x, LOG2E, S[n8][2]),
                               fmaf(b23.y, LOG2E, S[n8][3]));
        }

        #pragma unroll
        for (int kp = 0; kp < 8; kp++) {
            uint32_t aP[4];
            aP[0] = P2[2*kp    ][0];
            aP[1] = P2[2*kp    ][1];
            aP[2] = P2[2*kp + 1][0];
            aP[3] = P2[2*kp + 1][1];
            uint32_t bV[9][4];
            #pragma unroll
            for (int nt = 0; nt < 9; nt++)
                ldm4(bV[nt], vb + (nt * 16 + lrow) * FSTRIDE + kp * 32 + lchk * 16);
            #pragma unroll
            for (int n8 = 0; n8 < 17; n8++) {
                const int g = n8 >> 1, p = n8 & 1;
                mma16816(Oacc[n8], aP, bV[g][p], bV[g][p + 2]);
            }
        }
    }

    const float rs0 = __shfl_sync(0xffffffffu, Oacc[16][0], lane & 28);
    const float rs1 = __shfl_sync(0xffffffffu, Oacc[16][2], lane & 28);
    const float i0 = 1.f / rs0, i1 = 1.f / rs1;

    const size_t orow0 = (size_t)(b * SEQ + r0 + gr    ) * ldo + h * DH;
    const size_t orow1 = (size_t)(b * SEQ + r0 + gr + 8) * ldo + h * DH;
    #pragma unroll
    for (int n8 = 0; n8 < 16; n8++) {
        const int cc = n8 * 8 + 2 * tc;
        *(uint32_t*)(at + orow0 + cc) = pack2(Oacc[n8][0] * i0, Oacc[n8][1] * i0);
        *(uint32_t*)(at + orow1 + cc) = pack2(Oacc[n8][2] * i1, Oacc[n8][3] * i1);
    }
}

// ---------------- RMSNorm -> fp16 ----------------
__global__ __launch_bounds__(256) void rmsnorm_kernel(
    const float* __restrict__ x, const float* __restrict__ gamma,
    __half* __restrict__ xn)
{
    const size_t row = blockIdx.x;
    const float* xr = x + row * DIMC;
    const int t = threadIdx.x;

    float s = 0.f;
    for (int c = t; c < DIMC; c += 256) { float v = xr[c]; s += v * v; }
    __shared__ float red[8];
    #pragma unroll
    for (int o = 16; o; o >>= 1) s += __shfl_xor_sync(0xffffffffu, s, o);
    if ((t & 31) == 0) red[t >> 5] = s;
    __syncthreads();
    float tot = red[0]+red[1]+red[2]+red[3]+red[4]+red[5]+red[6]+red[7];
    float inv = rsqrtf(tot + 1e-5f) * RMS_SCALE;

    for (int c = t; c < DIMC; c += 256)
        xn[row * DIMC + c] = __float2half_rn(xr[c] * inv * gamma[c]);
}

// ---------------- fp32 -> transposed fp16 with row/col mapping -------------
// dst[rowBase + rowMul*(srcColRel)][colOff + srcRow] (fp16), src cols from colBase.
__global__ void transpose_perm_kernel(const float* __restrict__ src, int C, int colBase,
                                      __half* __restrict__ dst, int dstLd,
                                      int rowBase, int rowMul, int colOff)
{
    __shared__ float t[32][33];
    const int cx = colBase + blockIdx.x * 32 + threadIdx.x;
    const int ry = blockIdx.y * 32;
    #pragma unroll
    for (int j = 0; j < 32; j += 8)
        t[threadIdx.y + j][threadIdx.x] = src[(size_t)(ry + threadIdx.y + j) * C + cx];
    __syncthreads();
    const int colRel0 = blockIdx.x * 32;
    const int dc = ry + threadIdx.x;
    #pragma unroll
    for (int j = 0; j < 32; j += 8) {
        const size_t drow = (size_t)rowBase + (size_t)rowMul * (colRel0 + threadIdx.y + j);
        dst[drow * dstLd + colOff + dc] = __float2half_rn(t[threadIdx.x][threadIdx.y + j]);
    }
}

// ---------------- launch ----------------
extern "C" void kernel_launch(void* const* d_in, const int* in_sizes, int n_in,
                              void* d_out, int out_size)
{
    const float *x = 0, *bias = 0, *gamma = 0, *wi = 0, *attn_wo = 0, *ff_wo = 0;
    for (int i = 0; i < n_in; i++) {
        switch (in_sizes[i]) {
            case  8388608: x       = (const float*)d_in[i]; break;
            case 67108864: bias    = (const float*)d_in[i]; break;
            case     2048: gamma   = (const float*)d_in[i]; break;
            case 38273024: wi      = (const float*)d_in[i]; break;
            case  4194304: attn_wo = (const float*)d_in[i]; break;
            case 16777216: ff_wo   = (const float*)d_in[i]; break;
        }
    }
    float* out = (float*)d_out;

    __half *xn, *wiT, *qt, *kt, *vt, *cat, *wcat;
    cudaGetSymbolAddress((void**)&xn,   g_xn);
    cudaGetSymbolAddress((void**)&wiT,  g_wiT);
    cudaGetSymbolAddress((void**)&qt,   g_qt);
    cudaGetSymbolAddress((void**)&kt,   g_kt);
    cudaGetSymbolAddress((void**)&vt,   g_vt);
    cudaGetSymbolAddress((void**)&cat,  g_cat);
    cudaGetSymbolAddress((void**)&wcat, g_wcat);

    cudaFuncSetAttribute(gemm_kernel,
                         cudaFuncAttributeMaxDynamicSharedMemorySize, SMEM_GEMM);
    cudaFuncSetAttribute(proj_kernel,
                         cudaFuncAttributeMaxDynamicSharedMemorySize, SMEM_GEMM);
    cudaFuncSetAttribute(flash_kernel,
                         cudaFuncAttributeMaxDynamicSharedMemorySize, SMEM_FLASH);

    // 1. RMSNorm -> xn
    rmsnorm_kernel<<<NROWS, 256>>>(x, gamma, xn);

    // 2. build PERMUTED wiT:
    //    rows 0..2303  <- wi cols 0..2303 (q|k|v)
    //    rows 2304+2j  <- wi col 2304+j   (ff)
    //    rows 2305+2j  <- wi col 10496+j  (gate)
    transpose_perm_kernel<<<dim3(2304/32, DIMC/32), dim3(32, 8)>>>(
        wi, NPROJ, 0, wiT, DIMC, 0, 1, 0);
    transpose_perm_kernel<<<dim3(FFI/32, DIMC/32), dim3(32, 8)>>>(
        wi, NPROJ, 2304, wiT, DIMC, 2304, 2, 0);
    transpose_perm_kernel<<<dim3(FFI/32, DIMC/32), dim3(32, 8)>>>(
        wi, NPROJ, 10496, wiT, DIMC, 2305, 2, 0);
    //    wcat[outcol][k] = [awT | fwT]: attn_wo cols -> rows, ff_wo k at colOff 2048
    transpose_perm_kernel<<<dim3(DIMC/32, DIMC/32), dim3(32, 8)>>>(
        attn_wo, DIMC, 0, wcat, NCAT, 0, 1, 0);
    transpose_perm_kernel<<<dim3(DIMC/32, FFI/32), dim3(32, 8)>>>(
        ff_wo, DIMC, 0, wcat, NCAT, 0, 1, 2048);

    // 3. proj GEMM with fused gather/swiglu epilogue
    proj_kernel<<<dim3(NROWS/128, NPROJ/128), 256, SMEM_GEMM>>>(
        xn, DIMC, wiT, DIMC, qt, kt, vt, cat, DIMC);

    // 4. fused attention -> cat cols 0..2047
    flash_kernel<<<dim3(SEQ/128, BATCH*HEADS), 256, SMEM_FLASH>>>(
        qt, kt, vt, bias, cat, NCAT);

    // 5. out = cat @ wcat^T (K = 10240)
    gemm_kernel<<<dim3(NROWS/128, DIMC/128), 256, SMEM_GEMM>>>(
        cat, NCAT, wcat, NCAT, out, DIMC, NCAT);
}

// round 13
// speedup vs baseline: 7.8281x; 1.0477x over previous
#include <cuda_runtime.h>
#include <cuda_fp16.h>
#include <math.h>
#include <stdint.h>

// ---------------- problem constants ----------------
#define DIMC   2048
#define SEQ    2048
#define BATCH  2
#define HEADS  16
#define DH     128
#define FFI    8192
#define NPROJ  18688            // 2048+128+128+8192+8192
#define NROWS  4096             // BATCH*SEQ
#define NCAT   10240            // 2048 (attn) + 8192 (ff)
#define RMS_SCALE 45.25483399593904f   // sqrt(2048)
#define Q_SCALE   0.08838834764831845f // 1/sqrt(128)
#define LOG2E     1.4426950408889634f

// gemm smem: 3 stages * 2 tiles * (128 rows * 80B) = 61440
#define TILE_B   10240
#define STAGE_B  20480
#define SMEM_GEMM 61440
// flash smem: 2 stages * (K 128x272 + V 144x272) = 147968
#define FSTRIDE  272
#define FK_TILE  34816
#define FSTAGE   73984
#define SMEM_FLASH 147968

// ---------------- scratch (device globals; allocation-free) ----------------
__device__ __half g_xn  [(size_t)NROWS * DIMC];
__device__ __half g_wiT [(size_t)NPROJ * DIMC];     // PERMUTED: q|k|v|ff/gate interleaved
__device__ __half g_qt  [(size_t)BATCH * HEADS * SEQ * DH];
__device__ __half g_kt  [(size_t)BATCH * SEQ * DH];
__device__ __half g_vt  [(size_t)BATCH * DH * SEQ];
__device__ __half g_cat [(size_t)NROWS * NCAT];     // [at | h]
__device__ __half g_wcat[(size_t)DIMC * NCAT];      // [awT | fwT]

// ---------------- helpers ----------------
__device__ __forceinline__ uint32_t smem_u32(const void* p) {
    uint32_t a;
    asm("{ .reg .u64 t; cvta.to.shared.u64 t, %1; cvt.u32.u64 %0, t; }"
        : "=r"(a) : "l"(p));
    return a;
}
__device__ __forceinline__ void ldm4(uint32_t* r, uint32_t a) {
    asm volatile("ldmatrix.sync.aligned.m8n8.x4.shared.b16 {%0,%1,%2,%3}, [%4];"
                 : "=r"(r[0]), "=r"(r[1]), "=r"(r[2]), "=r"(r[3]) : "r"(a));
}
__device__ __forceinline__ void mma16816(float* d, const uint32_t* a,
                                         uint32_t b0, uint32_t b1) {
    asm volatile(
        "mma.sync.aligned.m16n8k16.row.col.f32.f16.f16.f32 "
        "{%0,%1,%2,%3}, {%4,%5,%6,%7}, {%8,%9}, {%0,%1,%2,%3};"
        : "+f"(d[0]), "+f"(d[1]), "+f"(d[2]), "+f"(d[3])
        : "r"(a[0]), "r"(a[1]), "r"(a[2]), "r"(a[3]), "r"(b0), "r"(b1));
}
__device__ __forceinline__ void cp16(uint32_t s, const void* g) {
    asm volatile("cp.async.cg.shared.global [%0], [%1], 16;" :: "r"(s), "l"(g));
}
#define CP_COMMIT() asm volatile("cp.async.commit_group;")
#define CP_WAITG1() asm volatile("cp.async.wait_group 1;" ::: "memory")
__device__ __forceinline__ uint32_t pack2(float v0, float v1) {
    __half2 H = __floats2half2_rn(v0, v1);
    return *(uint32_t*)&H;
}
__device__ __forceinline__ uint32_t exp2h2(float v0, float v1) {
    uint32_t p = pack2(v0, v1), r;
    asm("ex2.approx.f16x2 %0, %1;" : "=r"(r) : "r"(p));
    return r;
}

// ============ GEMM mainloop: 3-stage cp.async, ONE sync per chunk ===========
#define GEMM_ISSUE(cidx, Aptr, lda_, Bptr, ldb_)                                        \
    {                                                                                   \
        const int k0i = (cidx) << 5;                                                    \
        const uint32_t db = sb + ((cidx) % 3) * STAGE_B;                                \
        cp16(db + 0*TILE_B + ldr0*80 + ldc0*16, (Aptr) + (size_t)(row0+ldr0)*(lda_) + k0i + ldc0*8); \
        cp16(db + 0*TILE_B + ldr1*80 + ldc1*16, (Aptr) + (size_t)(row0+ldr1)*(lda_) + k0i + ldc1*8); \
        cp16(db + 1*TILE_B + ldr0*80 + ldc0*16, (Bptr) + (size_t)(col0+ldr0)*(ldb_) + k0i + ldc0*8); \
        cp16(db + 1*TILE_B + ldr1*80 + ldc1*16, (Bptr) + (size_t)(col0+ldr1)*(ldb_) + k0i + ldc1*8); \
    }

#define GEMM_MAIN(Aptr, lda_, Bptr, ldb_, Kdim)                                         \
    float acc[2][8][4];                                                                 \
    _Pragma("unroll")                                                                   \
    for (int i = 0; i < 2; i++)                                                         \
        _Pragma("unroll")                                                               \
        for (int j = 0; j < 8; j++)                                                     \
            _Pragma("unroll")                                                           \
            for (int k = 0; k < 4; k++) acc[i][j][k] = 0.f;                             \
    const int NC = (Kdim) >> 5;                                                         \
    const int lrow = lane & 15;                                                         \
    const int lchk = lane >> 4;                                                         \
    GEMM_ISSUE(0, Aptr, lda_, Bptr, ldb_); CP_COMMIT();                                 \
    GEMM_ISSUE(1, Aptr, lda_, Bptr, ldb_); CP_COMMIT();                                 \
    for (int c = 0; c < NC; c++) {                                                      \
        CP_WAITG1();                       /* chunk c resident */                       \
        __syncthreads();                   /* prev compute drained */                   \
        if (c + 2 < NC) GEMM_ISSUE(c + 2, Aptr, lda_, Bptr, ldb_);                      \
        CP_COMMIT();                                                                    \
        const uint32_t tb = sb + (c % 3) * STAGE_B;                                     \
        _Pragma("unroll")                                                               \
        for (int kk = 0; kk < 2; kk++) {                                                \
            const int ch0 = kk * 2;                                                     \
            uint32_t aF[2][4], bF[4][4];                                                \
            _Pragma("unroll")                                                           \
            for (int mt = 0; mt < 2; mt++)                                              \
                ldm4(aF[mt], tb + (mw*32 + mt*16 + lrow)*80 + (ch0 + lchk)*16);         \
            _Pragma("unroll")                                                           \
            for (int nt = 0; nt < 4; nt++)                                              \
                ldm4(bF[nt], tb + TILE_B + (nw*64 + nt*16 + lrow)*80 + (ch0 + lchk)*16);\
            _Pragma("unroll")                                                           \
            for (int mt = 0; mt < 2; mt++) {                                            \
                _Pragma("unroll")                                                       \
                for (int n8 = 0; n8 < 8; n8++) {                                        \
                    const int g = n8 >> 1, p = n8 & 1;                                  \
                    mma16816(acc[mt][n8], aF[mt], bF[g][p], bF[g][p + 2]);              \
                }                                                                       \
            }                                                                           \
        }                                                                               \
    }

// ---------------- plain GEMM (final output) ----------------
__global__ __launch_bounds__(256, 2) void gemm_kernel(
    const __half* __restrict__ A, int lda,
    const __half* __restrict__ B, int ldb,
    float* __restrict__ C, int ldc, int K)
{
    extern __shared__ char smem[];
    const uint32_t sb = smem_u32(smem);
    const int tid  = threadIdx.x;
    const int wid  = tid >> 5;
    const int lane = tid & 31;
    const int mw   = wid & 3;
    const int nw   = wid >> 2;
    const int row0 = blockIdx.x * 128, col0 = blockIdx.y * 128;
    const int ldr0 = (tid + 0)   >> 2, ldc0 = (tid + 0)   & 3;
    const int ldr1 = (tid + 256) >> 2, ldc1 = (tid + 256) & 3;

    GEMM_MAIN(A, lda, B, ldb, K)

    const int tr  = lane >> 2;
    const int tc2 = (lane & 3) * 2;
    #pragma unroll
    for (int mt = 0; mt < 2; mt++)
        #pragma unroll
        for (int hf = 0; hf < 2; hf++) {
            const int r = row0 + mw*32 + mt*16 + hf*8 + tr;
            #pragma unroll
            for (int n8 = 0; n8 < 8; n8++) {
                const int cc = col0 + nw*64 + n8*8 + tc2;
                float* cp = C + (size_t)r * ldc + cc;
                cp[0] = acc[mt][n8][hf*2 + 0];
                cp[1] = acc[mt][n8][hf*2 + 1];
            }
        }
}

// ---------------- proj GEMM with fused gather epilogue ----------------
// B = permuted wiT: rows 0..2047 q, 2048..2175 k, 2176..2303 v,
//                   2304..18687 interleaved (even=ff_j, odd=gate_j).
__global__ __launch_bounds__(256, 2) void proj_kernel(
    const __half* __restrict__ A, int lda,
    const __half* __restrict__ B, int ldb,
    __half* __restrict__ q, __half* __restrict__ kmat,
    __half* __restrict__ vmat, __half* __restrict__ cat, int K)
{
    extern __shared__ char smem[];
    const uint32_t sb = smem_u32(smem);
    const int tid  = threadIdx.x;
    const int wid  = tid >> 5;
    const int lane = tid & 31;
    const int mw   = wid & 3;
    const int nw   = wid >> 2;
    const int row0 = blockIdx.x * 128, col0 = blockIdx.y * 128;
    const int ldr0 = (tid + 0)   >> 2, ldc0 = (tid + 0)   & 3;
    const int ldr1 = (tid + 256) >> 2, ldc1 = (tid + 256) & 3;

    GEMM_MAIN(A, lda, B, ldb, K)

    const int tr  = lane >> 2;
    const int tc2 = (lane & 3) * 2;

    #pragma unroll
    for (int mt = 0; mt < 2; mt++)
        #pragma unroll
        for (int hf = 0; hf < 2; hf++) {
            const int r = row0 + mw*32 + mt*16 + hf*8 + tr;
            const int i = r & 2047, b = r >> 11;
            #pragma unroll
            for (int n8 = 0; n8 < 8; n8++) {
                const int cc = col0 + nw*64 + n8*8 + tc2;
                const float v0 = acc[mt][n8][hf*2 + 0];
                const float v1 = acc[mt][n8][hf*2 + 1];
                if (col0 < 2048) {
                    // q[z][i][d], pre-scaled by Q_SCALE*LOG2E
                    const int h = cc >> 7, d = cc & 127;
                    const size_t o = ((size_t)(b * HEADS + h) * SEQ + i) * DH + d;
                    *(uint32_t*)(q + o) = pack2(v0 * (Q_SCALE * LOG2E),
                                                v1 * (Q_SCALE * LOG2E));
                } else if (col0 == 2048) {
                    // k[b][j][d]
                    const int d = cc - 2048;
                    *(uint32_t*)(kmat + (size_t)r * DH + d) = pack2(v0, v1);
                } else if (col0 == 2176) {
                    // v[b][d][j]: scattered transpose (small region)
                    const int d = cc - 2176;
                    const size_t o = (size_t)b * DH * SEQ + (size_t)d * SEQ + i;
                    vmat[o]       = __float2half_rn(v0);
                    vmat[o + SEQ] = __float2half_rn(v1);
                } else {
                    // interleaved ff/gate: v0 = ff_j, v1 = gate_j
                    const int jp = (cc - 2304) >> 1;
                    const float sw = v1 / (1.f + __expf(-v1));
                    cat[(size_t)r * NCAT + 2048 + jp] = __float2half_rn(v0 * sw);
                }
            }
        }
}

// ---------------- fused flash attention ----------------
__global__ __launch_bounds__(256) void flash_kernel(
    const __half* __restrict__ q,      // [z][i][dh]  (pre-scaled by Q_SCALE*log2e)
    const __half* __restrict__ kmat,   // [b][key][dh]
    const __half* __restrict__ vmat,   // [b][dh][key]
    const float* __restrict__ bias,    // [h][i][j]
    __half* __restrict__ at, int ldo)
{
    extern __shared__ char smem[];
    const uint32_t sb = smem_u32(smem);
    const int tid  = threadIdx.x;
    const int wid  = tid >> 5;
    const int lane = tid & 31;
    const int gr   = lane >> 2;
    const int tc   = lane & 3;
    const int lrow = lane & 15;
    const int lchk = lane >> 4;

    const int z = blockIdx.y, b = z >> 4, h = z & 15;
    const int r0 = blockIdx.x * 128 + wid * 16;

    // init ones-row (dh=128) and zero rows of both V buffers
    #pragma unroll
    for (int bufi = 0; bufi < 2; bufi++) {
        char* vrows = smem + bufi * FSTAGE + FK_TILE + 128 * FSTRIDE;
        for (int i = tid; i < 16 * 136; i += 256) {
            const int r = i / 136, cc = i % 136;
            *(__half*)(vrows + r * FSTRIDE + cc * 2) =
                (r == 0) ? __float2half(1.0f) : __float2half(0.0f);
        }
    }

    uint32_t qF[8][4];
    {
        const __half* qb = q + (size_t)z * SEQ * DH;
        #pragma unroll
        for (int kt = 0; kt < 8; kt++) {
            const int c0 = kt * 16 + 2 * tc;
            qF[kt][0] = *(const uint32_t*)(qb + (size_t)(r0 + gr    ) * DH + c0);
            qF[kt][1] = *(const uint32_t*)(qb + (size_t)(r0 + gr + 8) * DH + c0);
            qF[kt][2] = *(const uint32_t*)(qb + (size_t)(r0 + gr    ) * DH + c0 + 8);
            qF[kt][3] = *(const uint32_t*)(qb + (size_t)(r0 + gr + 8) * DH + c0 + 8);
        }
    }

    const __half* ksrc = kmat + (size_t)b * SEQ * DH;
    const __half* vsrc = vmat + (size_t)b * DH * SEQ;

    auto issueKV = [&](int j, int buf) {
        const uint32_t kb = sb + buf * FSTAGE;
        #pragma unroll
        for (int t = 0; t < 8; t++) {
            const int lin = t * 256 + tid;
            const int r = lin >> 4, s = lin & 15;
            cp16(kb + r * FSTRIDE + s * 16,
                 ksrc + (size_t)(j * 128 + r) * DH + s * 8);
            cp16(kb + FK_TILE + r * FSTRIDE + s * 16,
                 vsrc + (size_t)r * SEQ + j * 128 + s * 8);
        }
    };

    issueKV(0, 0);
    CP_COMMIT();

    float Oacc[17][4];
    #pragma unroll
    for (int i = 0; i < 17; i++)
        #pragma unroll
        for (int k = 0; k < 4; k++) Oacc[i][k] = 0.f;

    for (int j = 0; j < 16; j++) {
        const int buf = j & 1;
        __syncthreads();
        if (j + 1 < 16) issueKV(j + 1, buf ^ 1);
        CP_COMMIT();
        CP_WAITG1();
        __syncthreads();

        const uint32_t kb = sb + buf * FSTAGE;
        const uint32_t vb = kb + FK_TILE;

        float S[16][4];
        #pragma unroll
        for (int i = 0; i < 16; i++)
            #pragma unroll
            for (int k = 0; k < 4; k++) S[i][k] = 0.f;

        #pragma unroll
        for (int kt = 0; kt < 8; kt++) {
            uint32_t bK[8][4];
            #pragma unroll
            for (int nt = 0; nt < 8; nt++)
                ldm4(bK[nt], kb + (nt * 16 + lrow) * FSTRIDE + kt * 32 + lchk * 16);
            #pragma unroll
            for (int n8 = 0; n8 < 16; n8++) {
                const int g = n8 >> 1, p = n8 & 1;
                mma16816(S[n8], qF[kt], bK[g][p], bK[g][p + 2]);
            }
        }

        const float* bp  = bias + ((size_t)h * SEQ + r0 + gr) * SEQ + j * 128;
        const float* bp8 = bp + (size_t)8 * SEQ;
        uint32_t P2[16][2];
        #pragma unroll
        for (int n8 = 0; n8 < 16; n8++) {
            const int cc = n8 * 8 + 2 * tc;
            const float2 b01 = *(const float2*)(bp + cc);
            const float2 b23 = *(const float2*)(bp8 + cc);
            P2[n8][0] = exp2h2(fmaf(b01.x, LOG2E, S[n8][0]),
                               fmaf(b01.y, LOG2E, S[n8][1]));
            P2[n8][1] = exp2h2(fmaf(b23.x, LOG2E, S[n8][2]),
                               fmaf(b23.y, LOG2E, S[n8][3]));
        }

        #pragma unroll
        for (int kp = 0; kp < 8; kp++) {
            uint32_t aP[4];
            aP[0] = P2[2*kp    ][0];
            aP[1] = P2[2*kp    ][1];
            aP[2] = P2[2*kp + 1][0];
            aP[3] = P2[2*kp + 1][1];
            uint32_t bV[9][4];
            #pragma unroll
            for (int nt = 0; nt < 9; nt++)
                ldm4(bV[nt], vb + (nt * 16 + lrow) * FSTRIDE + kp * 32 + lchk * 16);
            #pragma unroll
            for (int n8 = 0; n8 < 17; n8++) {
                const int g = n8 >> 1, p = n8 & 1;
                mma16816(Oacc[n8], aP, bV[g][p], bV[g][p + 2]);
            }
        }
    }

    const float rs0 = __shfl_sync(0xffffffffu, Oacc[16][0], lane & 28);
    const float rs1 = __shfl_sync(0xffffffffu, Oacc[16][2], lane & 28);
    const float i0 = 1.f / rs0, i1 = 1.f / rs1;

    const size_t orow0 = (size_t)(b * SEQ + r0 + gr    ) * ldo + h * DH;
    const size_t orow1 = (size_t)(b * SEQ + r0 + gr + 8) * ldo + h * DH;
    #pragma unroll
    for (int n8 = 0; n8 < 16; n8++) {
        const int cc = n8 * 8 + 2 * tc;
        *(uint32_t*)(at + orow0 + cc) = pack2(Oacc[n8][0] * i0, Oacc[n8][1] * i0);
        *(uint32_t*)(at + orow1 + cc) = pack2(Oacc[n8][2] * i1, Oacc[n8][3] * i1);
    }
}

// ---------------- RMSNorm -> fp16 ----------------
__global__ __launch_bounds__(256) void rmsnorm_kernel(
    const float* __restrict__ x, const float* __restrict__ gamma,
    __half* __restrict__ xn)
{
    const size_t row = blockIdx.x;
    const float* xr = x + row * DIMC;
    const int t = threadIdx.x;

    float s = 0.f;
    for (int c = t; c < DIMC; c += 256) { float v = xr[c]; s += v * v; }
    __shared__ float red[8];
    #pragma unroll
    for (int o = 16; o; o >>= 1) s += __shfl_xor_sync(0xffffffffu, s, o);
    if ((t & 31) == 0) red[t >> 5] = s;
    __syncthreads();
    float tot = red[0]+red[1]+red[2]+red[3]+red[4]+red[5]+red[6]+red[7];
    float inv = rsqrtf(tot + 1e-5f) * RMS_SCALE;

    for (int c = t; c < DIMC; c += 256)
        xn[row * DIMC + c] = __float2half_rn(xr[c] * inv * gamma[c]);
}

// ---------------- merged weight-prep kernels ----------------
// wiT build (permuted). z=0: qkv cols 0..2303; z=1: ff; z=2: gate.
__global__ void prep_wiT_kernel(const float* __restrict__ wi, __half* __restrict__ wiT)
{
    int colBase, rowBase, rowMul;
    if (blockIdx.z == 0) {
        if (blockIdx.x >= 72) return;          // 2304/32
        colBase = 0; rowBase = 0; rowMul = 1;
    } else if (blockIdx.z == 1) {
        colBase = 2304; rowBase = 2304; rowMul = 2;
    } else {
        colBase = 10496; rowBase = 2305; rowMul = 2;
    }
    __shared__ float t[32][33];
    const int cx = colBase + blockIdx.x * 32 + threadIdx.x;
    const int ry = blockIdx.y * 32;
    #pragma unroll
    for (int j = 0; j < 32; j += 8)
        t[threadIdx.y + j][threadIdx.x] = wi[(size_t)(ry + threadIdx.y + j) * NPROJ + cx];
    __syncthreads();
    const int colRel0 = blockIdx.x * 32;
    const int dc = ry + threadIdx.x;
    #pragma unroll
    for (int j = 0; j < 32; j += 8) {
        const size_t drow = (size_t)rowBase + (size_t)rowMul * (colRel0 + threadIdx.y + j);
        wiT[drow * DIMC + dc] = __float2half_rn(t[threadIdx.x][threadIdx.y + j]);
    }
}

// wcat build: z=0: attn_wo [2048x2048] -> wcat[col][row]; z=1: ff_wo [8192x2048] -> wcat[col][2048+row]
__global__ void prep_wcat_kernel(const float* __restrict__ attn_wo,
                                 const float* __restrict__ ff_wo,
                                 __half* __restrict__ wcat)
{
    const float* src;
    int colOff;
    if (blockIdx.z == 0) {
        if (blockIdx.y >= 64) return;          // 2048/32 source rows
        src = attn_wo; colOff = 0;
    } else {
        src = ff_wo; colOff = 2048;
    }
    __shared__ float t[32][33];
    const int cx = blockIdx.x * 32 + threadIdx.x;  // src col (out dim), 0..2047
    const int ry = blockIdx.y * 32;                // src row (k dim)
    #pragma unroll
    for (int j = 0; j < 32; j += 8)
        t[threadIdx.y + j][threadIdx.x] = src[(size_t)(ry + threadIdx.y + j) * DIMC + cx];
    __syncthreads();
    const int dr0 = blockIdx.x * 32;
    const int dc  = ry + threadIdx.x;
    #pragma unroll
    for (int j = 0; j < 32; j += 8) {
        const size_t drow = (size_t)(dr0 + threadIdx.y + j);
        wcat[drow * NCAT + colOff + dc] = __float2half_rn(t[threadIdx.x][threadIdx.y + j]);
    }
}

// ---------------- launch ----------------
extern "C" void kernel_launch(void* const* d_in, const int* in_sizes, int n_in,
                              void* d_out, int out_size)
{
    const float *x = 0, *bias = 0, *gamma = 0, *wi = 0, *attn_wo = 0, *ff_wo = 0;
    for (int i = 0; i < n_in; i++) {
        switch (in_sizes[i]) {
            case  8388608: x       = (const float*)d_in[i]; break;
            case 67108864: bias    = (const float*)d_in[i]; break;
            case     2048: gamma   = (const float*)d_in[i]; break;
            case 38273024: wi      = (const float*)d_in[i]; break;
            case  4194304: attn_wo = (const float*)d_in[i]; break;
            case 16777216: ff_wo   = (const float*)d_in[i]; break;
        }
    }
    float* out = (float*)d_out;

    __half *xn, *wiT, *qt, *kt, *vt, *cat, *wcat;
    cudaGetSymbolAddress((void**)&xn,   g_xn);
    cudaGetSymbolAddress((void**)&wiT,  g_wiT);
    cudaGetSymbolAddress((void**)&qt,   g_qt);
    cudaGetSymbolAddress((void**)&kt,   g_kt);
    cudaGetSymbolAddress((void**)&vt,   g_vt);
    cudaGetSymbolAddress((void**)&cat,  g_cat);
    cudaGetSymbolAddress((void**)&wcat, g_wcat);

    cudaFuncSetAttribute(gemm_kernel,
                         cudaFuncAttributeMaxDynamicSharedMemorySize, SMEM_GEMM);
    cudaFuncSetAttribute(proj_kernel,
                         cudaFuncAttributeMaxDynamicSharedMemorySize, SMEM_GEMM);
    cudaFuncSetAttribute(flash_kernel,
                         cudaFuncAttributeMaxDynamicSharedMemorySize, SMEM_FLASH);

    // 1. RMSNorm -> xn
    rmsnorm_kernel<<<NROWS, 256>>>(x, gamma, xn);

    // 2. weight prep (2 launches)
    prep_wiT_kernel<<<dim3(256, DIMC/32, 3), dim3(32, 8)>>>(wi, wiT);
    prep_wcat_kernel<<<dim3(DIMC/32, FFI/32, 2), dim3(32, 8)>>>(attn_wo, ff_wo, wcat);

    // 3. proj GEMM with fused gather/swiglu epilogue
    proj_kernel<<<dim3(NROWS/128, NPROJ/128), 256, SMEM_GEMM>>>(
        xn, DIMC, wiT, DIMC, qt, kt, vt, cat, DIMC);

    // 4. fused attention -> cat cols 0..2047
    flash_kernel<<<dim3(SEQ/128, BATCH*HEADS), 256, SMEM_FLASH>>>(
        qt, kt, vt, bias, cat, NCAT);

    // 5. out = cat @ wcat^T (K = 10240)   <- launch #6: ncu -s 5 captures this
    gemm_kernel<<<dim3(NROWS/128, DIMC/128), 256, SMEM_GEMM>>>(
        cat, NCAT, wcat, NCAT, out, DIMC, NCAT);
}

// round 14
// speedup vs baseline: 7.9478x; 1.0153x over previous
#include <cuda_runtime.h>
#include <cuda_fp16.h>
#include <math.h>
#include <stdint.h>

// ---------------- problem constants ----------------
#define DIMC   2048
#define SEQ    2048
#define BATCH  2
#define HEADS  16
#define DH     128
#define FFI    8192
#define NPROJ  18688            // 2048+128+128+8192+8192
#define NROWS  4096             // BATCH*SEQ
#define NCAT   10240            // 2048 (attn) + 8192 (ff)
#define RMS_SCALE 45.25483399593904f   // sqrt(2048)
#define Q_SCALE   0.08838834764831845f // 1/sqrt(128)
#define LOG2E     1.4426950408889634f

// gemm smem: 3 stages * 2 tiles * (128 rows * 144B) = 110592   (K-chunk = 64)
#define TILE_B   18432
#define STAGE_B  36864
#define SMEM_GEMM 110592
// flash smem: 2 stages * (K 128x272 + V 144x272) = 147968
#define FSTRIDE  272
#define FK_TILE  34816
#define FSTAGE   73984
#define SMEM_FLASH 147968

// ---------------- scratch (device globals; allocation-free) ----------------
__device__ __half g_xn  [(size_t)NROWS * DIMC];
__device__ __half g_wiT [(size_t)NPROJ * DIMC];     // PERMUTED: q|k|v|ff/gate interleaved
__device__ __half g_qt  [(size_t)BATCH * HEADS * SEQ * DH];
__device__ __half g_kt  [(size_t)BATCH * SEQ * DH];
__device__ __half g_vt  [(size_t)BATCH * DH * SEQ];
__device__ __half g_cat [(size_t)NROWS * NCAT];     // [at | h]
__device__ __half g_wcat[(size_t)DIMC * NCAT];      // [awT | fwT]

// ---------------- helpers ----------------
__device__ __forceinline__ uint32_t smem_u32(const void* p) {
    uint32_t a;
    asm("{ .reg .u64 t; cvta.to.shared.u64 t, %1; cvt.u32.u64 %0, t; }"
        : "=r"(a) : "l"(p));
    return a;
}
__device__ __forceinline__ void ldm4(uint32_t* r, uint32_t a) {
    asm volatile("ldmatrix.sync.aligned.m8n8.x4.shared.b16 {%0,%1,%2,%3}, [%4];"
                 : "=r"(r[0]), "=r"(r[1]), "=r"(r[2]), "=r"(r[3]) : "r"(a));
}
__device__ __forceinline__ void mma16816(float* d, const uint32_t* a,
                                         uint32_t b0, uint32_t b1) {
    asm volatile(
        "mma.sync.aligned.m16n8k16.row.col.f32.f16.f16.f32 "
        "{%0,%1,%2,%3}, {%4,%5,%6,%7}, {%8,%9}, {%0,%1,%2,%3};"
        : "+f"(d[0]), "+f"(d[1]), "+f"(d[2]), "+f"(d[3])
        : "r"(a[0]), "r"(a[1]), "r"(a[2]), "r"(a[3]), "r"(b0), "r"(b1));
}
__device__ __forceinline__ void cp16(uint32_t s, const void* g) {
    asm volatile("cp.async.cg.shared.global [%0], [%1], 16;" :: "r"(s), "l"(g));
}
#define CP_COMMIT() asm volatile("cp.async.commit_group;")
#define CP_WAITG1() asm volatile("cp.async.wait_group 1;" ::: "memory")
__device__ __forceinline__ uint32_t pack2(float v0, float v1) {
    __half2 H = __floats2half2_rn(v0, v1);
    return *(uint32_t*)&H;
}
__device__ __forceinline__ uint32_t exp2h2(float v0, float v1) {
    uint32_t p = pack2(v0, v1), r;
    asm("ex2.approx.f16x2 %0, %1;" : "=r"(r) : "r"(p));
    return r;
}

// ====== GEMM mainloop: K-chunk 64, 3-stage cp.async, ONE sync per chunk ======
// per chunk per thread: 4 cp16 per tile (A, B). lin = q*256+tid; r=lin>>3; s=lin&7.
#define GEMM_ISSUE(cidx, Aptr, lda_, Bptr, ldb_)                                        \
    {                                                                                   \
        const int k0i = (cidx) << 6;                                                    \
        const uint32_t db = sb + ((cidx) % 3) * STAGE_B;                                \
        _Pragma("unroll")                                                               \
        for (int qq = 0; qq < 4; qq++) {                                                \
            const int lin = qq * 256 + tid;                                             \
            const int rr = lin >> 3, ss = lin & 7;                                      \
            cp16(db + rr*144 + ss*16,                                                   \
                 (Aptr) + (size_t)(row0 + rr) * (lda_) + k0i + ss*8);                   \
            cp16(db + TILE_B + rr*144 + ss*16,                                          \
                 (Bptr) + (size_t)(col0 + rr) * (ldb_) + k0i + ss*8);                   \
        }                                                                               \
    }

#define GEMM_MAIN(Aptr, lda_, Bptr, ldb_, Kdim)                                         \
    float acc[2][8][4];                                                                 \
    _Pragma("unroll")                                                                   \
    for (int i = 0; i < 2; i++)                                                         \
        _Pragma("unroll")                                                               \
        for (int j = 0; j < 8; j++)                                                     \
            _Pragma("unroll")                                                           \
            for (int k = 0; k < 4; k++) acc[i][j][k] = 0.f;                             \
    const int NC = (Kdim) >> 6;                                                         \
    const int lrow = lane & 15;                                                         \
    const int lchk = lane >> 4;                                                         \
    GEMM_ISSUE(0, Aptr, lda_, Bptr, ldb_); CP_COMMIT();                                 \
    GEMM_ISSUE(1, Aptr, lda_, Bptr, ldb_); CP_COMMIT();                                 \
    for (int c = 0; c < NC; c++) {                                                      \
        CP_WAITG1();                       /* chunk c resident */                       \
        __syncthreads();                   /* prev compute drained */                   \
        if (c + 2 < NC) GEMM_ISSUE(c + 2, Aptr, lda_, Bptr, ldb_);                      \
        CP_COMMIT();                                                                    \
        const uint32_t tb = sb + (c % 3) * STAGE_B;                                     \
        _Pragma("unroll")                                                               \
        for (int kk = 0; kk < 4; kk++) {                                                \
            const int ch0 = kk * 2;                                                     \
            uint32_t aF[2][4], bF[4][4];                                                \
            _Pragma("unroll")                                                           \
            for (int mt = 0; mt < 2; mt++)                                              \
                ldm4(aF[mt], tb + (mw*32 + mt*16 + lrow)*144 + (ch0 + lchk)*16);        \
            _Pragma("unroll")                                                           \
            for (int nt = 0; nt < 4; nt++)                                              \
                ldm4(bF[nt], tb + TILE_B + (nw*64 + nt*16 + lrow)*144 + (ch0 + lchk)*16);\
            _Pragma("unroll")                                                           \
            for (int mt = 0; mt < 2; mt++) {                                            \
                _Pragma("unroll")                                                       \
                for (int n8 = 0; n8 < 8; n8++) {                                        \
                    const int g = n8 >> 1, p = n8 & 1;                                  \
                    mma16816(acc[mt][n8], aF[mt], bF[g][p], bF[g][p + 2]);              \
                }                                                                       \
            }                                                                           \
        }                                                                               \
    }

// ---------------- plain GEMM (final output) ----------------
__global__ __launch_bounds__(256, 2) void gemm_kernel(
    const __half* __restrict__ A, int lda,
    const __half* __restrict__ B, int ldb,
    float* __restrict__ C, int ldc, int K)
{
    extern __shared__ char smem[];
    const uint32_t sb = smem_u32(smem);
    const int tid  = threadIdx.x;
    const int wid  = tid >> 5;
    const int lane = tid & 31;
    const int mw   = wid & 3;
    const int nw   = wid >> 2;
    const int row0 = blockIdx.x * 128, col0 = blockIdx.y * 128;

    GEMM_MAIN(A, lda, B, ldb, K)

    const int tr  = lane >> 2;
    const int tc2 = (lane & 3) * 2;
    #pragma unroll
    for (int mt = 0; mt < 2; mt++)
        #pragma unroll
        for (int hf = 0; hf < 2; hf++) {
            const int r = row0 + mw*32 + mt*16 + hf*8 + tr;
            #pragma unroll
            for (int n8 = 0; n8 < 8; n8++) {
                const int cc = col0 + nw*64 + n8*8 + tc2;
                float* cp = C + (size_t)r * ldc + cc;
                cp[0] = acc[mt][n8][hf*2 + 0];
                cp[1] = acc[mt][n8][hf*2 + 1];
            }
        }
}

// ---------------- proj GEMM with fused gather epilogue ----------------
// B = permuted wiT: rows 0..2047 q, 2048..2175 k, 2176..2303 v,
//                   2304..18687 interleaved (even=ff_j, odd=gate_j).
__global__ __launch_bounds__(256, 2) void proj_kernel(
    const __half* __restrict__ A, int lda,
    const __half* __restrict__ B, int ldb,
    __half* __restrict__ q, __half* __restrict__ kmat,
    __half* __restrict__ vmat, __half* __restrict__ cat, int K)
{
    extern __shared__ char smem[];
    const uint32_t sb = smem_u32(smem);
    const int tid  = threadIdx.x;
    const int wid  = tid >> 5;
    const int lane = tid & 31;
    const int mw   = wid & 3;
    const int nw   = wid >> 2;
    const int row0 = blockIdx.x * 128, col0 = blockIdx.y * 128;

    GEMM_MAIN(A, lda, B, ldb, K)

    const int tr  = lane >> 2;
    const int tc2 = (lane & 3) * 2;

    #pragma unroll
    for (int mt = 0; mt < 2; mt++)
        #pragma unroll
        for (int hf = 0; hf < 2; hf++) {
            const int r = row0 + mw*32 + mt*16 + hf*8 + tr;
            const int i = r & 2047, b = r >> 11;
            #pragma unroll
            for (int n8 = 0; n8 < 8; n8++) {
                const int cc = col0 + nw*64 + n8*8 + tc2;
                const float v0 = acc[mt][n8][hf*2 + 0];
                const float v1 = acc[mt][n8][hf*2 + 1];
                if (col0 < 2048) {
                    // q[z][i][d], pre-scaled by Q_SCALE*LOG2E
                    const int h = cc >> 7, d = cc & 127;
                    const size_t o = ((size_t)(b * HEADS + h) * SEQ + i) * DH + d;
                    *(uint32_t*)(q + o) = pack2(v0 * (Q_SCALE * LOG2E),
                                                v1 * (Q_SCALE * LOG2E));
                } else if (col0 == 2048) {
                    // k[b][j][d]
                    const int d = cc - 2048;
                    *(uint32_t*)(kmat + (size_t)r * DH + d) = pack2(v0, v1);
                } else if (col0 == 2176) {
                    // v[b][d][j]: scattered transpose (small region)
                    const int d = cc - 2176;
                    const size_t o = (size_t)b * DH * SEQ + (size_t)d * SEQ + i;
                    vmat[o]       = __float2half_rn(v0);
                    vmat[o + SEQ] = __float2half_rn(v1);
                } else {
                    // interleaved ff/gate: v0 = ff_j, v1 = gate_j
                    const int jp = (cc - 2304) >> 1;
                    const float sw = v1 / (1.f + __expf(-v1));
                    cat[(size_t)r * NCAT + 2048 + jp] = __float2half_rn(v0 * sw);
                }
            }
        }
}

// ---------------- fused flash attention ----------------
__global__ __launch_bounds__(256) void flash_kernel(
    const __half* __restrict__ q,      // [z][i][dh]  (pre-scaled by Q_SCALE*log2e)
    const __half* __restrict__ kmat,   // [b][key][dh]
    const __half* __restrict__ vmat,   // [b][dh][key]
    const float* __restrict__ bias,    // [h][i][j]
    __half* __restrict__ at, int ldo)
{
    extern __shared__ char smem[];
    const uint32_t sb = smem_u32(smem);
    const int tid  = threadIdx.x;
    const int wid  = tid >> 5;
    const int lane = tid & 31;
    const int gr   = lane >> 2;
    const int tc   = lane & 3;
    const int lrow = lane & 15;
    const int lchk = lane >> 4;

    const int z = blockIdx.y, b = z >> 4, h = z & 15;
    const int r0 = blockIdx.x * 128 + wid * 16;

    // init ones-row (dh=128) and zero rows of both V buffers
    #pragma unroll
    for (int bufi = 0; bufi < 2; bufi++) {
        char* vrows = smem + bufi * FSTAGE + FK_TILE + 128 * FSTRIDE;
        for (int i = tid; i < 16 * 136; i += 256) {
            const int r = i / 136, cc = i % 136;
            *(__half*)(vrows + r * FSTRIDE + cc * 2) =
                (r == 0) ? __float2half(1.0f) : __float2half(0.0f);
        }
    }

    uint32_t qF[8][4];
    {
        const __half* qb = q + (size_t)z * SEQ * DH;
        #pragma unroll
        for (int kt = 0; kt < 8; kt++) {
            const int c0 = kt * 16 + 2 * tc;
            qF[kt][0] = *(const uint32_t*)(qb + (size_t)(r0 + gr    ) * DH + c0);
            qF[kt][1] = *(const uint32_t*)(qb + (size_t)(r0 + gr + 8) * DH + c0);
            qF[kt][2] = *(const uint32_t*)(qb + (size_t)(r0 + gr    ) * DH + c0 + 8);
            qF[kt][3] = *(const uint32_t*)(qb + (size_t)(r0 + gr + 8) * DH + c0 + 8);
        }
    }

    const __half* ksrc = kmat + (size_t)b * SEQ * DH;
    const __half* vsrc = vmat + (size_t)b * DH * SEQ;

    auto issueKV = [&](int j, int buf) {
        const uint32_t kb = sb + buf * FSTAGE;
        #pragma unroll
        for (int t = 0; t < 8; t++) {
            const int lin = t * 256 + tid;
            const int r = lin >> 4, s = lin & 15;
            cp16(kb + r * FSTRIDE + s * 16,
                 ksrc + (size_t)(j * 128 + r) * DH + s * 8);
            cp16(kb + FK_TILE + r * FSTRIDE + s * 16,
                 vsrc + (size_t)r * SEQ + j * 128 + s * 8);
        }
    };

    issueKV(0, 0);
    CP_COMMIT();

    float Oacc[17][4];
    #pragma unroll
    for (int i = 0; i < 17; i++)
        #pragma unroll
        for (int k = 0; k < 4; k++) Oacc[i][k] = 0.f;

    for (int j = 0; j < 16; j++) {
        const int buf = j & 1;
        __syncthreads();
        if (j + 1 < 16) issueKV(j + 1, buf ^ 1);
        CP_COMMIT();
        CP_WAITG1();
        __syncthreads();

        const uint32_t kb = sb + buf * FSTAGE;
        const uint32_t vb = kb + FK_TILE;

        float S[16][4];
        #pragma unroll
        for (int i = 0; i < 16; i++)
            #pragma unroll
            for (int k = 0; k < 4; k++) S[i][k] = 0.f;

        #pragma unroll
        for (int kt = 0; kt < 8; kt++) {
            uint32_t bK[8][4];
            #pragma unroll
            for (int nt = 0; nt < 8; nt++)
                ldm4(bK[nt], kb + (nt * 16 + lrow) * FSTRIDE + kt * 32 + lchk * 16);
            #pragma unroll
            for (int n8 = 0; n8 < 16; n8++) {
                const int g = n8 >> 1, p = n8 & 1;
                mma16816(S[n8], qF[kt], bK[g][p], bK[g][p + 2]);
            }
        }

        const float* bp  = bias + ((size_t)h * SEQ + r0 + gr) * SEQ + j * 128;
        const float* bp8 = bp + (size_t)8 * SEQ;
        uint32_t P2[16][2];
        #pragma unroll
        for (int n8 = 0; n8 < 16; n8++) {
            const int cc = n8 * 8 + 2 * tc;
            const float2 b01 = *(const float2*)(bp + cc);
            const float2 b23 = *(const float2*)(bp8 + cc);
            P2[n8][0] = exp2h2(fmaf(b01.x, LOG2E, S[n8][0]),
                               fmaf(b01.y, LOG2E, S[n8][1]));
            P2[n8][1] = exp2h2(fmaf(b23.x, LOG2E, S[n8][2]),
                               fmaf(b23.y, LOG2E, S[n8][3]));
        }

        #pragma unroll
        for (int kp = 0; kp < 8; kp++) {
            uint32_t aP[4];
            aP[0] = P2[2*kp    ][0];
            aP[1] = P2[2*kp    ][1];
            aP[2] = P2[2*kp + 1][0];
            aP[3] = P2[2*kp + 1][1];
            uint32_t bV[9][4];
            #pragma unroll
            for (int nt = 0; nt < 9; nt++)
                ldm4(bV[nt], vb + (nt * 16 + lrow) * FSTRIDE + kp * 32 + lchk * 16);
            #pragma unroll
            for (int n8 = 0; n8 < 17; n8++) {
                const int g = n8 >> 1, p = n8 & 1;
                mma16816(Oacc[n8], aP, bV[g][p], bV[g][p + 2]);
            }
        }
    }

    const float rs0 = __shfl_sync(0xffffffffu, Oacc[16][0], lane & 28);
    const float rs1 = __shfl_sync(0xffffffffu, Oacc[16][2], lane & 28);
    const float i0 = 1.f / rs0, i1 = 1.f / rs1;

    const size_t orow0 = (size_t)(b * SEQ + r0 + gr    ) * ldo + h * DH;
    const size_t orow1 = (size_t)(b * SEQ + r0 + gr + 8) * ldo + h * DH;
    #pragma unroll
    for (int n8 = 0; n8 < 16; n8++) {
        const int cc = n8 * 8 + 2 * tc;
        *(uint32_t*)(at + orow0 + cc) = pack2(Oacc[n8][0] * i0, Oacc[n8][1] * i0);
        *(uint32_t*)(at + orow1 + cc) = pack2(Oacc[n8][2] * i1, Oacc[n8][3] * i1);
    }
}

// ---------------- RMSNorm -> fp16 ----------------
__global__ __launch_bounds__(256) void rmsnorm_kernel(
    const float* __restrict__ x, const float* __restrict__ gamma,
    __half* __restrict__ xn)
{
    const size_t row = blockIdx.x;
    const float* xr = x + row * DIMC;
    const int t = threadIdx.x;

    float s = 0.f;
    for (int c = t; c < DIMC; c += 256) { float v = xr[c]; s += v * v; }
    __shared__ float red[8];
    #pragma unroll
    for (int o = 16; o; o >>= 1) s += __shfl_xor_sync(0xffffffffu, s, o);
    if ((t & 31) == 0) red[t >> 5] = s;
    __syncthreads();
    float tot = red[0]+red[1]+red[2]+red[3]+red[4]+red[5]+red[6]+red[7];
    float inv = rsqrtf(tot + 1e-5f) * RMS_SCALE;

    for (int c = t; c < DIMC; c += 256)
        xn[row * DIMC + c] = __float2half_rn(xr[c] * inv * gamma[c]);
}

// ---------------- merged weight-prep kernels ----------------
// wiT build (permuted). z=0: qkv cols 0..2303; z=1: ff; z=2: gate.
__global__ void prep_wiT_kernel(const float* __restrict__ wi, __half* __restrict__ wiT)
{
    int colBase, rowBase, rowMul;
    if (blockIdx.z == 0) {
        if (blockIdx.x >= 72) return;          // 2304/32
        colBase = 0; rowBase = 0; rowMul = 1;
    } else if (blockIdx.z == 1) {
        colBase = 2304; rowBase = 2304; rowMul = 2;
    } else {
        colBase = 10496; rowBase = 2305; rowMul = 2;
    }
    __shared__ float t[32][33];
    const int cx = colBase + blockIdx.x * 32 + threadIdx.x;
    const int ry = blockIdx.y * 32;
    #pragma unroll
    for (int j = 0; j < 32; j += 8)
        t[threadIdx.y + j][threadIdx.x] = wi[(size_t)(ry + threadIdx.y + j) * NPROJ + cx];
    __syncthreads();
    const int colRel0 = blockIdx.x * 32;
    const int dc = ry + threadIdx.x;
    #pragma unroll
    for (int j = 0; j < 32; j += 8) {
        const size_t drow = (size_t)rowBase + (size_t)rowMul * (colRel0 + threadIdx.y + j);
        wiT[drow * DIMC + dc] = __float2half_rn(t[threadIdx.x][threadIdx.y + j]);
    }
}

// wcat build: z=0: attn_wo -> wcat[col][row]; z=1: ff_wo -> wcat[col][2048+row]
__global__ void prep_wcat_kernel(const float* __restrict__ attn_wo,
                                 const float* __restrict__ ff_wo,
                                 __half* __restrict__ wcat)
{
    const float* src;
    int colOff;
    if (blockIdx.z == 0) {
        if (blockIdx.y >= 64) return;          // 2048/32 source rows
        src = attn_wo; colOff = 0;
    } else {
        src = ff_wo; colOff = 2048;
    }
    __shared__ float t[32][33];
    const int cx = blockIdx.x * 32 + threadIdx.x;  // src col (out dim), 0..2047
    const int ry = blockIdx.y * 32;                // src row (k dim)
    #pragma unroll
    for (int j = 0; j < 32; j += 8)
        t[threadIdx.y + j][threadIdx.x] = src[(size_t)(ry + threadIdx.y + j) * DIMC + cx];
    __syncthreads();
    const int dr0 = blockIdx.x * 32;
    const int dc  = ry + threadIdx.x;
    #pragma unroll
    for (int j = 0; j < 32; j += 8) {
        const size_t drow = (size_t)(dr0 + threadIdx.y + j);
        wcat[drow * NCAT + colOff + dc] = __float2half_rn(t[threadIdx.x][threadIdx.y + j]);
    }
}

// ---------------- launch ----------------
extern "C" void kernel_launch(void* const* d_in, const int* in_sizes, int n_in,
                              void* d_out, int out_size)
{
    const float *x = 0, *bias = 0, *gamma = 0, *wi = 0, *attn_wo = 0, *ff_wo = 0;
    for (int i = 0; i < n_in; i++) {
        switch (in_sizes[i]) {
            case  8388608: x       = (const float*)d_in[i]; break;
            case 67108864: bias    = (const float*)d_in[i]; break;
            case     2048: gamma   = (const float*)d_in[i]; break;
            case 38273024: wi      = (const float*)d_in[i]; break;
            case  4194304: attn_wo = (const float*)d_in[i]; break;
            case 16777216: ff_wo   = (const float*)d_in[i]; break;
        }
    }
    float* out = (float*)d_out;

    __half *xn, *wiT, *qt, *kt, *vt, *cat, *wcat;
    cudaGetSymbolAddress((void**)&xn,   g_xn);
    cudaGetSymbolAddress((void**)&wiT,  g_wiT);
    cudaGetSymbolAddress((void**)&qt,   g_qt);
    cudaGetSymbolAddress((void**)&kt,   g_kt);
    cudaGetSymbolAddress((void**)&vt,   g_vt);
    cudaGetSymbolAddress((void**)&cat,  g_cat);
    cudaGetSymbolAddress((void**)&wcat, g_wcat);

    cudaFuncSetAttribute(gemm_kernel,
                         cudaFuncAttributeMaxDynamicSharedMemorySize, SMEM_GEMM);
    cudaFuncSetAttribute(proj_kernel,
                         cudaFuncAttributeMaxDynamicSharedMemorySize, SMEM_GEMM);
    cudaFuncSetAttribute(flash_kernel,
                         cudaFuncAttributeMaxDynamicSharedMemorySize, SMEM_FLASH);

    // 1. RMSNorm -> xn
    rmsnorm_kernel<<<NROWS, 256>>>(x, gamma, xn);

    // 2. weight prep (2 launches)
    prep_wiT_kernel<<<dim3(256, DIMC/32, 3), dim3(32, 8)>>>(wi, wiT);
    prep_wcat_kernel<<<dim3(DIMC/32, FFI/32, 2), dim3(32, 8)>>>(attn_wo, ff_wo, wcat);

    // 3. proj GEMM with fused gather/swiglu epilogue
    proj_kernel<<<dim3(NROWS/128, NPROJ/128), 256, SMEM_GEMM>>>(
        xn, DIMC, wiT, DIMC, qt, kt, vt, cat, DIMC);

    // 4. fused attention -> cat cols 0..2047
    flash_kernel<<<dim3(SEQ/128, BATCH*HEADS), 256, SMEM_FLASH>>>(
        qt, kt, vt, bias, cat, NCAT);

    // 5. out = cat @ wcat^T (K = 10240)
    gemm_kernel<<<dim3(NROWS/128, DIMC/128), 256, SMEM_GEMM>>>(
        cat, NCAT, wcat, NCAT, out, DIMC, NCAT);
}

// round 15
// speedup vs baseline: 7.9733x; 1.0032x over previous
#include <cuda_runtime.h>
#include <cuda_fp16.h>
#include <math.h>
#include <stdint.h>

// ---------------- problem constants ----------------
#define DIMC   2048
#define SEQ    2048
#define BATCH  2
#define HEADS  16
#define DH     128
#define FFI    8192
#define NPROJ  18688            // 2048+128+128+8192+8192
#define NROWS  4096             // BATCH*SEQ
#define NCAT   10240            // 2048 (attn) + 8192 (ff)
#define RMS_SCALE 45.25483399593904f   // sqrt(2048)
#define Q_SCALE   0.08838834764831845f // 1/sqrt(128)
#define LOG2E     1.4426950408889634f

// gemm smem: 3 stages * 2 tiles * (128 rows * 144B) = 110592   (K-chunk = 64)
#define TILE_B   18432
#define STAGE_B  36864
#define SMEM_GEMM 110592
// flash smem: 2 stages * (K 128x272 + V 144x272) = 147968
#define FSTRIDE  272
#define FK_TILE  34816
#define FSTAGE   73984
#define SMEM_FLASH 147968

// ---------------- scratch (device globals; allocation-free) ----------------
__device__ __half g_xn  [(size_t)NROWS * DIMC];
__device__ __half g_wiT [(size_t)NPROJ * DIMC];     // PERMUTED: q|k|v|ff/gate interleaved
__device__ __half g_qt  [(size_t)BATCH * HEADS * SEQ * DH];
__device__ __half g_kt  [(size_t)BATCH * SEQ * DH];
__device__ __half g_vt  [(size_t)BATCH * DH * SEQ];
__device__ __half g_cat [(size_t)NROWS * NCAT];     // [at | h]
__device__ __half g_wcat[(size_t)DIMC * NCAT];      // [awT | fwT]

// ---------------- helpers ----------------
__device__ __forceinline__ uint32_t smem_u32(const void* p) {
    uint32_t a;
    asm("{ .reg .u64 t; cvta.to.shared.u64 t, %1; cvt.u32.u64 %0, t; }"
        : "=r"(a) : "l"(p));
    return a;
}
__device__ __forceinline__ void ldm4(uint32_t* r, uint32_t a) {
    asm volatile("ldmatrix.sync.aligned.m8n8.x4.shared.b16 {%0,%1,%2,%3}, [%4];"
                 : "=r"(r[0]), "=r"(r[1]), "=r"(r[2]), "=r"(r[3]) : "r"(a));
}
__device__ __forceinline__ void mma16816(float* d, const uint32_t* a,
                                         uint32_t b0, uint32_t b1) {
    asm volatile(
        "mma.sync.aligned.m16n8k16.row.col.f32.f16.f16.f32 "
        "{%0,%1,%2,%3}, {%4,%5,%6,%7}, {%8,%9}, {%0,%1,%2,%3};"
        : "+f"(d[0]), "+f"(d[1]), "+f"(d[2]), "+f"(d[3])
        : "r"(a[0]), "r"(a[1]), "r"(a[2]), "r"(a[3]), "r"(b0), "r"(b1));
}
__device__ __forceinline__ void cp16(uint32_t s, const void* g) {
    asm volatile("cp.async.cg.shared.global [%0], [%1], 16;" :: "r"(s), "l"(g));
}
#define CP_COMMIT() asm volatile("cp.async.commit_group;")
#define CP_WAITG1() asm volatile("cp.async.wait_group 1;" ::: "memory")
__device__ __forceinline__ uint32_t pack2(float v0, float v1) {
    __half2 H = __floats2half2_rn(v0, v1);
    return *(uint32_t*)&H;
}
__device__ __forceinline__ uint32_t exp2h2(float v0, float v1) {
    uint32_t p = pack2(v0, v1), r;
    asm("ex2.approx.f16x2 %0, %1;" : "=r"(r) : "r"(p));
    return r;
}

// ====== GEMM mainloop: K-chunk 64, 3-stage cp.async, ONE sync per chunk ======
#define GEMM_ISSUE(cidx, Aptr, lda_, Bptr, ldb_)                                        \
    {                                                                                   \
        const int k0i = (cidx) << 6;                                                    \
        const uint32_t db = sb + ((cidx) % 3) * STAGE_B;                                \
        _Pragma("unroll")                                                               \
        for (int qq = 0; qq < 4; qq++) {                                                \
            const int lin = qq * 256 + tid;                                             \
            const int rr = lin >> 3, ss = lin & 7;                                      \
            cp16(db + rr*144 + ss*16,                                                   \
                 (Aptr) + (size_t)(row0 + rr) * (lda_) + k0i + ss*8);                   \
            cp16(db + TILE_B + rr*144 + ss*16,                                          \
                 (Bptr) + (size_t)(col0 + rr) * (ldb_) + k0i + ss*8);                   \
        }                                                                               \
    }

#define GEMM_MAIN(Aptr, lda_, Bptr, ldb_, Kdim)                                         \
    float acc[2][8][4];                                                                 \
    _Pragma("unroll")                                                                   \
    for (int i = 0; i < 2; i++)                                                         \
        _Pragma("unroll")                                                               \
        for (int j = 0; j < 8; j++)                                                     \
            _Pragma("unroll")                                                           \
            for (int k = 0; k < 4; k++) acc[i][j][k] = 0.f;                             \
    const int NC = (Kdim) >> 6;                                                         \
    const int lrow = lane & 15;                                                         \
    const int lchk = lane >> 4;                                                         \
    GEMM_ISSUE(0, Aptr, lda_, Bptr, ldb_); CP_COMMIT();                                 \
    GEMM_ISSUE(1, Aptr, lda_, Bptr, ldb_); CP_COMMIT();                                 \
    for (int c = 0; c < NC; c++) {                                                      \
        CP_WAITG1();                       /* chunk c resident */                       \
        __syncthreads();                   /* prev compute drained */                   \
        if (c + 2 < NC) GEMM_ISSUE(c + 2, Aptr, lda_, Bptr, ldb_);                      \
        CP_COMMIT();                                                                    \
        const uint32_t tb = sb + (c % 3) * STAGE_B;                                     \
        _Pragma("unroll")                                                               \
        for (int kk = 0; kk < 4; kk++) {                                                \
            const int ch0 = kk * 2;                                                     \
            uint32_t aF[2][4], bF[4][4];                                                \
            _Pragma("unroll")                                                           \
            for (int mt = 0; mt < 2; mt++)                                              \
                ldm4(aF[mt], tb + (mw*32 + mt*16 + lrow)*144 + (ch0 + lchk)*16);        \
            _Pragma("unroll")                                                           \
            for (int nt = 0; nt < 4; nt++)                                              \
                ldm4(bF[nt], tb + TILE_B + (nw*64 + nt*16 + lrow)*144 + (ch0 + lchk)*16);\
            _Pragma("unroll")                                                           \
            for (int mt = 0; mt < 2; mt++) {                                            \
                _Pragma("unroll")                                                       \
                for (int n8 = 0; n8 < 8; n8++) {                                        \
                    const int g = n8 >> 1, p = n8 & 1;                                  \
                    mma16816(acc[mt][n8], aF[mt], bF[g][p], bF[g][p + 2]);              \
                }                                                                       \
            }                                                                           \
        }                                                                               \
    }

// ---------------- plain GEMM (final output) ----------------
__global__ __launch_bounds__(256, 2) void gemm_kernel(
    const __half* __restrict__ A, int lda,
    const __half* __restrict__ B, int ldb,
    float* __restrict__ C, int ldc, int K)
{
    extern __shared__ char smem[];
    const uint32_t sb = smem_u32(smem);
    const int tid  = threadIdx.x;
    const int wid  = tid >> 5;
    const int lane = tid & 31;
    const int mw   = wid & 3;
    const int nw   = wid >> 2;
    const int row0 = blockIdx.x * 128, col0 = blockIdx.y * 128;

    GEMM_MAIN(A, lda, B, ldb, K)

    const int tr  = lane >> 2;
    const int tc2 = (lane & 3) * 2;
    #pragma unroll
    for (int mt = 0; mt < 2; mt++)
        #pragma unroll
        for (int hf = 0; hf < 2; hf++) {
            const int r = row0 + mw*32 + mt*16 + hf*8 + tr;
            #pragma unroll
            for (int n8 = 0; n8 < 8; n8++) {
                const int cc = col0 + nw*64 + n8*8 + tc2;
                float* cp = C + (size_t)r * ldc + cc;
                cp[0] = acc[mt][n8][hf*2 + 0];
                cp[1] = acc[mt][n8][hf*2 + 1];
            }
        }
}

// ---------------- proj GEMM with fused gather epilogue ----------------
// B = permuted wiT: rows 0..2047 q, 2048..2175 k, 2176..2303 v,
//                   2304..18687 interleaved (even=ff_j, odd=gate_j).
__global__ __launch_bounds__(256, 2) void proj_kernel(
    const __half* __restrict__ A, int lda,
    const __half* __restrict__ B, int ldb,
    __half* __restrict__ q, __half* __restrict__ kmat,
    __half* __restrict__ vmat, __half* __restrict__ cat, int K)
{
    extern __shared__ char smem[];
    const uint32_t sb = smem_u32(smem);
    const int tid  = threadIdx.x;
    const int wid  = tid >> 5;
    const int lane = tid & 31;
    const int mw   = wid & 3;
    const int nw   = wid >> 2;
    const int row0 = blockIdx.x * 128, col0 = blockIdx.y * 128;

    GEMM_MAIN(A, lda, B, ldb, K)

    const int tr  = lane >> 2;
    const int tc2 = (lane & 3) * 2;

    #pragma unroll
    for (int mt = 0; mt < 2; mt++)
        #pragma unroll
        for (int hf = 0; hf < 2; hf++) {
            const int r = row0 + mw*32 + mt*16 + hf*8 + tr;
            const int i = r & 2047, b = r >> 11;
            #pragma unroll
            for (int n8 = 0; n8 < 8; n8++) {
                const int cc = col0 + nw*64 + n8*8 + tc2;
                const float v0 = acc[mt][n8][hf*2 + 0];
                const float v1 = acc[mt][n8][hf*2 + 1];
                if (col0 < 2048) {
                    // q[z][i][d], pre-scaled by Q_SCALE*LOG2E
                    const int h = cc >> 7, d = cc & 127;
                    const size_t o = ((size_t)(b * HEADS + h) * SEQ + i) * DH + d;
                    *(uint32_t*)(q + o) = pack2(v0 * (Q_SCALE * LOG2E),
                                                v1 * (Q_SCALE * LOG2E));
                } else if (col0 == 2048) {
                    // k[b][j][d]
                    const int d = cc - 2048;
                    *(uint32_t*)(kmat + (size_t)r * DH + d) = pack2(v0, v1);
                } else if (col0 == 2176) {
                    // v[b][d][j]: scattered transpose (small region)
                    const int d = cc - 2176;
                    const size_t o = (size_t)b * DH * SEQ + (size_t)d * SEQ + i;
                    vmat[o]       = __float2half_rn(v0);
                    vmat[o + SEQ] = __float2half_rn(v1);
                } else {
                    // interleaved ff/gate: v0 = ff_j, v1 = gate_j
                    const int jp = (cc - 2304) >> 1;
                    const float sw = v1 / (1.f + __expf(-v1));
                    cat[(size_t)r * NCAT + 2048 + jp] = __float2half_rn(v0 * sw);
                }
            }
        }
}

// ---------------- fused flash attention ----------------
__global__ __launch_bounds__(256) void flash_kernel(
    const __half* __restrict__ q,      // [z][i][dh]  (pre-scaled by Q_SCALE*log2e)
    const __half* __restrict__ kmat,   // [b][key][dh]
    const __half* __restrict__ vmat,   // [b][dh][key]
    const float* __restrict__ bias,    // [h][i][j]
    __half* __restrict__ at, int ldo)
{
    extern __shared__ char smem[];
    const uint32_t sb = smem_u32(smem);
    const int tid  = threadIdx.x;
    const int wid  = tid >> 5;
    const int lane = tid & 31;
    const int gr   = lane >> 2;
    const int tc   = lane & 3;
    const int lrow = lane & 15;
    const int lchk = lane >> 4;

    const int z = blockIdx.y, b = z >> 4, h = z & 15;
    const int r0 = blockIdx.x * 128 + wid * 16;

    // init ones-row (dh=128) and zero rows of both V buffers
    #pragma unroll
    for (int bufi = 0; bufi < 2; bufi++) {
        char* vrows = smem + bufi * FSTAGE + FK_TILE + 128 * FSTRIDE;
        for (int i = tid; i < 16 * 136; i += 256) {
            const int r = i / 136, cc = i % 136;
            *(__half*)(vrows + r * FSTRIDE + cc * 2) =
                (r == 0) ? __float2half(1.0f) : __float2half(0.0f);
        }
    }

    uint32_t qF[8][4];
    {
        const __half* qb = q + (size_t)z * SEQ * DH;
        #pragma unroll
        for (int kt = 0; kt < 8; kt++) {
            const int c0 = kt * 16 + 2 * tc;
            qF[kt][0] = *(const uint32_t*)(qb + (size_t)(r0 + gr    ) * DH + c0);
            qF[kt][1] = *(const uint32_t*)(qb + (size_t)(r0 + gr + 8) * DH + c0);
            qF[kt][2] = *(const uint32_t*)(qb + (size_t)(r0 + gr    ) * DH + c0 + 8);
            qF[kt][3] = *(const uint32_t*)(qb + (size_t)(r0 + gr + 8) * DH + c0 + 8);
        }
    }

    const __half* ksrc = kmat + (size_t)b * SEQ * DH;
    const __half* vsrc = vmat + (size_t)b * DH * SEQ;

    auto issueKV = [&](int j, int buf) {
        const uint32_t kb = sb + buf * FSTAGE;
        #pragma unroll
        for (int t = 0; t < 8; t++) {
            const int lin = t * 256 + tid;
            const int r = lin >> 4, s = lin & 15;
            cp16(kb + r * FSTRIDE + s * 16,
                 ksrc + (size_t)(j * 128 + r) * DH + s * 8);
            cp16(kb + FK_TILE + r * FSTRIDE + s * 16,
                 vsrc + (size_t)r * SEQ + j * 128 + s * 8);
        }
    };

    issueKV(0, 0);
    CP_COMMIT();

    float Oacc[17][4];
    #pragma unroll
    for (int i = 0; i < 17; i++)
        #pragma unroll
        for (int k = 0; k < 4; k++) Oacc[i][k] = 0.f;

    for (int j = 0; j < 16; j++) {
        const int buf = j & 1;
        __syncthreads();
        if (j + 1 < 16) issueKV(j + 1, buf ^ 1);
        CP_COMMIT();
        CP_WAITG1();
        __syncthreads();

        const uint32_t kb = sb + buf * FSTAGE;
        const uint32_t vb = kb + FK_TILE;

        float S[16][4];
        #pragma unroll
        for (int i = 0; i < 16; i++)
            #pragma unroll
            for (int k = 0; k < 4; k++) S[i][k] = 0.f;

        #pragma unroll
        for (int kt = 0; kt < 8; kt++) {
            uint32_t bK[8][4];
            #pragma unroll
            for (int nt = 0; nt < 8; nt++)
                ldm4(bK[nt], kb + (nt * 16 + lrow) * FSTRIDE + kt * 32 + lchk * 16);
            #pragma unroll
            for (int n8 = 0; n8 < 16; n8++) {
                const int g = n8 >> 1, p = n8 & 1;
                mma16816(S[n8], qF[kt], bK[g][p], bK[g][p + 2]);
            }
        }

        const float* bp  = bias + ((size_t)h * SEQ + r0 + gr) * SEQ + j * 128;
        const float* bp8 = bp + (size_t)8 * SEQ;
        uint32_t P2[16][2];
        #pragma unroll
        for (int n8 = 0; n8 < 16; n8++) {
            const int cc = n8 * 8 + 2 * tc;
            const float2 b01 = *(const float2*)(bp + cc);
            const float2 b23 = *(const float2*)(bp8 + cc);
            P2[n8][0] = exp2h2(fmaf(b01.x, LOG2E, S[n8][0]),
                               fmaf(b01.y, LOG2E, S[n8][1]));
            P2[n8][1] = exp2h2(fmaf(b23.x, LOG2E, S[n8][2]),
                               fmaf(b23.y, LOG2E, S[n8][3]));
        }

        #pragma unroll
        for (int kp = 0; kp < 8; kp++) {
            uint32_t aP[4];
            aP[0] = P2[2*kp    ][0];
            aP[1] = P2[2*kp    ][1];
            aP[2] = P2[2*kp + 1][0];
            aP[3] = P2[2*kp + 1][1];
            uint32_t bV[9][4];
            #pragma unroll
            for (int nt = 0; nt < 9; nt++)
                ldm4(bV[nt], vb + (nt * 16 + lrow) * FSTRIDE + kp * 32 + lchk * 16);
            #pragma unroll
            for (int n8 = 0; n8 < 17; n8++) {
                const int g = n8 >> 1, p = n8 & 1;
                mma16816(Oacc[n8], aP, bV[g][p], bV[g][p + 2]);
            }
        }
    }

    const float rs0 = __shfl_sync(0xffffffffu, Oacc[16][0], lane & 28);
    const float rs1 = __shfl_sync(0xffffffffu, Oacc[16][2], lane & 28);
    const float i0 = 1.f / rs0, i1 = 1.f / rs1;

    const size_t orow0 = (size_t)(b * SEQ + r0 + gr    ) * ldo + h * DH;
    const size_t orow1 = (size_t)(b * SEQ + r0 + gr + 8) * ldo + h * DH;
    #pragma unroll
    for (int n8 = 0; n8 < 16; n8++) {
        const int cc = n8 * 8 + 2 * tc;
        *(uint32_t*)(at + orow0 + cc) = pack2(Oacc[n8][0] * i0, Oacc[n8][1] * i0);
        *(uint32_t*)(at + orow1 + cc) = pack2(Oacc[n8][2] * i1, Oacc[n8][3] * i1);
    }
}

// ---------------- RMSNorm -> fp16 ----------------
__global__ __launch_bounds__(256) void rmsnorm_kernel(
    const float* __restrict__ x, const float* __restrict__ gamma,
    __half* __restrict__ xn)
{
    const size_t row = blockIdx.x;
    const float* xr = x + row * DIMC;
    const int t = threadIdx.x;

    float s = 0.f;
    for (int c = t; c < DIMC; c += 256) { float v = xr[c]; s += v * v; }
    __shared__ float red[8];
    #pragma unroll
    for (int o = 16; o; o >>= 1) s += __shfl_xor_sync(0xffffffffu, s, o);
    if ((t & 31) == 0) red[t >> 5] = s;
    __syncthreads();
    float tot = red[0]+red[1]+red[2]+red[3]+red[4]+red[5]+red[6]+red[7];
    float inv = rsqrtf(tot + 1e-5f) * RMS_SCALE;

    for (int c = t; c < DIMC; c += 256)
        xn[row * DIMC + c] = __float2half_rn(xr[c] * inv * gamma[c]);
}

// ---------------- merged weight-prep kernels ----------------
// wiT build (permuted). z=0: qkv cols 0..2303; z=1: ff; z=2: gate.
__global__ void prep_wiT_kernel(const float* __restrict__ wi, __half* __restrict__ wiT)
{
    int colBase, rowBase, rowMul;
    if (blockIdx.z == 0) {
        if (blockIdx.x >= 72) return;          // 2304/32
        colBase = 0; rowBase = 0; rowMul = 1;
    } else if (blockIdx.z == 1) {
        colBase = 2304; rowBase = 2304; rowMul = 2;
    } else {
        colBase = 10496; rowBase = 2305; rowMul = 2;
    }
    __shared__ float t[32][33];
    const int cx = colBase + blockIdx.x * 32 + threadIdx.x;
    const int ry = blockIdx.y * 32;
    #pragma unroll
    for (int j = 0; j < 32; j += 8)
        t[threadIdx.y + j][threadIdx.x] = wi[(size_t)(ry + threadIdx.y + j) * NPROJ + cx];
    __syncthreads();
    const int colRel0 = blockIdx.x * 32;
    const int dc = ry + threadIdx.x;
    #pragma unroll
    for (int j = 0; j < 32; j += 8) {
        const size_t drow = (size_t)rowBase + (size_t)rowMul * (colRel0 + threadIdx.y + j);
        wiT[drow * DIMC + dc] = __float2half_rn(t[threadIdx.x][threadIdx.y + j]);
    }
}

// wcat build: z=0: attn_wo -> wcat[col][row]; z=1: ff_wo -> wcat[col][2048+row]
__global__ void prep_wcat_kernel(const float* __restrict__ attn_wo,
                                 const float* __restrict__ ff_wo,
                                 __half* __restrict__ wcat)
{
    const float* src;
    int colOff;
    if (blockIdx.z == 0) {
        if (blockIdx.y >= 64) return;          // 2048/32 source rows
        src = attn_wo; colOff = 0;
    } else {
        src = ff_wo; colOff = 2048;
    }
    __shared__ float t[32][33];
    const int cx = blockIdx.x * 32 + threadIdx.x;  // src col (out dim), 0..2047
    const int ry = blockIdx.y * 32;                // src row (k dim)
    #pragma unroll
    for (int j = 0; j < 32; j += 8)
        t[threadIdx.y + j][threadIdx.x] = src[(size_t)(ry + threadIdx.y + j) * DIMC + cx];
    __syncthreads();
    const int dr0 = blockIdx.x * 32;
    const int dc  = ry + threadIdx.x;
    #pragma unroll
    for (int j = 0; j < 32; j += 8) {
        const size_t drow = (size_t)(dr0 + threadIdx.y + j);
        wcat[drow * NCAT + colOff + dc] = __float2half_rn(t[threadIdx.x][threadIdx.y + j]);
    }
}

// ---------------- launch ----------------
extern "C" void kernel_launch(void* const* d_in, const int* in_sizes, int n_in,
                              void* d_out, int out_size)
{
    const float *x = 0, *bias = 0, *gamma = 0, *wi = 0, *attn_wo = 0, *ff_wo = 0;
    for (int i = 0; i < n_in; i++) {
        switch (in_sizes[i]) {
            case  8388608: x       = (const float*)d_in[i]; break;
            case 67108864: bias    = (const float*)d_in[i]; break;
            case     2048: gamma   = (const float*)d_in[i]; break;
            case 38273024: wi      = (const float*)d_in[i]; break;
            case  4194304: attn_wo = (const float*)d_in[i]; break;
            case 16777216: ff_wo   = (const float*)d_in[i]; break;
        }
    }
    float* out = (float*)d_out;

    __half *xn, *wiT, *qt, *kt, *vt, *cat, *wcat;
    cudaGetSymbolAddress((void**)&xn,   g_xn);
    cudaGetSymbolAddress((void**)&wiT,  g_wiT);
    cudaGetSymbolAddress((void**)&qt,   g_qt);
    cudaGetSymbolAddress((void**)&kt,   g_kt);
    cudaGetSymbolAddress((void**)&vt,   g_vt);
    cudaGetSymbolAddress((void**)&cat,  g_cat);
    cudaGetSymbolAddress((void**)&wcat, g_wcat);

    cudaFuncSetAttribute(gemm_kernel,
                         cudaFuncAttributeMaxDynamicSharedMemorySize, SMEM_GEMM);
    cudaFuncSetAttribute(proj_kernel,
                         cudaFuncAttributeMaxDynamicSharedMemorySize, SMEM_GEMM);
    cudaFuncSetAttribute(flash_kernel,
                         cudaFuncAttributeMaxDynamicSharedMemorySize, SMEM_FLASH);

    // ---- fork side streams off the capture (default) stream via events ----
    cudaStream_t s1, s2;
    cudaStreamCreateWithFlags(&s1, cudaStreamNonBlocking);
    cudaStreamCreateWithFlags(&s2, cudaStreamNonBlocking);
    cudaEvent_t eFork, eWiT, eWcat;
    cudaEventCreateWithFlags(&eFork, cudaEventDisableTiming);
    cudaEventCreateWithFlags(&eWiT,  cudaEventDisableTiming);
    cudaEventCreateWithFlags(&eWcat, cudaEventDisableTiming);

    cudaEventRecord(eFork, 0);
    cudaStreamWaitEvent(s1, eFork, 0);
    cudaStreamWaitEvent(s2, eFork, 0);

    // s1: prep_wiT (needed by proj)   s2: prep_wcat (needed only by final gemm)
    prep_wiT_kernel<<<dim3(256, DIMC/32, 3), dim3(32, 8), 0, s1>>>(wi, wiT);
    cudaEventRecord(eWiT, s1);
    prep_wcat_kernel<<<dim3(DIMC/32, FFI/32, 2), dim3(32, 8), 0, s2>>>(attn_wo, ff_wo, wcat);
    cudaEventRecord(eWcat, s2);

    // main chain on capture stream: rmsnorm overlaps the preps
    rmsnorm_kernel<<<NROWS, 256>>>(x, gamma, xn);
    cudaStreamWaitEvent(0, eWiT, 0);

    // proj GEMM with fused gather/swiglu epilogue
    proj_kernel<<<dim3(NROWS/128, NPROJ/128), 256, SMEM_GEMM>>>(
        xn, DIMC, wiT, DIMC, qt, kt, vt, cat, DIMC);

    // fused attention -> cat cols 0..2047
    flash_kernel<<<dim3(SEQ/128, BATCH*HEADS), 256, SMEM_FLASH>>>(
        qt, kt, vt, bias, cat, NCAT);

    // join wcat before the final GEMM
    cudaStreamWaitEvent(0, eWcat, 0);

    // out = cat @ wcat^T (K = 10240)
    gemm_kernel<<<dim3(NROWS/128, DIMC/128), 256, SMEM_GEMM>>>(
        cat, NCAT, wcat, NCAT, out, DIMC, NCAT);

    cudaEventDestroy(eFork);
    cudaEventDestroy(eWiT);
    cudaEventDestroy(eWcat);
    cudaStreamDestroy(s1);
    cudaStreamDestroy(s2);
}